// round 5
// baseline (speedup 1.0000x reference)
#include <cuda_runtime.h>
#include <math.h>
#include <stdint.h>

#define Bn 2
#define Tn 2048
#define Dn 1024
#define Hn 16
#define Gn 4
#define Kn 64
#define Rn (Hn / Gn)
#define Fn 4096
#define EPSF 1e-6f
#define Mrows (Bn * Tn)

// ---------------- scratch ----------------
__device__ float g_x[Mrows * Dn];
__device__ float g_q[Mrows * Hn * Kn];
__device__ float g_k[Mrows * Gn * Kn];
__device__ float g_v[Mrows * Gn * Kn];
__device__ float g_attn[Mrows * Hn * Kn];
__device__ float g_h2[Mrows * Dn];
__device__ float g_y[Mrows * Dn];
__device__ float g_gate[Mrows * Fn];
__device__ float g_ff[Mrows * Fn];

// ---------------- helpers ----------------
__device__ __forceinline__ uint32_t tf32_bits(float x) {
    uint32_t u;
    asm("cvt.rna.tf32.f32 %0, %1;" : "=r"(u) : "f"(x));
    return u;
}
__device__ __forceinline__ float tf32_rna(float x) {
    return __uint_as_float(tf32_bits(x));
}
__device__ __forceinline__ uint32_t smem_u32(const void* p) {
    return (uint32_t)__cvta_generic_to_shared(p);
}
__device__ __forceinline__ void cpa16(uint32_t dst, const void* src) {
    asm volatile("cp.async.cg.shared.global [%0], [%1], 16;" ::"r"(dst), "l"(src));
}
#define CP_COMMIT asm volatile("cp.async.commit_group;")
#define CP_WAIT0 asm volatile("cp.async.wait_group 0;")
#define CP_WAIT1 asm volatile("cp.async.wait_group 1;")

#define MMA_TF32(d, a0, a1, a2, a3, b0, b1)                                   \
    asm volatile(                                                             \
        "mma.sync.aligned.m16n8k8.row.col.f32.tf32.tf32.f32 "                 \
        "{%0,%1,%2,%3}, {%4,%5,%6,%7}, {%8,%9}, {%0,%1,%2,%3};"               \
        : "+f"(d[0]), "+f"(d[1]), "+f"(d[2]), "+f"(d[3])                      \
        : "r"(a0), "r"(a1), "r"(a2), "r"(a3), "r"(b0), "r"(b1))

// ---------------- RMSNorm ----------------
__global__ void rmsnorm_k(const float* __restrict__ in, const float* __restrict__ sc,
                          float* __restrict__ out) {
    int row = blockIdx.x;
    const float* x = in + (size_t)row * Dn;
    float ss = 0.f;
    for (int i = threadIdx.x; i < Dn; i += blockDim.x) {
        float v = x[i];
        ss += v * v;
    }
    for (int o = 16; o; o >>= 1) ss += __shfl_xor_sync(0xFFFFFFFFu, ss, o);
    __shared__ float sm[8];
    int w = threadIdx.x >> 5;
    if ((threadIdx.x & 31) == 0) sm[w] = ss;
    __syncthreads();
    if (threadIdx.x == 0) {
        float tot = 0.f;
        for (int i = 0; i < 8; i++) tot += sm[i];
        sm[0] = tot;
    }
    __syncthreads();
    float inv = rsqrtf(sm[0] / (float)Dn + EPSF);
    float* o = out + (size_t)row * Dn;
    for (int i = threadIdx.x; i < Dn; i += blockDim.x) o[i] = x[i] * inv * sc[i];
}

// ---------------- per-head RMSNorm + RoPE ----------------
__global__ void norm_rope_k(float* __restrict__ qk, const float* __restrict__ nscale,
                            const float* __restrict__ sinp, const float* __restrict__ cosp,
                            int nheads) {
    int gw = (blockIdx.x * blockDim.x + threadIdx.x) >> 5;
    int lane = threadIdx.x & 31;
    int total = Bn * Tn * nheads;
    if (gw >= total) return;
    int bt = gw / nheads;
    float* p = qk + (size_t)gw * Kn;
    float x1 = p[lane];
    float x2 = p[lane + 32];
    float ss = x1 * x1 + x2 * x2;
    for (int o = 16; o; o >>= 1) ss += __shfl_xor_sync(0xFFFFFFFFu, ss, o);
    float inv = rsqrtf(ss / (float)Kn + EPSF);
    x1 = x1 * inv * nscale[lane];
    x2 = x2 * inv * nscale[lane + 32];
    float s = sinp[bt * (Kn / 2) + lane];
    float c = cosp[bt * (Kn / 2) + lane];
    p[lane]      = x1 * c - x2 * s;
    p[lane + 32] = x2 * c + x1 * s;
}

// ============================================================
// TF32 GEMM, cp.async 3-stage pipeline. 128x256x16 tile, 8 warps (2x4),
// warp tile 64x64 -> 1.0 LDS per MMA.
// Modes: 0 = plain, 1 = +res, 2 = silu(aux)*val
// ============================================================
#define GBM 128
#define GBN 256
#define GBK 16
#define SA 20
#define SB 264
#define GSTG 3
#define GEMM_SMEM ((GSTG * (GBM * SA + GBK * SB)) * 4)

__device__ __forceinline__ void gemm_issue(float* As, float* Bs, int stage,
                                           const float* Aptr, const float* Wptr,
                                           int k0, int N, int Kd) {
    int tid = threadIdx.x;
    int a_row = tid >> 2, a_col = (tid & 3) * 4;
    uint32_t as = smem_u32(As + stage * GBM * SA);
    uint32_t bs = smem_u32(Bs + stage * GBK * SB);
    cpa16(as + (uint32_t)(a_row * SA + a_col) * 4,
          Aptr + (size_t)a_row * Kd + k0 + a_col);
    cpa16(as + (uint32_t)((a_row + 64) * SA + a_col) * 4,
          Aptr + (size_t)(a_row + 64) * Kd + k0 + a_col);
    int b_row = tid >> 6, b_col = (tid & 63) * 4;
#pragma unroll
    for (int j = 0; j < 4; j++) {
        cpa16(bs + (uint32_t)((b_row + 4 * j) * SB + b_col) * 4,
              Wptr + (size_t)(k0 + b_row + 4 * j) * N + b_col);
    }
}

__device__ __forceinline__ void gemm_compute(int wm, int wn, int fr, int fc,
                                             const float* A, const float* B,
                                             float acc[4][8][4]) {
#pragma unroll
    for (int kk = 0; kk < GBK; kk += 8) {
        uint32_t af[4][4];
#pragma unroll
        for (int mi = 0; mi < 4; mi++) {
            int r0 = wm * 64 + mi * 16 + fr;
            af[mi][0] = tf32_bits(A[r0 * SA + kk + fc]);
            af[mi][1] = tf32_bits(A[(r0 + 8) * SA + kk + fc]);
            af[mi][2] = tf32_bits(A[r0 * SA + kk + fc + 4]);
            af[mi][3] = tf32_bits(A[(r0 + 8) * SA + kk + fc + 4]);
        }
#pragma unroll
        for (int ni = 0; ni < 8; ni++) {
            int nc = wn * 64 + ni * 8 + fr;
            uint32_t b0 = tf32_bits(B[(kk + fc) * SB + nc]);
            uint32_t b1 = tf32_bits(B[(kk + fc + 4) * SB + nc]);
#pragma unroll
            for (int mi = 0; mi < 4; mi++)
                MMA_TF32(acc[mi][ni], af[mi][0], af[mi][1], af[mi][2], af[mi][3], b0, b1);
        }
    }
}

__device__ __forceinline__ void gemm_body(const float* A, const float* W,
                                          const float* aux, float* C,
                                          int M, int N, int Kd, int bx, int by,
                                          float* As, float* Bs, int mode) {
    int tid = threadIdx.x;
    int lane = tid & 31, wid = tid >> 5;
    int wm = wid >> 2, wn = wid & 3;
    int fr = lane >> 2, fc = lane & 3;

    const float* Aptr = A + (size_t)(by * GBM) * Kd;
    const float* Wptr = W + (size_t)bx * GBN;

    float acc[4][8][4];
#pragma unroll
    for (int mi = 0; mi < 4; mi++)
#pragma unroll
        for (int ni = 0; ni < 8; ni++)
#pragma unroll
            for (int c = 0; c < 4; c++) acc[mi][ni][c] = 0.f;

    int nk = Kd / GBK;
    gemm_issue(As, Bs, 0, Aptr, Wptr, 0, N, Kd); CP_COMMIT;
    gemm_issue(As, Bs, 1, Aptr, Wptr, GBK, N, Kd); CP_COMMIT;

    for (int i = 0; i < nk; i++) {
        CP_WAIT1;
        __syncthreads();
        if (i + 2 < nk) {
            gemm_issue(As, Bs, (i + 2) % GSTG, Aptr, Wptr, (i + 2) * GBK, N, Kd);
            CP_COMMIT;
        }
        gemm_compute(wm, wn, fr, fc, As + (i % GSTG) * GBM * SA,
                     Bs + (i % GSTG) * GBK * SB, acc);
        __syncthreads();
    }

#pragma unroll
    for (int mi = 0; mi < 4; mi++) {
#pragma unroll
        for (int ni = 0; ni < 8; ni++) {
            int row = by * GBM + wm * 64 + mi * 16 + fr;
            int col = bx * GBN + wn * 64 + ni * 8 + fc * 2;
            float2 r0 = make_float2(acc[mi][ni][0], acc[mi][ni][1]);
            float2 r1 = make_float2(acc[mi][ni][2], acc[mi][ni][3]);
            if (mode == 1) {
                float2 h0 = *(const float2*)(aux + (size_t)row * N + col);
                float2 h1 = *(const float2*)(aux + (size_t)(row + 8) * N + col);
                r0.x += h0.x; r0.y += h0.y;
                r1.x += h1.x; r1.y += h1.y;
            } else if (mode == 2) {
                float2 gv0 = *(const float2*)(aux + (size_t)row * N + col);
                float2 gv1 = *(const float2*)(aux + (size_t)(row + 8) * N + col);
                r0.x *= gv0.x / (1.f + __expf(-gv0.x));
                r0.y *= gv0.y / (1.f + __expf(-gv0.y));
                r1.x *= gv1.x / (1.f + __expf(-gv1.x));
                r1.y *= gv1.y / (1.f + __expf(-gv1.y));
            }
            *(float2*)(C + (size_t)row * N + col) = r0;
            *(float2*)(C + (size_t)(row + 8) * N + col) = r1;
        }
    }
}

__global__ __launch_bounds__(256, 1) void tf32gemm_k(
    const float* __restrict__ A, const float* __restrict__ W,
    const float* __restrict__ aux, float* __restrict__ C,
    int M, int N, int Kd, int mode) {
    extern __shared__ float smg[];
    float* As = smg;
    float* Bs = smg + GSTG * GBM * SA;
    gemm_body(A, W, aux, C, M, N, Kd, blockIdx.x, blockIdx.y, As, Bs, mode);
}

// fused q/k/v projection: bx 0..3 -> q (N=1024), 4 -> k, 5 -> v (N=256)
__global__ __launch_bounds__(256, 1) void tf32gemm_qkv_k(
    const float* __restrict__ A,
    const float* __restrict__ Wq, const float* __restrict__ Wk, const float* __restrict__ Wv,
    float* __restrict__ Cq, float* __restrict__ Ck, float* __restrict__ Cv) {
    extern __shared__ float smg[];
    float* As = smg;
    float* Bs = smg + GSTG * GBM * SA;
    int bx = blockIdx.x;
    const float* W; float* C; int N;
    if (bx < 4)      { W = Wq; C = Cq; N = 1024; }
    else if (bx == 4){ W = Wk; C = Ck; N = 256; bx = 0; }
    else             { W = Wv; C = Cv; N = 256; bx = 0; }
    gemm_body(A, W, nullptr, C, Mrows, N, Dn, bx, blockIdx.y, As, Bs, 0);
}

// ============================================================
// Flash attention (tf32 mma), GQA-packed: M-tile = 32 t x 4 r = 128 rows.
// Each warp owns 16 complete rows; P is warp-private in smem.
// ============================================================
#define QSS 68
#define KSS 68
#define VSS 72
#define PSS 132
#define ATT_SMEM ((128 * QSS + 128 * KSS + 128 * VSS + 128 * PSS) * 4)

__global__ __launch_bounds__(256, 1) void flashattn_k(
    const float* __restrict__ q, const float* __restrict__ k,
    const float* __restrict__ v, float* __restrict__ out) {
    extern __shared__ float sm[];
    float* Qs = sm;
    float* Ks = Qs + 128 * QSS;
    float* Vs = Ks + 128 * KSS;
    float* Ps = Vs + 128 * VSS;
    uint32_t qs_u = smem_u32(Qs), ks_u = smem_u32(Ks), vs_u = smem_u32(Vs);

    int tid = threadIdx.x;
    int lane = tid & 31, wid = tid >> 5;
    int fr = lane >> 2, fc = lane & 3;
    float* Pw = Ps + wid * 16 * PSS;

    int bg = blockIdx.y;
    int b = bg >> 2, g = bg & 3;
    int t0 = (gridDim.x - 1 - blockIdx.x) * 32;
    int ntiles = (t0 >> 7) + 1;

    const float* qbase = q + ((size_t)((size_t)b * Tn + t0) * Hn + g * Rn) * Kn;
    const float* kbase = k + ((size_t)b * Tn * Gn + g) * Kn;
    const float* vbase = v + ((size_t)b * Tn * Gn + g) * Kn;

#pragma unroll
    for (int i = 0; i < 8; i++) {
        int idx = tid + (i << 8);
        int m = idx >> 4, c4 = (idx & 15) << 2;
        cpa16(qs_u + (uint32_t)(m * QSS + c4) * 4,
              qbase + (size_t)(m >> 2) * (Hn * Kn) + (m & 3) * Kn + c4);
    }
    CP_COMMIT;
#pragma unroll
    for (int i = 0; i < 8; i++) {
        int idx = tid + (i << 8);
        int j = idx >> 4, c4 = (idx & 15) << 2;
        cpa16(ks_u + (uint32_t)(j * KSS + c4) * 4, kbase + (size_t)j * (Gn * Kn) + c4);
    }
    CP_COMMIT;
#pragma unroll
    for (int i = 0; i < 8; i++) {
        int idx = tid + (i << 8);
        int j = idx >> 4, c4 = (idx & 15) << 2;
        cpa16(vs_u + (uint32_t)(j * VSS + c4) * 4, vbase + (size_t)j * (Gn * Kn) + c4);
    }
    CP_COMMIT;
    CP_WAIT0;
    __syncthreads();

    float m_r[2], l_r[2], acco[8][4];
#pragma unroll
    for (int h = 0; h < 2; h++) { m_r[h] = -INFINITY; l_r[h] = 0.f; }
#pragma unroll
    for (int ni = 0; ni < 8; ni++)
#pragma unroll
        for (int c = 0; c < 4; c++) acco[ni][c] = 0.f;

    int r0 = wid * 16 + fr;

    for (int it = 0; it < ntiles; it++) {
        int s0 = it << 7;
        bool more = (it + 1 < ntiles);

        float accs[16][4];
#pragma unroll
        for (int ni = 0; ni < 16; ni++)
#pragma unroll
            for (int c = 0; c < 4; c++) accs[ni][c] = 0.f;

#pragma unroll
        for (int kc = 0; kc < 64; kc += 8) {
            uint32_t af[4];
            af[0] = tf32_bits(Qs[r0 * QSS + kc + fc]);
            af[1] = tf32_bits(Qs[(r0 + 8) * QSS + kc + fc]);
            af[2] = tf32_bits(Qs[r0 * QSS + kc + fc + 4]);
            af[3] = tf32_bits(Qs[(r0 + 8) * QSS + kc + fc + 4]);
#pragma unroll
            for (int ni = 0; ni < 16; ni++) {
                int nc = ni * 8 + fr;
                uint32_t b0 = tf32_bits(Ks[nc * KSS + kc + fc]);
                uint32_t b1 = tf32_bits(Ks[nc * KSS + kc + fc + 4]);
                MMA_TF32(accs[ni], af[0], af[1], af[2], af[3], b0, b1);
            }
        }

#pragma unroll
        for (int ni = 0; ni < 16; ni++)
#pragma unroll
            for (int c = 0; c < 4; c++) accs[ni][c] *= 0.125f;
        if (it == ntiles - 1) {
#pragma unroll
            for (int ni = 0; ni < 16; ni++)
#pragma unroll
                for (int c = 0; c < 4; c++) {
                    int row = r0 + ((c >= 2) ? 8 : 0);
                    int tt = t0 + (row >> 2);
                    int ss = s0 + ni * 8 + fc * 2 + (c & 1);
                    if (ss > tt) accs[ni][c] = -1e30f;
                }
        }

#pragma unroll
        for (int h = 0; h < 2; h++) {
            float mx = -1e30f;
#pragma unroll
            for (int ni = 0; ni < 16; ni++) {
                mx = fmaxf(mx, accs[ni][2 * h]);
                mx = fmaxf(mx, accs[ni][2 * h + 1]);
            }
            mx = fmaxf(mx, __shfl_xor_sync(0xFFFFFFFFu, mx, 1));
            mx = fmaxf(mx, __shfl_xor_sync(0xFFFFFFFFu, mx, 2));
            float mnew = fmaxf(m_r[h], mx);
            float corr = __expf(m_r[h] - mnew);
            m_r[h] = mnew;
            float sum = 0.f;
#pragma unroll
            for (int ni = 0; ni < 16; ni++) {
                float p0 = __expf(accs[ni][2 * h] - mnew);
                float p1 = __expf(accs[ni][2 * h + 1] - mnew);
                accs[ni][2 * h] = p0;
                accs[ni][2 * h + 1] = p1;
                sum += p0 + p1;
            }
            sum += __shfl_xor_sync(0xFFFFFFFFu, sum, 1);
            sum += __shfl_xor_sync(0xFFFFFFFFu, sum, 2);
            l_r[h] = l_r[h] * corr + sum;
#pragma unroll
            for (int ni = 0; ni < 8; ni++) {
                acco[ni][2 * h] *= corr;
                acco[ni][2 * h + 1] *= corr;
            }
        }

#pragma unroll
        for (int ni = 0; ni < 16; ni++) {
            int cc = ni * 8 + fc * 2;
            *(float2*)(Pw + fr * PSS + cc) =
                make_float2(tf32_rna(accs[ni][0]), tf32_rna(accs[ni][1]));
            *(float2*)(Pw + (fr + 8) * PSS + cc) =
                make_float2(tf32_rna(accs[ni][2]), tf32_rna(accs[ni][3]));
        }

        __syncthreads();
        if (more) {
            int sn = s0 + 128;
#pragma unroll
            for (int i = 0; i < 8; i++) {
                int idx = tid + (i << 8);
                int j = idx >> 4, c4 = (idx & 15) << 2;
                cpa16(ks_u + (uint32_t)(j * KSS + c4) * 4,
                      kbase + (size_t)(sn + j) * (Gn * Kn) + c4);
            }
            CP_COMMIT;
            CP_WAIT1;
        } else {
            CP_WAIT0;
        }
        __syncthreads();

#pragma unroll
        for (int kc = 0; kc < 128; kc += 8) {
            uint32_t af[4];
            af[0] = __float_as_uint(Pw[fr * PSS + kc + fc]);
            af[1] = __float_as_uint(Pw[(fr + 8) * PSS + kc + fc]);
            af[2] = __float_as_uint(Pw[fr * PSS + kc + fc + 4]);
            af[3] = __float_as_uint(Pw[(fr + 8) * PSS + kc + fc + 4]);
#pragma unroll
            for (int ni = 0; ni < 8; ni++) {
                int n0 = ni * 8 + fr;
                uint32_t b0 = tf32_bits(Vs[(kc + fc) * VSS + n0]);
                uint32_t b1 = tf32_bits(Vs[(kc + fc + 4) * VSS + n0]);
                MMA_TF32(acco[ni], af[0], af[1], af[2], af[3], b0, b1);
            }
        }
        __syncthreads();

        if (more) {
            int sn = s0 + 128;
#pragma unroll
            for (int i = 0; i < 8; i++) {
                int idx = tid + (i << 8);
                int j = idx >> 4, c4 = (idx & 15) << 2;
                cpa16(vs_u + (uint32_t)(j * VSS + c4) * 4,
                      vbase + (size_t)(sn + j) * (Gn * Kn) + c4);
            }
            CP_COMMIT;
            CP_WAIT1;
            __syncthreads();
        }
    }

#pragma unroll
    for (int h = 0; h < 2; h++) {
        float inv = 1.f / l_r[h];
        int row = r0 + 8 * h;
        int tt = t0 + (row >> 2);
        int hh = g * Rn + (row & 3);
        float* op = out + ((size_t)((size_t)b * Tn + tt) * Hn + hh) * Kn;
#pragma unroll
        for (int ni = 0; ni < 8; ni++) {
            int col = ni * 8 + fc * 2;
            *(float2*)(op + col) =
                make_float2(acco[ni][2 * h] * inv, acco[ni][2 * h + 1] * inv);
        }
    }
}

// ---------------- launch ----------------
static void gemm(const float* A, const float* W, const float* aux, float* C,
                 int M, int N, int Kd, int mode) {
    dim3 grid(N / GBN, M / GBM);
    tf32gemm_k<<<grid, 256, GEMM_SMEM>>>(A, W, aux, C, M, N, Kd, mode);
}

extern "C" void kernel_launch(void* const* d_in, const int* in_sizes, int n_in,
                              void* d_out, int out_size) {
    const float* hidden = (const float*)d_in[0];
    const float* sinp   = (const float*)d_in[1];
    const float* cosp   = (const float*)d_in[2];
    /* d_in[3] = mask (exact causal tril; applied analytically) */
    const float* ln1    = (const float*)d_in[4];
    const float* ln2    = (const float*)d_in[5];
    const float* qn     = (const float*)d_in[6];
    const float* kn     = (const float*)d_in[7];
    const float* q_w    = (const float*)d_in[8];
    const float* k_w    = (const float*)d_in[9];
    const float* v_w    = (const float*)d_in[10];
    const float* o_w    = (const float*)d_in[11];
    const float* gate_w = (const float*)d_in[12];
    const float* up_w   = (const float*)d_in[13];
    const float* down_w = (const float*)d_in[14];
    float* out = (float*)d_out;

    cudaFuncSetAttribute(tf32gemm_k, cudaFuncAttributeMaxDynamicSharedMemorySize, GEMM_SMEM);
    cudaFuncSetAttribute(tf32gemm_qkv_k, cudaFuncAttributeMaxDynamicSharedMemorySize, GEMM_SMEM);
    cudaFuncSetAttribute(flashattn_k, cudaFuncAttributeMaxDynamicSharedMemorySize, ATT_SMEM);

    float *x, *q, *k, *v, *attn, *h2, *y, *gate, *ff;
    cudaGetSymbolAddress((void**)&x, g_x);
    cudaGetSymbolAddress((void**)&q, g_q);
    cudaGetSymbolAddress((void**)&k, g_k);
    cudaGetSymbolAddress((void**)&v, g_v);
    cudaGetSymbolAddress((void**)&attn, g_attn);
    cudaGetSymbolAddress((void**)&h2, g_h2);
    cudaGetSymbolAddress((void**)&y, g_y);
    cudaGetSymbolAddress((void**)&gate, g_gate);
    cudaGetSymbolAddress((void**)&ff, g_ff);

    const int M = Mrows;

    rmsnorm_k<<<M, 256>>>(hidden, ln1, x);

    // fused q/k/v projection (q: 4 N-tiles, k: 1, v: 1)
    tf32gemm_qkv_k<<<dim3(6, M / GBM), 256, GEMM_SMEM>>>(x, q_w, k_w, v_w, q, k, v);

    {
        int warps_q = Bn * Tn * Hn;
        norm_rope_k<<<(warps_q * 32) / 256, 256>>>(q, qn, sinp, cosp, Hn);
        int warps_k = Bn * Tn * Gn;
        norm_rope_k<<<(warps_k * 32) / 256, 256>>>(k, kn, sinp, cosp, Gn);
    }

    flashattn_k<<<dim3(Tn / 32, Bn * Gn), 256, ATT_SMEM>>>(q, k, v, attn);

    // h2 = hidden + attn @ o_w
    gemm(attn, o_w, hidden, h2, M, Dn, Hn * Kn, 1);

    rmsnorm_k<<<M, 256>>>(h2, ln2, y);

    // gate = y @ gate_w ; ff = silu(gate) * (y @ up_w)
    gemm(y, gate_w, nullptr, gate, M, Fn, Dn, 0);
    gemm(y, up_w, gate, ff, M, Fn, Dn, 2);

    // out = h2 + ff @ down_w
    gemm(ff, down_w, h2, out, M, Dn, Fn, 1);
}

// round 6
// speedup vs baseline: 1.0561x; 1.0561x over previous
#include <cuda_runtime.h>
#include <math.h>
#include <stdint.h>

#define Bn 2
#define Tn 2048
#define Dn 1024
#define Hn 16
#define Gn 4
#define Kn 64
#define Rn (Hn / Gn)
#define Fn 4096
#define EPSF 1e-6f
#define Mrows (Bn * Tn)

// ---------------- scratch ----------------
__device__ float g_x[Mrows * Dn];
__device__ float g_q[Mrows * Hn * Kn];
__device__ float g_k[Mrows * Gn * Kn];
__device__ float g_v[Mrows * Gn * Kn];
__device__ float g_attn[Mrows * Hn * Kn];
__device__ float g_h2[Mrows * Dn];
__device__ float g_y[Mrows * Dn];
__device__ float g_gate[Mrows * Fn];
__device__ float g_ff[Mrows * Fn];

// ---------------- helpers ----------------
__device__ __forceinline__ uint32_t tf32_bits(float x) {
    uint32_t u;
    asm("cvt.rna.tf32.f32 %0, %1;" : "=r"(u) : "f"(x));
    return u;
}
__device__ __forceinline__ float tf32_rna(float x) {
    return __uint_as_float(tf32_bits(x));
}
__device__ __forceinline__ uint32_t smem_u32(const void* p) {
    return (uint32_t)__cvta_generic_to_shared(p);
}
__device__ __forceinline__ void cpa16(uint32_t dst, const void* src) {
    asm volatile("cp.async.cg.shared.global [%0], [%1], 16;" ::"r"(dst), "l"(src));
}
#define CP_COMMIT asm volatile("cp.async.commit_group;")
#define CP_WAIT0 asm volatile("cp.async.wait_group 0;")
#define CP_WAIT1 asm volatile("cp.async.wait_group 1;")

#define MMA_TF32(d, a0, a1, a2, a3, b0, b1)                                   \
    asm volatile(                                                             \
        "mma.sync.aligned.m16n8k8.row.col.f32.tf32.tf32.f32 "                 \
        "{%0,%1,%2,%3}, {%4,%5,%6,%7}, {%8,%9}, {%0,%1,%2,%3};"               \
        : "+f"(d[0]), "+f"(d[1]), "+f"(d[2]), "+f"(d[3])                      \
        : "r"(a0), "r"(a1), "r"(a2), "r"(a3), "r"(b0), "r"(b1))

// ---------------- RMSNorm ----------------
__global__ void rmsnorm_k(const float* __restrict__ in, const float* __restrict__ sc,
                          float* __restrict__ out) {
    int row = blockIdx.x;
    const float* x = in + (size_t)row * Dn;
    float ss = 0.f;
    for (int i = threadIdx.x; i < Dn; i += blockDim.x) {
        float v = x[i];
        ss += v * v;
    }
    for (int o = 16; o; o >>= 1) ss += __shfl_xor_sync(0xFFFFFFFFu, ss, o);
    __shared__ float sm[8];
    int w = threadIdx.x >> 5;
    if ((threadIdx.x & 31) == 0) sm[w] = ss;
    __syncthreads();
    if (threadIdx.x == 0) {
        float tot = 0.f;
        for (int i = 0; i < 8; i++) tot += sm[i];
        sm[0] = tot;
    }
    __syncthreads();
    float inv = rsqrtf(sm[0] / (float)Dn + EPSF);
    float* o = out + (size_t)row * Dn;
    for (int i = threadIdx.x; i < Dn; i += blockDim.x) o[i] = x[i] * inv * sc[i];
}

// ---------------- per-head RMSNorm + RoPE ----------------
__global__ void norm_rope_k(float* __restrict__ qk, const float* __restrict__ nscale,
                            const float* __restrict__ sinp, const float* __restrict__ cosp,
                            int nheads) {
    int gw = (blockIdx.x * blockDim.x + threadIdx.x) >> 5;
    int lane = threadIdx.x & 31;
    int total = Bn * Tn * nheads;
    if (gw >= total) return;
    int bt = gw / nheads;
    float* p = qk + (size_t)gw * Kn;
    float x1 = p[lane];
    float x2 = p[lane + 32];
    float ss = x1 * x1 + x2 * x2;
    for (int o = 16; o; o >>= 1) ss += __shfl_xor_sync(0xFFFFFFFFu, ss, o);
    float inv = rsqrtf(ss / (float)Kn + EPSF);
    x1 = x1 * inv * nscale[lane];
    x2 = x2 * inv * nscale[lane + 32];
    float s = sinp[bt * (Kn / 2) + lane];
    float c = cosp[bt * (Kn / 2) + lane];
    p[lane]      = x1 * c - x2 * s;
    p[lane + 32] = x2 * c + x1 * s;
}

// ============================================================
// TF32 GEMM, cp.async 3-stage pipeline. 128x128x16 tile, 8 warps.
// Modes: 0 = plain, 1 = +aux (residual), 2 = silu(aux)*acc
// ============================================================
#define GBM 128
#define GBN 128
#define GBK 16
#define SA 20
#define SB 136
#define GSTG 3
#define GEMM_SMEM ((GSTG * (GBM * SA + GBK * SB)) * 4)

struct GemmIdx {
    int a_row, a_col, b_row, b_col;
    int wm, wn, fr, fc;
};

__device__ __forceinline__ GemmIdx gemm_idx(int tid) {
    GemmIdx g;
    int lane = tid & 31, wid = tid >> 5;
    g.wm = wid >> 2; g.wn = wid & 3;
    g.fr = lane >> 2; g.fc = lane & 3;
    g.a_row = tid >> 2;        g.a_col = (tid & 3) * 4;
    g.b_row = tid >> 5;        g.b_col = (tid & 31) * 4;
    return g;
}

__device__ __forceinline__ void gemm_issue(const GemmIdx& gi, float* As, float* Bs, int stage,
                                           const float* Aptr, const float* Wptr,
                                           int k0, int N, int Kd) {
    uint32_t as = smem_u32(As + stage * GBM * SA);
    uint32_t bs = smem_u32(Bs + stage * GBK * SB);
    cpa16(as + (uint32_t)(gi.a_row * SA + gi.a_col) * 4,
          Aptr + (size_t)gi.a_row * Kd + k0 + gi.a_col);
    cpa16(as + (uint32_t)((gi.a_row + 64) * SA + gi.a_col) * 4,
          Aptr + (size_t)(gi.a_row + 64) * Kd + k0 + gi.a_col);
    cpa16(bs + (uint32_t)(gi.b_row * SB + gi.b_col) * 4,
          Wptr + (size_t)(k0 + gi.b_row) * N + gi.b_col);
    cpa16(bs + (uint32_t)((gi.b_row + 8) * SB + gi.b_col) * 4,
          Wptr + (size_t)(k0 + gi.b_row + 8) * N + gi.b_col);
}

__device__ __forceinline__ void gemm_compute(const GemmIdx& gi, const float* As, const float* Bs,
                                             int stage, float acc[4][4][4]) {
    const float* A = As + stage * GBM * SA;
    const float* B = Bs + stage * GBK * SB;
#pragma unroll
    for (int kk = 0; kk < GBK; kk += 8) {
        uint32_t af[4][4], bf[4][2];
#pragma unroll
        for (int mi = 0; mi < 4; mi++) {
            int r0 = gi.wm * 64 + mi * 16 + gi.fr;
            af[mi][0] = tf32_bits(A[r0 * SA + kk + gi.fc]);
            af[mi][1] = tf32_bits(A[(r0 + 8) * SA + kk + gi.fc]);
            af[mi][2] = tf32_bits(A[r0 * SA + kk + gi.fc + 4]);
            af[mi][3] = tf32_bits(A[(r0 + 8) * SA + kk + gi.fc + 4]);
        }
#pragma unroll
        for (int ni = 0; ni < 4; ni++) {
            int nc = gi.wn * 32 + ni * 8 + gi.fr;
            bf[ni][0] = tf32_bits(B[(kk + gi.fc) * SB + nc]);
            bf[ni][1] = tf32_bits(B[(kk + gi.fc + 4) * SB + nc]);
        }
#pragma unroll
        for (int mi = 0; mi < 4; mi++)
#pragma unroll
            for (int ni = 0; ni < 4; ni++)
                MMA_TF32(acc[mi][ni], af[mi][0], af[mi][1], af[mi][2], af[mi][3],
                         bf[ni][0], bf[ni][1]);
    }
}

__device__ __forceinline__ void gemm_body(const float* A, const float* W,
                                          const float* aux, float* C,
                                          int M, int N, int Kd, int bx, int by,
                                          float* As, float* Bs, int mode) {
    GemmIdx gi = gemm_idx(threadIdx.x);
    const float* Aptr = A + (size_t)(by * GBM) * Kd;
    const float* Wptr = W + (size_t)bx * GBN;

    float acc[4][4][4];
#pragma unroll
    for (int mi = 0; mi < 4; mi++)
#pragma unroll
        for (int ni = 0; ni < 4; ni++)
#pragma unroll
            for (int c = 0; c < 4; c++) acc[mi][ni][c] = 0.f;

    int nk = Kd / GBK;
    gemm_issue(gi, As, Bs, 0, Aptr, Wptr, 0, N, Kd); CP_COMMIT;
    gemm_issue(gi, As, Bs, 1, Aptr, Wptr, GBK, N, Kd); CP_COMMIT;

    for (int i = 0; i < nk; i++) {
        CP_WAIT1;
        __syncthreads();
        if (i + 2 < nk) {
            gemm_issue(gi, As, Bs, (i + 2) % GSTG, Aptr, Wptr, (i + 2) * GBK, N, Kd);
            CP_COMMIT;
        }
        gemm_compute(gi, As, Bs, i % GSTG, acc);
        __syncthreads();
    }

#pragma unroll
    for (int mi = 0; mi < 4; mi++) {
#pragma unroll
        for (int ni = 0; ni < 4; ni++) {
            int row = by * GBM + gi.wm * 64 + mi * 16 + gi.fr;
            int col = bx * GBN + gi.wn * 32 + ni * 8 + gi.fc * 2;
            float2 r0 = make_float2(acc[mi][ni][0], acc[mi][ni][1]);
            float2 r1 = make_float2(acc[mi][ni][2], acc[mi][ni][3]);
            if (mode == 1) {
                float2 h0 = *(const float2*)(aux + (size_t)row * N + col);
                float2 h1 = *(const float2*)(aux + (size_t)(row + 8) * N + col);
                r0.x += h0.x; r0.y += h0.y;
                r1.x += h1.x; r1.y += h1.y;
            } else if (mode == 2) {
                float2 g0 = *(const float2*)(aux + (size_t)row * N + col);
                float2 g1 = *(const float2*)(aux + (size_t)(row + 8) * N + col);
                r0.x *= g0.x / (1.f + __expf(-g0.x));
                r0.y *= g0.y / (1.f + __expf(-g0.y));
                r1.x *= g1.x / (1.f + __expf(-g1.x));
                r1.y *= g1.y / (1.f + __expf(-g1.y));
            }
            *(float2*)(C + (size_t)row * N + col) = r0;
            *(float2*)(C + (size_t)(row + 8) * N + col) = r1;
        }
    }
}

__global__ __launch_bounds__(256, 2) void tf32gemm_k(
    const float* __restrict__ A, const float* __restrict__ W,
    const float* __restrict__ aux, float* __restrict__ C,
    int M, int N, int Kd, int mode) {
    extern __shared__ float smg[];
    float* As = smg;
    float* Bs = smg + GSTG * GBM * SA;
    gemm_body(A, W, aux, C, M, N, Kd, blockIdx.x, blockIdx.y, As, Bs, mode);
}

// fused q/k/v projection: bx 0..7 -> q (N=1024), 8..9 -> k, 10..11 -> v (N=256)
__global__ __launch_bounds__(256, 2) void tf32gemm_qkv_k(
    const float* __restrict__ A,
    const float* __restrict__ Wq, const float* __restrict__ Wk, const float* __restrict__ Wv,
    float* __restrict__ Cq, float* __restrict__ Ck, float* __restrict__ Cv) {
    extern __shared__ float smg[];
    float* As = smg;
    float* Bs = smg + GSTG * GBM * SA;
    int bx = blockIdx.x;
    const float* W; float* C; int N;
    if (bx < 8)       { W = Wq; C = Cq; N = 1024; }
    else if (bx < 10) { W = Wk; C = Ck; N = 256; bx -= 8; }
    else              { W = Wv; C = Cv; N = 256; bx -= 10; }
    gemm_body(A, W, nullptr, C, Mrows, N, Dn, bx, blockIdx.y, As, Bs, 0);
}

// ============================================================
// Flash attention (tf32 mma), GQA-packed: M-tile = 32 t x 4 r = 128 rows.
// Each warp owns 16 complete rows; P is warp-private in smem.
// ============================================================
#define QSS 68
#define KSS 68
#define VSS 72
#define PSS 132
#define ATT_SMEM ((128 * QSS + 128 * KSS + 128 * VSS + 128 * PSS) * 4)

__global__ __launch_bounds__(256, 1) void flashattn_k(
    const float* __restrict__ q, const float* __restrict__ k,
    const float* __restrict__ v, float* __restrict__ out) {
    extern __shared__ float sm[];
    float* Qs = sm;
    float* Ks = Qs + 128 * QSS;
    float* Vs = Ks + 128 * KSS;
    float* Ps = Vs + 128 * VSS;
    uint32_t qs_u = smem_u32(Qs), ks_u = smem_u32(Ks), vs_u = smem_u32(Vs);

    int tid = threadIdx.x;
    int lane = tid & 31, wid = tid >> 5;
    int fr = lane >> 2, fc = lane & 3;
    float* Pw = Ps + wid * 16 * PSS;

    int bg = blockIdx.y;
    int b = bg >> 2, g = bg & 3;
    int t0 = (gridDim.x - 1 - blockIdx.x) * 32;
    int ntiles = (t0 >> 7) + 1;

    const float* qbase = q + ((size_t)((size_t)b * Tn + t0) * Hn + g * Rn) * Kn;
    const float* kbase = k + ((size_t)b * Tn * Gn + g) * Kn;
    const float* vbase = v + ((size_t)b * Tn * Gn + g) * Kn;

#pragma unroll
    for (int i = 0; i < 8; i++) {
        int idx = tid + (i << 8);
        int m = idx >> 4, c4 = (idx & 15) << 2;
        cpa16(qs_u + (uint32_t)(m * QSS + c4) * 4,
              qbase + (size_t)(m >> 2) * (Hn * Kn) + (m & 3) * Kn + c4);
    }
    CP_COMMIT;
#pragma unroll
    for (int i = 0; i < 8; i++) {
        int idx = tid + (i << 8);
        int j = idx >> 4, c4 = (idx & 15) << 2;
        cpa16(ks_u + (uint32_t)(j * KSS + c4) * 4, kbase + (size_t)j * (Gn * Kn) + c4);
    }
    CP_COMMIT;
#pragma unroll
    for (int i = 0; i < 8; i++) {
        int idx = tid + (i << 8);
        int j = idx >> 4, c4 = (idx & 15) << 2;
        cpa16(vs_u + (uint32_t)(j * VSS + c4) * 4, vbase + (size_t)j * (Gn * Kn) + c4);
    }
    CP_COMMIT;
    CP_WAIT0;
    __syncthreads();

    float m_r[2], l_r[2], acco[8][4];
#pragma unroll
    for (int h = 0; h < 2; h++) { m_r[h] = -INFINITY; l_r[h] = 0.f; }
#pragma unroll
    for (int ni = 0; ni < 8; ni++)
#pragma unroll
        for (int c = 0; c < 4; c++) acco[ni][c] = 0.f;

    int r0 = wid * 16 + fr;

    for (int it = 0; it < ntiles; it++) {
        int s0 = it << 7;
        bool more = (it + 1 < ntiles);

        float accs[16][4];
#pragma unroll
        for (int ni = 0; ni < 16; ni++)
#pragma unroll
            for (int c = 0; c < 4; c++) accs[ni][c] = 0.f;

#pragma unroll
        for (int kc = 0; kc < 64; kc += 8) {
            uint32_t af[4];
            af[0] = tf32_bits(Qs[r0 * QSS + kc + fc]);
            af[1] = tf32_bits(Qs[(r0 + 8) * QSS + kc + fc]);
            af[2] = tf32_bits(Qs[r0 * QSS + kc + fc + 4]);
            af[3] = tf32_bits(Qs[(r0 + 8) * QSS + kc + fc + 4]);
#pragma unroll
            for (int ni = 0; ni < 16; ni++) {
                int nc = ni * 8 + fr;
                uint32_t b0 = tf32_bits(Ks[nc * KSS + kc + fc]);
                uint32_t b1 = tf32_bits(Ks[nc * KSS + kc + fc + 4]);
                MMA_TF32(accs[ni], af[0], af[1], af[2], af[3], b0, b1);
            }
        }

#pragma unroll
        for (int ni = 0; ni < 16; ni++)
#pragma unroll
            for (int c = 0; c < 4; c++) accs[ni][c] *= 0.125f;
        if (it == ntiles - 1) {
#pragma unroll
            for (int ni = 0; ni < 16; ni++)
#pragma unroll
                for (int c = 0; c < 4; c++) {
                    int row = r0 + ((c >= 2) ? 8 : 0);
                    int tt = t0 + (row >> 2);
                    int ss = s0 + ni * 8 + fc * 2 + (c & 1);
                    if (ss > tt) accs[ni][c] = -1e30f;
                }
        }

#pragma unroll
        for (int h = 0; h < 2; h++) {
            float mx = -1e30f;
#pragma unroll
            for (int ni = 0; ni < 16; ni++) {
                mx = fmaxf(mx, accs[ni][2 * h]);
                mx = fmaxf(mx, accs[ni][2 * h + 1]);
            }
            mx = fmaxf(mx, __shfl_xor_sync(0xFFFFFFFFu, mx, 1));
            mx = fmaxf(mx, __shfl_xor_sync(0xFFFFFFFFu, mx, 2));
            float mnew = fmaxf(m_r[h], mx);
            float corr = __expf(m_r[h] - mnew);
            m_r[h] = mnew;
            float sum = 0.f;
#pragma unroll
            for (int ni = 0; ni < 16; ni++) {
                float p0 = __expf(accs[ni][2 * h] - mnew);
                float p1 = __expf(accs[ni][2 * h + 1] - mnew);
                accs[ni][2 * h] = p0;
                accs[ni][2 * h + 1] = p1;
                sum += p0 + p1;
            }
            sum += __shfl_xor_sync(0xFFFFFFFFu, sum, 1);
            sum += __shfl_xor_sync(0xFFFFFFFFu, sum, 2);
            l_r[h] = l_r[h] * corr + sum;
#pragma unroll
            for (int ni = 0; ni < 8; ni++) {
                acco[ni][2 * h] *= corr;
                acco[ni][2 * h + 1] *= corr;
            }
        }

#pragma unroll
        for (int ni = 0; ni < 16; ni++) {
            int cc = ni * 8 + fc * 2;
            *(float2*)(Pw + fr * PSS + cc) =
                make_float2(tf32_rna(accs[ni][0]), tf32_rna(accs[ni][1]));
            *(float2*)(Pw + (fr + 8) * PSS + cc) =
                make_float2(tf32_rna(accs[ni][2]), tf32_rna(accs[ni][3]));
        }

        __syncthreads();
        if (more) {
            int sn = s0 + 128;
#pragma unroll
            for (int i = 0; i < 8; i++) {
                int idx = tid + (i << 8);
                int j = idx >> 4, c4 = (idx & 15) << 2;
                cpa16(ks_u + (uint32_t)(j * KSS + c4) * 4,
                      kbase + (size_t)(sn + j) * (Gn * Kn) + c4);
            }
            CP_COMMIT;
            CP_WAIT1;
        } else {
            CP_WAIT0;
        }
        __syncthreads();

#pragma unroll
        for (int kc = 0; kc < 128; kc += 8) {
            uint32_t af[4];
            af[0] = __float_as_uint(Pw[fr * PSS + kc + fc]);
            af[1] = __float_as_uint(Pw[(fr + 8) * PSS + kc + fc]);
            af[2] = __float_as_uint(Pw[fr * PSS + kc + fc + 4]);
            af[3] = __float_as_uint(Pw[(fr + 8) * PSS + kc + fc + 4]);
#pragma unroll
            for (int ni = 0; ni < 8; ni++) {
                int n0 = ni * 8 + fr;
                uint32_t b0 = tf32_bits(Vs[(kc + fc) * VSS + n0]);
                uint32_t b1 = tf32_bits(Vs[(kc + fc + 4) * VSS + n0]);
                MMA_TF32(acco[ni], af[0], af[1], af[2], af[3], b0, b1);
            }
        }
        __syncthreads();

        if (more) {
            int sn = s0 + 128;
#pragma unroll
            for (int i = 0; i < 8; i++) {
                int idx = tid + (i << 8);
                int j = idx >> 4, c4 = (idx & 15) << 2;
                cpa16(vs_u + (uint32_t)(j * VSS + c4) * 4,
                      vbase + (size_t)(sn + j) * (Gn * Kn) + c4);
            }
            CP_COMMIT;
            CP_WAIT1;
            __syncthreads();
        }
    }

#pragma unroll
    for (int h = 0; h < 2; h++) {
        float inv = 1.f / l_r[h];
        int row = r0 + 8 * h;
        int tt = t0 + (row >> 2);
        int hh = g * Rn + (row & 3);
        float* op = out + ((size_t)((size_t)b * Tn + tt) * Hn + hh) * Kn;
#pragma unroll
        for (int ni = 0; ni < 8; ni++) {
            int col = ni * 8 + fc * 2;
            *(float2*)(op + col) =
                make_float2(acco[ni][2 * h] * inv, acco[ni][2 * h + 1] * inv);
        }
    }
}

// ---------------- launch ----------------
static void gemm(const float* A, const float* W, const float* aux, float* C,
                 int M, int N, int Kd, int mode) {
    dim3 grid(N / GBN, M / GBM);
    tf32gemm_k<<<grid, 256, GEMM_SMEM>>>(A, W, aux, C, M, N, Kd, mode);
}

extern "C" void kernel_launch(void* const* d_in, const int* in_sizes, int n_in,
                              void* d_out, int out_size) {
    const float* hidden = (const float*)d_in[0];
    const float* sinp   = (const float*)d_in[1];
    const float* cosp   = (const float*)d_in[2];
    /* d_in[3] = mask (exact causal tril; applied analytically) */
    const float* ln1    = (const float*)d_in[4];
    const float* ln2    = (const float*)d_in[5];
    const float* qn     = (const float*)d_in[6];
    const float* kn     = (const float*)d_in[7];
    const float* q_w    = (const float*)d_in[8];
    const float* k_w    = (const float*)d_in[9];
    const float* v_w    = (const float*)d_in[10];
    const float* o_w    = (const float*)d_in[11];
    const float* gate_w = (const float*)d_in[12];
    const float* up_w   = (const float*)d_in[13];
    const float* down_w = (const float*)d_in[14];
    float* out = (float*)d_out;

    cudaFuncSetAttribute(tf32gemm_k, cudaFuncAttributeMaxDynamicSharedMemorySize, GEMM_SMEM);
    cudaFuncSetAttribute(tf32gemm_qkv_k, cudaFuncAttributeMaxDynamicSharedMemorySize, GEMM_SMEM);
    cudaFuncSetAttribute(flashattn_k, cudaFuncAttributeMaxDynamicSharedMemorySize, ATT_SMEM);

    float *x, *q, *k, *v, *attn, *h2, *y, *gate, *ff;
    cudaGetSymbolAddress((void**)&x, g_x);
    cudaGetSymbolAddress((void**)&q, g_q);
    cudaGetSymbolAddress((void**)&k, g_k);
    cudaGetSymbolAddress((void**)&v, g_v);
    cudaGetSymbolAddress((void**)&attn, g_attn);
    cudaGetSymbolAddress((void**)&h2, g_h2);
    cudaGetSymbolAddress((void**)&y, g_y);
    cudaGetSymbolAddress((void**)&gate, g_gate);
    cudaGetSymbolAddress((void**)&ff, g_ff);

    const int M = Mrows;

    rmsnorm_k<<<M, 256>>>(hidden, ln1, x);

    // fused q/k/v projection
    tf32gemm_qkv_k<<<dim3(12, M / GBM), 256, GEMM_SMEM>>>(x, q_w, k_w, v_w, q, k, v);

    {
        int warps_q = Bn * Tn * Hn;
        norm_rope_k<<<(warps_q * 32) / 256, 256>>>(q, qn, sinp, cosp, Hn);
        int warps_k = Bn * Tn * Gn;
        norm_rope_k<<<(warps_k * 32) / 256, 256>>>(k, kn, sinp, cosp, Gn);
    }

    flashattn_k<<<dim3(Tn / 32, Bn * Gn), 256, ATT_SMEM>>>(q, k, v, attn);

    // h2 = hidden + attn @ o_w
    gemm(attn, o_w, hidden, h2, M, Dn, Hn * Kn, 1);

    rmsnorm_k<<<M, 256>>>(h2, ln2, y);

    // gate = y @ gate_w ; ff = silu(gate) * (y @ up_w)
    gemm(y, gate_w, nullptr, gate, M, Fn, Dn, 0);
    gemm(y, up_w, gate, ff, M, Fn, Dn, 2);

    // out = h2 + ff @ down_w
    gemm(ff, down_w, h2, out, M, Dn, Fn, 1);
}

// round 8
// speedup vs baseline: 1.6442x; 1.5569x over previous
#include <cuda_runtime.h>
#include <cuda_fp16.h>
#include <math.h>
#include <stdint.h>

#define Bn 2
#define Tn 2048
#define Dn 1024
#define Hn 16
#define Gn 4
#define Kn 64
#define Rn (Hn / Gn)
#define Fn 4096
#define EPSF 1e-6f
#define Mrows (Bn * Tn)

// ---------------- scratch ----------------
__device__ __half g_x[Mrows * Dn];        // ln1 out (fp16, feeds qkv gemm)
__device__ float  g_q[Mrows * Hn * Kn];
__device__ float  g_k[Mrows * Gn * Kn];
__device__ float  g_v[Mrows * Gn * Kn];
__device__ __half g_attn[Mrows * Hn * Kn];// attention out (fp16, feeds o gemm)
__device__ float  g_h2[Mrows * Dn];       // residual stream (fp32)
__device__ __half g_y[Mrows * Dn];        // ln2 out (fp16)
__device__ float  g_gate[Mrows * Fn];     // gate pre-activation (fp32 aux)
__device__ __half g_ff[Mrows * Fn];       // silu(gate)*up (fp16, feeds down gemm)
// transposed fp16 weights [N][K]
__device__ __half g_wt_q[1024 * 1024];
__device__ __half g_wt_k[256 * 1024];
__device__ __half g_wt_v[256 * 1024];
__device__ __half g_wt_o[1024 * 1024];
__device__ __half g_wt_gate[4096 * 1024];
__device__ __half g_wt_up[4096 * 1024];
__device__ __half g_wt_down[1024 * 4096];

// ---------------- helpers ----------------
__device__ __forceinline__ uint32_t tf32_bits(float x) {
    uint32_t u;
    asm("cvt.rna.tf32.f32 %0, %1;" : "=r"(u) : "f"(x));
    return u;
}
__device__ __forceinline__ float tf32_rna(float x) {
    return __uint_as_float(tf32_bits(x));
}
__device__ __forceinline__ uint32_t smem_u32(const void* p) {
    return (uint32_t)__cvta_generic_to_shared(p);
}
__device__ __forceinline__ void cpa16(uint32_t dst, const void* src) {
    asm volatile("cp.async.cg.shared.global [%0], [%1], 16;" ::"r"(dst), "l"(src));
}
#define CP_COMMIT asm volatile("cp.async.commit_group;")
#define CP_WAIT0 asm volatile("cp.async.wait_group 0;")
#define CP_WAIT1 asm volatile("cp.async.wait_group 1;")

#define MMA_TF32(d, a0, a1, a2, a3, b0, b1)                                   \
    asm volatile(                                                             \
        "mma.sync.aligned.m16n8k8.row.col.f32.tf32.tf32.f32 "                 \
        "{%0,%1,%2,%3}, {%4,%5,%6,%7}, {%8,%9}, {%0,%1,%2,%3};"               \
        : "+f"(d[0]), "+f"(d[1]), "+f"(d[2]), "+f"(d[3])                      \
        : "r"(a0), "r"(a1), "r"(a2), "r"(a3), "r"(b0), "r"(b1))

#define MMA_F16(d, a0, a1, a2, a3, b0, b1)                                    \
    asm volatile(                                                             \
        "mma.sync.aligned.m16n8k16.row.col.f32.f16.f16.f32 "                  \
        "{%0,%1,%2,%3}, {%4,%5,%6,%7}, {%8,%9}, {%0,%1,%2,%3};"               \
        : "+f"(d[0]), "+f"(d[1]), "+f"(d[2]), "+f"(d[3])                      \
        : "r"(a0), "r"(a1), "r"(a2), "r"(a3), "r"(b0), "r"(b1))

// ---------------- fused weight transpose (+fp16 cvt): W[K][N] -> Wt[N][K] ----------------
__global__ void transpose_all_k(
    const float* __restrict__ q_w, const float* __restrict__ k_w,
    const float* __restrict__ v_w, const float* __restrict__ o_w,
    const float* __restrict__ gate_w, const float* __restrict__ up_w,
    const float* __restrict__ down_w,
    __half* __restrict__ tq, __half* __restrict__ tk, __half* __restrict__ tv,
    __half* __restrict__ to, __half* __restrict__ tg, __half* __restrict__ tu,
    __half* __restrict__ td) {
    __shared__ float t[32][33];
    int b = blockIdx.x;
    const float* W; __half* Wt; int K, N, base;
    if (b < 1024)       { W = q_w;    Wt = tq; K = 1024; N = 1024; base = 0; }
    else if (b < 1280)  { W = k_w;    Wt = tk; K = 1024; N = 256;  base = 1024; }
    else if (b < 1536)  { W = v_w;    Wt = tv; K = 1024; N = 256;  base = 1280; }
    else if (b < 2560)  { W = o_w;    Wt = to; K = 1024; N = 1024; base = 1536; }
    else if (b < 6656)  { W = gate_w; Wt = tg; K = 1024; N = 4096; base = 2560; }
    else if (b < 10752) { W = up_w;   Wt = tu; K = 1024; N = 4096; base = 6656; }
    else                { W = down_w; Wt = td; K = 4096; N = 1024; base = 10752; }
    int local = b - base;
    int nb = N >> 5;
    int bx = local % nb, by = local / nb;
    int x = threadIdx.x & 31, y = threadIdx.x >> 5;  // 32 x 8
#pragma unroll
    for (int j = 0; j < 4; j++)
        t[y + j * 8][x] = W[(size_t)(by * 32 + y + j * 8) * N + bx * 32 + x];
    __syncthreads();
#pragma unroll
    for (int j = 0; j < 4; j++)
        Wt[(size_t)(bx * 32 + y + j * 8) * K + by * 32 + x] = __float2half(t[x][y + j * 8]);
}

// ---------------- RMSNorm (fp32 in, fp16 out) ----------------
__global__ void rmsnorm_k(const float* __restrict__ in, const float* __restrict__ sc,
                          __half* __restrict__ out) {
    int row = blockIdx.x;
    const float* x = in + (size_t)row * Dn;
    float ss = 0.f;
    for (int i = threadIdx.x; i < Dn; i += blockDim.x) {
        float v = x[i];
        ss += v * v;
    }
    for (int o = 16; o; o >>= 1) ss += __shfl_xor_sync(0xFFFFFFFFu, ss, o);
    __shared__ float sm[8];
    int w = threadIdx.x >> 5;
    if ((threadIdx.x & 31) == 0) sm[w] = ss;
    __syncthreads();
    if (threadIdx.x == 0) {
        float tot = 0.f;
        for (int i = 0; i < 8; i++) tot += sm[i];
        sm[0] = tot;
    }
    __syncthreads();
    float inv = rsqrtf(sm[0] / (float)Dn + EPSF);
    __half* o = out + (size_t)row * Dn;
    for (int i = threadIdx.x; i < Dn; i += blockDim.x)
        o[i] = __float2half(x[i] * inv * sc[i]);
}

// ---------------- per-head RMSNorm + RoPE (fp32 q/k) ----------------
__global__ void norm_rope_k(float* __restrict__ qk, const float* __restrict__ nscale,
                            const float* __restrict__ sinp, const float* __restrict__ cosp,
                            int nheads) {
    int gw = (blockIdx.x * blockDim.x + threadIdx.x) >> 5;
    int lane = threadIdx.x & 31;
    int total = Bn * Tn * nheads;
    if (gw >= total) return;
    int bt = gw / nheads;
    float* p = qk + (size_t)gw * Kn;
    float x1 = p[lane];
    float x2 = p[lane + 32];
    float ss = x1 * x1 + x2 * x2;
    for (int o = 16; o; o >>= 1) ss += __shfl_xor_sync(0xFFFFFFFFu, ss, o);
    float inv = rsqrtf(ss / (float)Kn + EPSF);
    x1 = x1 * inv * nscale[lane];
    x2 = x2 * inv * nscale[lane + 32];
    float s = sinp[bt * (Kn / 2) + lane];
    float c = cosp[bt * (Kn / 2) + lane];
    p[lane]      = x1 * c - x2 * s;
    p[lane + 32] = x2 * c + x1 * s;
}

// ============================================================
// FP16 GEMM (mma.sync m16n8k16), cp.async 3-stage. 128x128x32 tile, 8 warps.
// A[M,Kd] fp16 row-major, Wt[N,Kd] fp16 row-major (i.e. B^T K-major).
// Modes: 0 plain, 1 +aux(fp32), 2 silu(aux fp32)*acc. ohalf: fp16 output.
// ============================================================
#define HBK 32                 // k halves per stage
#define HAS 40                 // halves per smem row (stride) -> banks 20r+fc, conflict-free
#define HG_STAGE 10240         // 128 * 40 * 2 bytes
#define HG_SMEM (2 * 3 * HG_STAGE)

__device__ __forceinline__ void hgemm_issue(uint32_t aB, uint32_t bB, int s,
                                            const __half* Arow, const __half* Brow,
                                            int k0, int Kd) {
    int tid = threadIdx.x;
#pragma unroll
    for (int j = 0; j < 2; j++) {
        int idx = tid + j * 256;
        int row = idx >> 2, ch = idx & 3;
        uint32_t dst = (uint32_t)(row * (HAS * 2) + ch * 16);
        cpa16(aB + s * HG_STAGE + dst, Arow + (size_t)row * Kd + k0 + ch * 8);
        cpa16(bB + s * HG_STAGE + dst, Brow + (size_t)row * Kd + k0 + ch * 8);
    }
}

__device__ __forceinline__ void hgemm_compute(int wm, int wn, int fr, int fc,
                                              const uint32_t* A32, const uint32_t* B32,
                                              float acc[4][4][4]) {
#pragma unroll
    for (int k2 = 0; k2 < 16; k2 += 8) {  // two k16 chunks (u32 offsets 0, 8)
        uint32_t af[4][4], bf[4][2];
#pragma unroll
        for (int mi = 0; mi < 4; mi++) {
            int r0 = wm * 64 + mi * 16 + fr;
            af[mi][0] = A32[r0 * 20 + k2 + fc];
            af[mi][1] = A32[(r0 + 8) * 20 + k2 + fc];
            af[mi][2] = A32[r0 * 20 + k2 + fc + 4];
            af[mi][3] = A32[(r0 + 8) * 20 + k2 + fc + 4];
        }
#pragma unroll
        for (int ni = 0; ni < 4; ni++) {
            int nc = wn * 32 + ni * 8 + fr;
            bf[ni][0] = B32[nc * 20 + k2 + fc];
            bf[ni][1] = B32[nc * 20 + k2 + fc + 4];
        }
#pragma unroll
        for (int mi = 0; mi < 4; mi++)
#pragma unroll
            for (int ni = 0; ni < 4; ni++)
                MMA_F16(acc[mi][ni], af[mi][0], af[mi][1], af[mi][2], af[mi][3],
                        bf[ni][0], bf[ni][1]);
    }
}

__device__ __forceinline__ void hgemm_body(const __half* A, const __half* Wt,
                                           const float* aux, void* Cv,
                                           int N, int Kd, int bx, int by,
                                           int mode, int ohalf, char* smn) {
    uint32_t aB = smem_u32(smn);
    uint32_t bB = aB + 3 * HG_STAGE;
    int tid = threadIdx.x;
    int lane = tid & 31, wid = tid >> 5;
    int wm = wid >> 2, wn = wid & 3;
    int fr = lane >> 2, fc = lane & 3;

    const __half* Arow = A + (size_t)(by * 128) * Kd;
    const __half* Brow = Wt + (size_t)(bx * 128) * Kd;

    float acc[4][4][4];
#pragma unroll
    for (int mi = 0; mi < 4; mi++)
#pragma unroll
        for (int ni = 0; ni < 4; ni++)
#pragma unroll
            for (int c = 0; c < 4; c++) acc[mi][ni][c] = 0.f;

    int nk = Kd / HBK;
    hgemm_issue(aB, bB, 0, Arow, Brow, 0, Kd); CP_COMMIT;
    hgemm_issue(aB, bB, 1, Arow, Brow, HBK, Kd); CP_COMMIT;

    for (int i = 0; i < nk; i++) {
        if (i + 1 < nk) { CP_WAIT1; } else { CP_WAIT0; }
        __syncthreads();
        if (i + 2 < nk) {
            hgemm_issue(aB, bB, (i + 2) % 3, Arow, Brow, (i + 2) * HBK, Kd);
            CP_COMMIT;
        }
        int s = i % 3;
        hgemm_compute(wm, wn, fr, fc,
                      (const uint32_t*)(smn + s * HG_STAGE),
                      (const uint32_t*)(smn + 3 * HG_STAGE + s * HG_STAGE), acc);
        __syncthreads();
    }

#pragma unroll
    for (int mi = 0; mi < 4; mi++) {
#pragma unroll
        for (int ni = 0; ni < 4; ni++) {
            int row = by * 128 + wm * 64 + mi * 16 + fr;
            int col = bx * 128 + wn * 32 + ni * 8 + fc * 2;
            float2 r0 = make_float2(acc[mi][ni][0], acc[mi][ni][1]);
            float2 r1 = make_float2(acc[mi][ni][2], acc[mi][ni][3]);
            if (mode == 1) {
                float2 h0 = *(const float2*)(aux + (size_t)row * N + col);
                float2 h1 = *(const float2*)(aux + (size_t)(row + 8) * N + col);
                r0.x += h0.x; r0.y += h0.y;
                r1.x += h1.x; r1.y += h1.y;
            } else if (mode == 2) {
                float2 g0 = *(const float2*)(aux + (size_t)row * N + col);
                float2 g1 = *(const float2*)(aux + (size_t)(row + 8) * N + col);
                r0.x *= g0.x / (1.f + __expf(-g0.x));
                r0.y *= g0.y / (1.f + __expf(-g0.y));
                r1.x *= g1.x / (1.f + __expf(-g1.x));
                r1.y *= g1.y / (1.f + __expf(-g1.y));
            }
            if (ohalf) {
                __half* C = (__half*)Cv;
                *(__half2*)(C + (size_t)row * N + col) = __floats2half2_rn(r0.x, r0.y);
                *(__half2*)(C + (size_t)(row + 8) * N + col) = __floats2half2_rn(r1.x, r1.y);
            } else {
                float* C = (float*)Cv;
                *(float2*)(C + (size_t)row * N + col) = r0;
                *(float2*)(C + (size_t)(row + 8) * N + col) = r1;
            }
        }
    }
}

__global__ __launch_bounds__(256, 2) void hgemm_k(
    const __half* __restrict__ A, const __half* __restrict__ Wt,
    const float* __restrict__ aux, void* __restrict__ C,
    int N, int Kd, int mode, int ohalf) {
    extern __shared__ char smn[];
    hgemm_body(A, Wt, aux, C, N, Kd, blockIdx.x, blockIdx.y, mode, ohalf, smn);
}

// fused q/k/v: bx 0..7 -> q (N=1024), 8..9 -> k, 10..11 -> v (N=256); fp32 out
__global__ __launch_bounds__(256, 2) void hgemm_qkv_k(
    const __half* __restrict__ A,
    const __half* __restrict__ Wtq, const __half* __restrict__ Wtk, const __half* __restrict__ Wtv,
    float* __restrict__ Cq, float* __restrict__ Ck, float* __restrict__ Cv) {
    extern __shared__ char smn[];
    int bx = blockIdx.x;
    const __half* Wt; float* C; int N;
    if (bx < 8)       { Wt = Wtq; C = Cq; N = 1024; }
    else if (bx < 10) { Wt = Wtk; C = Ck; N = 256; bx -= 8; }
    else              { Wt = Wtv; C = Cv; N = 256; bx -= 10; }
    hgemm_body(A, Wt, (const float*)0, C, N, Dn, bx, blockIdx.y, 0, 0, smn);
}

// ============================================================
// Flash attention (tf32 mma.sync), GQA-packed — unchanged math,
// epilogue writes fp16 for the o-proj GEMM.
// ============================================================
#define QSS 68
#define KSS 68
#define VSS 72
#define PSS 132
#define ATT_SMEM ((128 * QSS + 128 * KSS + 128 * VSS + 128 * PSS) * 4)

__global__ __launch_bounds__(256, 1) void flashattn_k(
    const float* __restrict__ q, const float* __restrict__ k,
    const float* __restrict__ v, __half* __restrict__ out) {
    extern __shared__ float sm[];
    float* Qs = sm;
    float* Ks = Qs + 128 * QSS;
    float* Vs = Ks + 128 * KSS;
    float* Ps = Vs + 128 * VSS;
    uint32_t qs_u = smem_u32(Qs), ks_u = smem_u32(Ks), vs_u = smem_u32(Vs);

    int tid = threadIdx.x;
    int lane = tid & 31, wid = tid >> 5;
    int fr = lane >> 2, fc = lane & 3;
    float* Pw = Ps + wid * 16 * PSS;

    int bg = blockIdx.y;
    int b = bg >> 2, g = bg & 3;
    int t0 = (gridDim.x - 1 - blockIdx.x) * 32;
    int ntiles = (t0 >> 7) + 1;

    const float* qbase = q + ((size_t)((size_t)b * Tn + t0) * Hn + g * Rn) * Kn;
    const float* kbase = k + ((size_t)b * Tn * Gn + g) * Kn;
    const float* vbase = v + ((size_t)b * Tn * Gn + g) * Kn;

#pragma unroll
    for (int i = 0; i < 8; i++) {
        int idx = tid + (i << 8);
        int m = idx >> 4, c4 = (idx & 15) << 2;
        cpa16(qs_u + (uint32_t)(m * QSS + c4) * 4,
              qbase + (size_t)(m >> 2) * (Hn * Kn) + (m & 3) * Kn + c4);
    }
    CP_COMMIT;
#pragma unroll
    for (int i = 0; i < 8; i++) {
        int idx = tid + (i << 8);
        int j = idx >> 4, c4 = (idx & 15) << 2;
        cpa16(ks_u + (uint32_t)(j * KSS + c4) * 4, kbase + (size_t)j * (Gn * Kn) + c4);
    }
    CP_COMMIT;
#pragma unroll
    for (int i = 0; i < 8; i++) {
        int idx = tid + (i << 8);
        int j = idx >> 4, c4 = (idx & 15) << 2;
        cpa16(vs_u + (uint32_t)(j * VSS + c4) * 4, vbase + (size_t)j * (Gn * Kn) + c4);
    }
    CP_COMMIT;
    CP_WAIT0;
    __syncthreads();

    float m_r[2], l_r[2], acco[8][4];
#pragma unroll
    for (int h = 0; h < 2; h++) { m_r[h] = -INFINITY; l_r[h] = 0.f; }
#pragma unroll
    for (int ni = 0; ni < 8; ni++)
#pragma unroll
        for (int c = 0; c < 4; c++) acco[ni][c] = 0.f;

    int r0 = wid * 16 + fr;

    for (int it = 0; it < ntiles; it++) {
        int s0 = it << 7;
        bool more = (it + 1 < ntiles);

        float accs[16][4];
#pragma unroll
        for (int ni = 0; ni < 16; ni++)
#pragma unroll
            for (int c = 0; c < 4; c++) accs[ni][c] = 0.f;

#pragma unroll
        for (int kc = 0; kc < 64; kc += 8) {
            uint32_t af[4];
            af[0] = tf32_bits(Qs[r0 * QSS + kc + fc]);
            af[1] = tf32_bits(Qs[(r0 + 8) * QSS + kc + fc]);
            af[2] = tf32_bits(Qs[r0 * QSS + kc + fc + 4]);
            af[3] = tf32_bits(Qs[(r0 + 8) * QSS + kc + fc + 4]);
#pragma unroll
            for (int ni = 0; ni < 16; ni++) {
                int nc = ni * 8 + fr;
                uint32_t b0 = tf32_bits(Ks[nc * KSS + kc + fc]);
                uint32_t b1 = tf32_bits(Ks[nc * KSS + kc + fc + 4]);
                MMA_TF32(accs[ni], af[0], af[1], af[2], af[3], b0, b1);
            }
        }

#pragma unroll
        for (int ni = 0; ni < 16; ni++)
#pragma unroll
            for (int c = 0; c < 4; c++) accs[ni][c] *= 0.125f;
        if (it == ntiles - 1) {
#pragma unroll
            for (int ni = 0; ni < 16; ni++)
#pragma unroll
                for (int c = 0; c < 4; c++) {
                    int row = r0 + ((c >= 2) ? 8 : 0);
                    int tt = t0 + (row >> 2);
                    int ss = s0 + ni * 8 + fc * 2 + (c & 1);
                    if (ss > tt) accs[ni][c] = -1e30f;
                }
        }

#pragma unroll
        for (int h = 0; h < 2; h++) {
            float mx = -1e30f;
#pragma unroll
            for (int ni = 0; ni < 16; ni++) {
                mx = fmaxf(mx, accs[ni][2 * h]);
                mx = fmaxf(mx, accs[ni][2 * h + 1]);
            }
            mx = fmaxf(mx, __shfl_xor_sync(0xFFFFFFFFu, mx, 1));
            mx = fmaxf(mx, __shfl_xor_sync(0xFFFFFFFFu, mx, 2));
            float mnew = fmaxf(m_r[h], mx);
            float corr = __expf(m_r[h] - mnew);
            m_r[h] = mnew;
            float sum = 0.f;
#pragma unroll
            for (int ni = 0; ni < 16; ni++) {
                float p0 = __expf(accs[ni][2 * h] - mnew);
                float p1 = __expf(accs[ni][2 * h + 1] - mnew);
                accs[ni][2 * h] = p0;
                accs[ni][2 * h + 1] = p1;
                sum += p0 + p1;
            }
            sum += __shfl_xor_sync(0xFFFFFFFFu, sum, 1);
            sum += __shfl_xor_sync(0xFFFFFFFFu, sum, 2);
            l_r[h] = l_r[h] * corr + sum;
#pragma unroll
            for (int ni = 0; ni < 8; ni++) {
                acco[ni][2 * h] *= corr;
                acco[ni][2 * h + 1] *= corr;
            }
        }

#pragma unroll
        for (int ni = 0; ni < 16; ni++) {
            int cc = ni * 8 + fc * 2;
            *(float2*)(Pw + fr * PSS + cc) =
                make_float2(tf32_rna(accs[ni][0]), tf32_rna(accs[ni][1]));
            *(float2*)(Pw + (fr + 8) * PSS + cc) =
                make_float2(tf32_rna(accs[ni][2]), tf32_rna(accs[ni][3]));
        }

        __syncthreads();
        if (more) {
            int sn = s0 + 128;
#pragma unroll
            for (int i = 0; i < 8; i++) {
                int idx = tid + (i << 8);
                int j = idx >> 4, c4 = (idx & 15) << 2;
                cpa16(ks_u + (uint32_t)(j * KSS + c4) * 4,
                      kbase + (size_t)(sn + j) * (Gn * Kn) + c4);
            }
            CP_COMMIT;
            CP_WAIT1;
        } else {
            CP_WAIT0;
        }
        __syncthreads();

#pragma unroll
        for (int kc = 0; kc < 128; kc += 8) {
            uint32_t af[4];
            af[0] = __float_as_uint(Pw[fr * PSS + kc + fc]);
            af[1] = __float_as_uint(Pw[(fr + 8) * PSS + kc + fc]);
            af[2] = __float_as_uint(Pw[fr * PSS + kc + fc + 4]);
            af[3] = __float_as_uint(Pw[(fr + 8) * PSS + kc + fc + 4]);
#pragma unroll
            for (int ni = 0; ni < 8; ni++) {
                int n0 = ni * 8 + fr;
                uint32_t b0 = tf32_bits(Vs[(kc + fc) * VSS + n0]);
                uint32_t b1 = tf32_bits(Vs[(kc + fc + 4) * VSS + n0]);
                MMA_TF32(acco[ni], af[0], af[1], af[2], af[3], b0, b1);
            }
        }
        __syncthreads();

        if (more) {
            int sn = s0 + 128;
#pragma unroll
            for (int i = 0; i < 8; i++) {
                int idx = tid + (i << 8);
                int j = idx >> 4, c4 = (idx & 15) << 2;
                cpa16(vs_u + (uint32_t)(j * VSS + c4) * 4,
                      vbase + (size_t)(sn + j) * (Gn * Kn) + c4);
            }
            CP_COMMIT;
            CP_WAIT1;
            __syncthreads();
        }
    }

#pragma unroll
    for (int h = 0; h < 2; h++) {
        float inv = 1.f / l_r[h];
        int row = r0 + 8 * h;
        int tt = t0 + (row >> 2);
        int hh = g * Rn + (row & 3);
        __half* op = out + ((size_t)((size_t)b * Tn + tt) * Hn + hh) * Kn;
#pragma unroll
        for (int ni = 0; ni < 8; ni++) {
            int col = ni * 8 + fc * 2;
            *(__half2*)(op + col) =
                __floats2half2_rn(acco[ni][2 * h] * inv, acco[ni][2 * h + 1] * inv);
        }
    }
}

// ---------------- launch ----------------
static void hgemm(const __half* A, const __half* Wt, const float* aux, void* C,
                  int M, int N, int Kd, int mode, int ohalf) {
    dim3 grid(N / 128, M / 128);
    hgemm_k<<<grid, 256, HG_SMEM>>>(A, Wt, aux, C, N, Kd, mode, ohalf);
}

extern "C" void kernel_launch(void* const* d_in, const int* in_sizes, int n_in,
                              void* d_out, int out_size) {
    const float* hidden = (const float*)d_in[0];
    const float* sinp   = (const float*)d_in[1];
    const float* cosp   = (const float*)d_in[2];
    /* d_in[3] = mask (exact causal tril; applied analytically) */
    const float* ln1    = (const float*)d_in[4];
    const float* ln2    = (const float*)d_in[5];
    const float* qn     = (const float*)d_in[6];
    const float* kn     = (const float*)d_in[7];
    const float* q_w    = (const float*)d_in[8];
    const float* k_w    = (const float*)d_in[9];
    const float* v_w    = (const float*)d_in[10];
    const float* o_w    = (const float*)d_in[11];
    const float* gate_w = (const float*)d_in[12];
    const float* up_w   = (const float*)d_in[13];
    const float* down_w = (const float*)d_in[14];
    float* out = (float*)d_out;

    cudaFuncSetAttribute(hgemm_k, cudaFuncAttributeMaxDynamicSharedMemorySize, HG_SMEM);
    cudaFuncSetAttribute(hgemm_qkv_k, cudaFuncAttributeMaxDynamicSharedMemorySize, HG_SMEM);
    cudaFuncSetAttribute(flashattn_k, cudaFuncAttributeMaxDynamicSharedMemorySize, ATT_SMEM);

    __half *x, *attn, *y, *ff;
    float *q, *k, *v, *h2, *gate;
    __half *tq, *tk, *tv, *to, *tg, *tu, *td;
    cudaGetSymbolAddress((void**)&x, g_x);
    cudaGetSymbolAddress((void**)&q, g_q);
    cudaGetSymbolAddress((void**)&k, g_k);
    cudaGetSymbolAddress((void**)&v, g_v);
    cudaGetSymbolAddress((void**)&attn, g_attn);
    cudaGetSymbolAddress((void**)&h2, g_h2);
    cudaGetSymbolAddress((void**)&y, g_y);
    cudaGetSymbolAddress((void**)&gate, g_gate);
    cudaGetSymbolAddress((void**)&ff, g_ff);
    cudaGetSymbolAddress((void**)&tq, g_wt_q);
    cudaGetSymbolAddress((void**)&tk, g_wt_k);
    cudaGetSymbolAddress((void**)&tv, g_wt_v);
    cudaGetSymbolAddress((void**)&to, g_wt_o);
    cudaGetSymbolAddress((void**)&tg, g_wt_gate);
    cudaGetSymbolAddress((void**)&tu, g_wt_up);
    cudaGetSymbolAddress((void**)&td, g_wt_down);

    const int M = Mrows;

    // 0. transpose + fp16-convert all weights
    transpose_all_k<<<14848, 256>>>(q_w, k_w, v_w, o_w, gate_w, up_w, down_w,
                                    tq, tk, tv, to, tg, tu, td);

    // 1. x = rmsnorm(hidden) -> fp16
    rmsnorm_k<<<M, 256>>>(hidden, ln1, x);

    // 2. fused q/k/v projection (fp16 x fp16 -> fp32)
    hgemm_qkv_k<<<dim3(12, M / 128), 256, HG_SMEM>>>(x, tq, tk, tv, q, k, v);

    // 3. head norm + rope (fp32)
    {
        int warps_q = Bn * Tn * Hn;
        norm_rope_k<<<(warps_q * 32) / 256, 256>>>(q, qn, sinp, cosp, Hn);
        int warps_k = Bn * Tn * Gn;
        norm_rope_k<<<(warps_k * 32) / 256, 256>>>(k, kn, sinp, cosp, Gn);
    }

    // 4. attention (tf32 mma; fp16 out)
    flashattn_k<<<dim3(Tn / 32, Bn * Gn), 256, ATT_SMEM>>>(q, k, v, attn);

    // 5. h2 = hidden + attn @ o_w (fp32 out)
    hgemm(attn, to, hidden, h2, M, Dn, Hn * Kn, 1, 0);

    // 6. y = rmsnorm(h2) -> fp16
    rmsnorm_k<<<M, 256>>>(h2, ln2, y);

    // 7. gate = y @ gate_w (fp32) ; ff = silu(gate) * (y @ up_w) -> fp16
    hgemm(y, tg, (const float*)0, gate, M, Fn, Dn, 0, 0);
    hgemm(y, tu, gate, ff, M, Fn, Dn, 2, 1);

    // 8. out = h2 + ff @ down_w (fp32)
    hgemm(ff, td, h2, out, M, Dn, Fn, 1, 0);
}

// round 9
// speedup vs baseline: 1.8187x; 1.1062x over previous
#include <cuda_runtime.h>
#include <cuda_fp16.h>
#include <math.h>
#include <stdint.h>

#define Bn 2
#define Tn 2048
#define Dn 1024
#define Hn 16
#define Gn 4
#define Kn 64
#define Rn (Hn / Gn)
#define Fn 4096
#define EPSF 1e-6f
#define Mrows (Bn * Tn)

// ---------------- scratch ----------------
__device__ __half g_x[Mrows * Dn];         // ln1 out (fp16)
__device__ float  g_q[Mrows * Hn * Kn];    // q proj fp32 (pre-rope)
__device__ float  g_k[Mrows * Gn * Kn];    // k proj fp32 (pre-rope)
__device__ __half g_v16[Mrows * Gn * Kn];  // v proj fp16
__device__ __half g_q16[Mrows * Hn * Kn];  // q post rope fp16
__device__ __half g_k16[Mrows * Gn * Kn];  // k post rope fp16
__device__ __half g_vt[Bn * Gn * Kn * Tn]; // V^T per (b,g): [64][T]
__device__ __half g_attn[Mrows * Hn * Kn];
__device__ float  g_h2[Mrows * Dn];
__device__ __half g_y[Mrows * Dn];
__device__ float  g_gate[Mrows * Fn];
__device__ __half g_ff[Mrows * Fn];
// transposed fp16 weights [N][K]
__device__ __half g_wt_q[1024 * 1024];
__device__ __half g_wt_k[256 * 1024];
__device__ __half g_wt_v[256 * 1024];
__device__ __half g_wt_o[1024 * 1024];
__device__ __half g_wt_gate[4096 * 1024];
__device__ __half g_wt_up[4096 * 1024];
__device__ __half g_wt_down[1024 * 4096];

// ---------------- helpers ----------------
__device__ __forceinline__ uint32_t smem_u32(const void* p) {
    return (uint32_t)__cvta_generic_to_shared(p);
}
__device__ __forceinline__ void cpa16(uint32_t dst, const void* src) {
    asm volatile("cp.async.cg.shared.global [%0], [%1], 16;" ::"r"(dst), "l"(src));
}
#define CP_COMMIT asm volatile("cp.async.commit_group;")
#define CP_WAIT0 asm volatile("cp.async.wait_group 0;")
#define CP_WAIT1 asm volatile("cp.async.wait_group 1;")

#define MMA_F16(d, a0, a1, a2, a3, b0, b1)                                    \
    asm volatile(                                                             \
        "mma.sync.aligned.m16n8k16.row.col.f32.f16.f16.f32 "                  \
        "{%0,%1,%2,%3}, {%4,%5,%6,%7}, {%8,%9}, {%0,%1,%2,%3};"               \
        : "+f"(d[0]), "+f"(d[1]), "+f"(d[2]), "+f"(d[3])                      \
        : "r"(a0), "r"(a1), "r"(a2), "r"(a3), "r"(b0), "r"(b1))

// ---------------- fused weight transpose (+fp16 cvt): W[K][N] -> Wt[N][K] ----------------
__global__ void transpose_all_k(
    const float* __restrict__ q_w, const float* __restrict__ k_w,
    const float* __restrict__ v_w, const float* __restrict__ o_w,
    const float* __restrict__ gate_w, const float* __restrict__ up_w,
    const float* __restrict__ down_w,
    __half* __restrict__ tq, __half* __restrict__ tk, __half* __restrict__ tv,
    __half* __restrict__ to, __half* __restrict__ tg, __half* __restrict__ tu,
    __half* __restrict__ td) {
    __shared__ float t[32][33];
    int b = blockIdx.x;
    const float* W; __half* Wt; int K, N, base;
    if (b < 1024)       { W = q_w;    Wt = tq; K = 1024; N = 1024; base = 0; }
    else if (b < 1280)  { W = k_w;    Wt = tk; K = 1024; N = 256;  base = 1024; }
    else if (b < 1536)  { W = v_w;    Wt = tv; K = 1024; N = 256;  base = 1280; }
    else if (b < 2560)  { W = o_w;    Wt = to; K = 1024; N = 1024; base = 1536; }
    else if (b < 6656)  { W = gate_w; Wt = tg; K = 1024; N = 4096; base = 2560; }
    else if (b < 10752) { W = up_w;   Wt = tu; K = 1024; N = 4096; base = 6656; }
    else                { W = down_w; Wt = td; K = 4096; N = 1024; base = 10752; }
    int local = b - base;
    int nb = N >> 5;
    int bx = local % nb, by = local / nb;
    int x = threadIdx.x & 31, y = threadIdx.x >> 5;  // 32 x 8
#pragma unroll
    for (int j = 0; j < 4; j++)
        t[y + j * 8][x] = W[(size_t)(by * 32 + y + j * 8) * N + bx * 32 + x];
    __syncthreads();
#pragma unroll
    for (int j = 0; j < 4; j++)
        Wt[(size_t)(bx * 32 + y + j * 8) * K + by * 32 + x] = __float2half(t[x][y + j * 8]);
}

// ---------------- V transpose: v16[bt][g][64] -> vt[(b,g)][64][Tn] ----------------
__global__ void vtrans_k(const __half* __restrict__ v16, __half* __restrict__ vt) {
    __shared__ __half t[32][33];
    int bg = blockIdx.z;          // b*Gn+g
    int b = bg >> 2, g = bg & 3;
    int t0 = blockIdx.x * 32;     // seq tile
    int d0 = blockIdx.y * 32;     // dim tile
    int x = threadIdx.x & 31, y = threadIdx.x >> 5;
#pragma unroll
    for (int j = 0; j < 4; j++) {
        int tt = t0 + y + j * 8;
        t[y + j * 8][x] = v16[((size_t)((size_t)b * Tn + tt) * Gn + g) * Kn + d0 + x];
    }
    __syncthreads();
#pragma unroll
    for (int j = 0; j < 4; j++) {
        int dd = d0 + y + j * 8;
        vt[((size_t)bg * Kn + dd) * Tn + t0 + x] = t[x][y + j * 8];
    }
}

// ---------------- RMSNorm (fp32 in, fp16 out) ----------------
__global__ void rmsnorm_k(const float* __restrict__ in, const float* __restrict__ sc,
                          __half* __restrict__ out) {
    int row = blockIdx.x;
    const float* x = in + (size_t)row * Dn;
    float ss = 0.f;
    for (int i = threadIdx.x; i < Dn; i += blockDim.x) {
        float v = x[i];
        ss += v * v;
    }
    for (int o = 16; o; o >>= 1) ss += __shfl_xor_sync(0xFFFFFFFFu, ss, o);
    __shared__ float sm[8];
    int w = threadIdx.x >> 5;
    if ((threadIdx.x & 31) == 0) sm[w] = ss;
    __syncthreads();
    if (threadIdx.x == 0) {
        float tot = 0.f;
        for (int i = 0; i < 8; i++) tot += sm[i];
        sm[0] = tot;
    }
    __syncthreads();
    float inv = rsqrtf(sm[0] / (float)Dn + EPSF);
    __half* o = out + (size_t)row * Dn;
    for (int i = threadIdx.x; i < Dn; i += blockDim.x)
        o[i] = __float2half(x[i] * inv * sc[i]);
}

// ---------------- per-head RMSNorm + RoPE (fp32 in, fp16 out) ----------------
__global__ void norm_rope_k(const float* __restrict__ qk, __half* __restrict__ out16,
                            const float* __restrict__ nscale,
                            const float* __restrict__ sinp, const float* __restrict__ cosp,
                            int nheads) {
    int gw = (blockIdx.x * blockDim.x + threadIdx.x) >> 5;
    int lane = threadIdx.x & 31;
    int total = Bn * Tn * nheads;
    if (gw >= total) return;
    int bt = gw / nheads;
    const float* p = qk + (size_t)gw * Kn;
    float x1 = p[lane];
    float x2 = p[lane + 32];
    float ss = x1 * x1 + x2 * x2;
    for (int o = 16; o; o >>= 1) ss += __shfl_xor_sync(0xFFFFFFFFu, ss, o);
    float inv = rsqrtf(ss / (float)Kn + EPSF);
    x1 = x1 * inv * nscale[lane];
    x2 = x2 * inv * nscale[lane + 32];
    float s = sinp[bt * (Kn / 2) + lane];
    float c = cosp[bt * (Kn / 2) + lane];
    __half* o = out16 + (size_t)gw * Kn;
    o[lane]      = __float2half(x1 * c - x2 * s);
    o[lane + 32] = __float2half(x2 * c + x1 * s);
}

// ============================================================
// FP16 GEMM (mma.sync m16n8k16), cp.async 3-stage. 128x128x32 tile, 8 warps.
// ============================================================
#define HBK 32
#define HAS 40
#define HG_STAGE 10240
#define HG_SMEM (2 * 3 * HG_STAGE)

__device__ __forceinline__ void hgemm_issue(uint32_t aB, uint32_t bB, int s,
                                            const __half* Arow, const __half* Brow,
                                            int k0, int Kd) {
    int tid = threadIdx.x;
#pragma unroll
    for (int j = 0; j < 2; j++) {
        int idx = tid + j * 256;
        int row = idx >> 2, ch = idx & 3;
        uint32_t dst = (uint32_t)(row * (HAS * 2) + ch * 16);
        cpa16(aB + s * HG_STAGE + dst, Arow + (size_t)row * Kd + k0 + ch * 8);
        cpa16(bB + s * HG_STAGE + dst, Brow + (size_t)row * Kd + k0 + ch * 8);
    }
}

__device__ __forceinline__ void hgemm_compute(int wm, int wn, int fr, int fc,
                                              const uint32_t* A32, const uint32_t* B32,
                                              float acc[4][4][4]) {
#pragma unroll
    for (int k2 = 0; k2 < 16; k2 += 8) {
        uint32_t af[4][4], bf[4][2];
#pragma unroll
        for (int mi = 0; mi < 4; mi++) {
            int r0 = wm * 64 + mi * 16 + fr;
            af[mi][0] = A32[r0 * 20 + k2 + fc];
            af[mi][1] = A32[(r0 + 8) * 20 + k2 + fc];
            af[mi][2] = A32[r0 * 20 + k2 + fc + 4];
            af[mi][3] = A32[(r0 + 8) * 20 + k2 + fc + 4];
        }
#pragma unroll
        for (int ni = 0; ni < 4; ni++) {
            int nc = wn * 32 + ni * 8 + fr;
            bf[ni][0] = B32[nc * 20 + k2 + fc];
            bf[ni][1] = B32[nc * 20 + k2 + fc + 4];
        }
#pragma unroll
        for (int mi = 0; mi < 4; mi++)
#pragma unroll
            for (int ni = 0; ni < 4; ni++)
                MMA_F16(acc[mi][ni], af[mi][0], af[mi][1], af[mi][2], af[mi][3],
                        bf[ni][0], bf[ni][1]);
    }
}

__device__ __forceinline__ void hgemm_body(const __half* A, const __half* Wt,
                                           const float* aux, void* Cv,
                                           int N, int Kd, int bx, int by,
                                           int mode, int ohalf, char* smn) {
    uint32_t aB = smem_u32(smn);
    uint32_t bB = aB + 3 * HG_STAGE;
    int tid = threadIdx.x;
    int lane = tid & 31, wid = tid >> 5;
    int wm = wid >> 2, wn = wid & 3;
    int fr = lane >> 2, fc = lane & 3;

    const __half* Arow = A + (size_t)(by * 128) * Kd;
    const __half* Brow = Wt + (size_t)(bx * 128) * Kd;

    float acc[4][4][4];
#pragma unroll
    for (int mi = 0; mi < 4; mi++)
#pragma unroll
        for (int ni = 0; ni < 4; ni++)
#pragma unroll
            for (int c = 0; c < 4; c++) acc[mi][ni][c] = 0.f;

    int nk = Kd / HBK;
    hgemm_issue(aB, bB, 0, Arow, Brow, 0, Kd); CP_COMMIT;
    hgemm_issue(aB, bB, 1, Arow, Brow, HBK, Kd); CP_COMMIT;

    for (int i = 0; i < nk; i++) {
        if (i + 1 < nk) { CP_WAIT1; } else { CP_WAIT0; }
        __syncthreads();
        if (i + 2 < nk) {
            hgemm_issue(aB, bB, (i + 2) % 3, Arow, Brow, (i + 2) * HBK, Kd);
            CP_COMMIT;
        }
        int s = i % 3;
        hgemm_compute(wm, wn, fr, fc,
                      (const uint32_t*)(smn + s * HG_STAGE),
                      (const uint32_t*)(smn + 3 * HG_STAGE + s * HG_STAGE), acc);
        __syncthreads();
    }

#pragma unroll
    for (int mi = 0; mi < 4; mi++) {
#pragma unroll
        for (int ni = 0; ni < 4; ni++) {
            int row = by * 128 + wm * 64 + mi * 16 + fr;
            int col = bx * 128 + wn * 32 + ni * 8 + fc * 2;
            float2 r0 = make_float2(acc[mi][ni][0], acc[mi][ni][1]);
            float2 r1 = make_float2(acc[mi][ni][2], acc[mi][ni][3]);
            if (mode == 1) {
                float2 h0 = *(const float2*)(aux + (size_t)row * N + col);
                float2 h1 = *(const float2*)(aux + (size_t)(row + 8) * N + col);
                r0.x += h0.x; r0.y += h0.y;
                r1.x += h1.x; r1.y += h1.y;
            } else if (mode == 2) {
                float2 g0 = *(const float2*)(aux + (size_t)row * N + col);
                float2 g1 = *(const float2*)(aux + (size_t)(row + 8) * N + col);
                r0.x *= g0.x / (1.f + __expf(-g0.x));
                r0.y *= g0.y / (1.f + __expf(-g0.y));
                r1.x *= g1.x / (1.f + __expf(-g1.x));
                r1.y *= g1.y / (1.f + __expf(-g1.y));
            }
            if (ohalf) {
                __half* C = (__half*)Cv;
                *(__half2*)(C + (size_t)row * N + col) = __floats2half2_rn(r0.x, r0.y);
                *(__half2*)(C + (size_t)(row + 8) * N + col) = __floats2half2_rn(r1.x, r1.y);
            } else {
                float* C = (float*)Cv;
                *(float2*)(C + (size_t)row * N + col) = r0;
                *(float2*)(C + (size_t)(row + 8) * N + col) = r1;
            }
        }
    }
}

__global__ __launch_bounds__(256, 2) void hgemm_k(
    const __half* __restrict__ A, const __half* __restrict__ Wt,
    const float* __restrict__ aux, void* __restrict__ C,
    int N, int Kd, int mode, int ohalf) {
    extern __shared__ char smn[];
    hgemm_body(A, Wt, aux, C, N, Kd, blockIdx.x, blockIdx.y, mode, ohalf, smn);
}

// fused q/k/v: bx 0..7 -> q (fp32), 8..9 -> k (fp32), 10..11 -> v (fp16)
__global__ __launch_bounds__(256, 2) void hgemm_qkv_k(
    const __half* __restrict__ A,
    const __half* __restrict__ Wtq, const __half* __restrict__ Wtk, const __half* __restrict__ Wtv,
    float* __restrict__ Cq, float* __restrict__ Ck, __half* __restrict__ Cv) {
    extern __shared__ char smn[];
    int bx = blockIdx.x;
    const __half* Wt; void* C; int N; int oh;
    if (bx < 8)       { Wt = Wtq; C = Cq; N = 1024; oh = 0; }
    else if (bx < 10) { Wt = Wtk; C = Ck; N = 256; bx -= 8; oh = 0; }
    else              { Wt = Wtv; C = Cv; N = 256; bx -= 10; oh = 1; }
    hgemm_body(A, Wt, (const float*)0, C, N, Dn, bx, blockIdx.y, 0, oh, smn);
}

// ============================================================
// Flash attention, FULL FP16 MMA (m16n8k16), GQA-packed.
// M-tile = 32 t x 4 r = 128 rows; warp owns 16 complete rows.
// Q/K tiles [128][64] fp16 (stride 72h), V^T tile [64][128] fp16 (stride 136h),
// P warp-private fp16 [16][128] (stride 136h).
// ============================================================
#define QSH 72   // halves stride (36 u32)
#define VTH 136  // halves stride (68 u32)
#define PSH 136
#define ATT_SMEM ((128 * QSH + 128 * QSH + 64 * VTH + 128 * PSH) * 2)

__global__ __launch_bounds__(256, 2) void flashattn_k(
    const __half* __restrict__ q16, const __half* __restrict__ k16,
    const __half* __restrict__ vt, __half* __restrict__ out) {
    extern __shared__ __half smh[];
    __half* Qs = smh;
    __half* Ks = Qs + 128 * QSH;
    __half* Vs = Ks + 128 * QSH;
    __half* Ps = Vs + 64 * VTH;
    uint32_t qs_u = smem_u32(Qs), ks_u = smem_u32(Ks), vs_u = smem_u32(Vs);
    const uint32_t* Q32 = (const uint32_t*)Qs;
    const uint32_t* K32 = (const uint32_t*)Ks;
    const uint32_t* V32 = (const uint32_t*)Vs;

    int tid = threadIdx.x;
    int lane = tid & 31, wid = tid >> 5;
    int fr = lane >> 2, fc = lane & 3;
    __half* Pw = Ps + wid * 16 * PSH;
    const uint32_t* Pw32 = (const uint32_t*)Pw;

    int bg = blockIdx.y;
    int b = bg >> 2, g = bg & 3;
    int t0 = (gridDim.x - 1 - blockIdx.x) * 32;
    int ntiles = (t0 >> 7) + 1;

    const __half* qbase = q16 + ((size_t)((size_t)b * Tn + t0) * Hn + g * Rn) * Kn;
    const __half* kbase = k16 + ((size_t)b * Tn * Gn + g) * Kn;
    const __half* vtbase = vt + (size_t)bg * Kn * Tn;

    // Q: 128 rows x 64 halves = 1024 16B-chunks
#pragma unroll
    for (int i = 0; i < 4; i++) {
        int idx = tid + (i << 8);
        int m = idx >> 3, ch = idx & 7;
        cpa16(qs_u + (uint32_t)(m * QSH * 2 + ch * 16),
              qbase + (size_t)(m >> 2) * (Hn * Kn) + (m & 3) * Kn + ch * 8);
    }
    CP_COMMIT;
    // K tile
#pragma unroll
    for (int i = 0; i < 4; i++) {
        int idx = tid + (i << 8);
        int j = idx >> 3, ch = idx & 7;
        cpa16(ks_u + (uint32_t)(j * QSH * 2 + ch * 16),
              kbase + (size_t)j * (Gn * Kn) + ch * 8);
    }
    CP_COMMIT;
    // V^T tile: 64 rows x 128 halves = 1024 chunks
#pragma unroll
    for (int i = 0; i < 4; i++) {
        int idx = tid + (i << 8);
        int d = idx >> 4, ch = idx & 15;
        cpa16(vs_u + (uint32_t)(d * VTH * 2 + ch * 16),
              vtbase + (size_t)d * Tn + 0 + ch * 8);
    }
    CP_COMMIT;
    CP_WAIT0;
    __syncthreads();

    float m_r[2], l_r[2], acco[8][4];
#pragma unroll
    for (int h = 0; h < 2; h++) { m_r[h] = -INFINITY; l_r[h] = 0.f; }
#pragma unroll
    for (int ni = 0; ni < 8; ni++)
#pragma unroll
        for (int c = 0; c < 4; c++) acco[ni][c] = 0.f;

    int r0 = wid * 16 + fr;

    for (int it = 0; it < ntiles; it++) {
        int s0 = it << 7;
        bool more = (it + 1 < ntiles);

        // ---- S = Q @ K^T : fp16 MMA, 4 k-chunks x 16 n-tiles ----
        float accs[16][4];
#pragma unroll
        for (int ni = 0; ni < 16; ni++)
#pragma unroll
            for (int c = 0; c < 4; c++) accs[ni][c] = 0.f;

#pragma unroll
        for (int kc = 0; kc < 32; kc += 8) {  // u32 units; 32 u32 = 64 halves
            uint32_t af[4];
            af[0] = Q32[r0 * 36 + kc + fc];
            af[1] = Q32[(r0 + 8) * 36 + kc + fc];
            af[2] = Q32[r0 * 36 + kc + fc + 4];
            af[3] = Q32[(r0 + 8) * 36 + kc + fc + 4];
#pragma unroll
            for (int ni = 0; ni < 16; ni++) {
                int nc = ni * 8 + fr;
                uint32_t b0 = K32[nc * 36 + kc + fc];
                uint32_t b1 = K32[nc * 36 + kc + fc + 4];
                MMA_F16(accs[ni], af[0], af[1], af[2], af[3], b0, b1);
            }
        }

#pragma unroll
        for (int ni = 0; ni < 16; ni++)
#pragma unroll
            for (int c = 0; c < 4; c++) accs[ni][c] *= 0.125f;
        if (it == ntiles - 1) {
#pragma unroll
            for (int ni = 0; ni < 16; ni++)
#pragma unroll
                for (int c = 0; c < 4; c++) {
                    int row = r0 + ((c >= 2) ? 8 : 0);
                    int tt = t0 + (row >> 2);
                    int ss = s0 + ni * 8 + fc * 2 + (c & 1);
                    if (ss > tt) accs[ni][c] = -1e30f;
                }
        }

        // ---- online softmax (rows fully warp-owned) ----
#pragma unroll
        for (int h = 0; h < 2; h++) {
            float mx = -1e30f;
#pragma unroll
            for (int ni = 0; ni < 16; ni++) {
                mx = fmaxf(mx, accs[ni][2 * h]);
                mx = fmaxf(mx, accs[ni][2 * h + 1]);
            }
            mx = fmaxf(mx, __shfl_xor_sync(0xFFFFFFFFu, mx, 1));
            mx = fmaxf(mx, __shfl_xor_sync(0xFFFFFFFFu, mx, 2));
            float mnew = fmaxf(m_r[h], mx);
            float corr = __expf(m_r[h] - mnew);
            m_r[h] = mnew;
            float sum = 0.f;
#pragma unroll
            for (int ni = 0; ni < 16; ni++) {
                float p0 = __expf(accs[ni][2 * h] - mnew);
                float p1 = __expf(accs[ni][2 * h + 1] - mnew);
                accs[ni][2 * h] = p0;
                accs[ni][2 * h + 1] = p1;
                sum += p0 + p1;
            }
            sum += __shfl_xor_sync(0xFFFFFFFFu, sum, 1);
            sum += __shfl_xor_sync(0xFFFFFFFFu, sum, 2);
            l_r[h] = l_r[h] * corr + sum;
#pragma unroll
            for (int ni = 0; ni < 8; ni++) {
                acco[ni][2 * h] *= corr;
                acco[ni][2 * h + 1] *= corr;
            }
        }

        // ---- P -> warp-private smem (fp16) ----
#pragma unroll
        for (int ni = 0; ni < 16; ni++) {
            int cc = ni * 8 + fc * 2;
            *(__half2*)(Pw + fr * PSH + cc) = __floats2half2_rn(accs[ni][0], accs[ni][1]);
            *(__half2*)(Pw + (fr + 8) * PSH + cc) = __floats2half2_rn(accs[ni][2], accs[ni][3]);
        }

        __syncthreads();  // Ks reads done
        if (more) {
            int sn = s0 + 128;
#pragma unroll
            for (int i = 0; i < 4; i++) {
                int idx = tid + (i << 8);
                int j = idx >> 3, ch = idx & 7;
                cpa16(ks_u + (uint32_t)(j * QSH * 2 + ch * 16),
                      kbase + (size_t)(sn + j) * (Gn * Kn) + ch * 8);
            }
            CP_COMMIT;
            CP_WAIT1;  // V(it) done
        } else {
            CP_WAIT0;
        }
        __syncthreads();

        // ---- O += P @ V : fp16 MMA, 8 k-chunks x 8 n-tiles ----
#pragma unroll
        for (int kc = 0; kc < 64; kc += 8) {  // u32 units; 64 u32 = 128 halves
            uint32_t af[4];
            af[0] = Pw32[fr * 68 + kc + fc];
            af[1] = Pw32[(fr + 8) * 68 + kc + fc];
            af[2] = Pw32[fr * 68 + kc + fc + 4];
            af[3] = Pw32[(fr + 8) * 68 + kc + fc + 4];
#pragma unroll
            for (int ni = 0; ni < 8; ni++) {
                int n0 = ni * 8 + fr;
                uint32_t b0 = V32[n0 * 68 + kc + fc];
                uint32_t b1 = V32[n0 * 68 + kc + fc + 4];
                MMA_F16(acco[ni], af[0], af[1], af[2], af[3], b0, b1);
            }
        }
        __syncthreads();  // Vs reads done

        if (more) {
            int sn = s0 + 128;
#pragma unroll
            for (int i = 0; i < 4; i++) {
                int idx = tid + (i << 8);
                int d = idx >> 4, ch = idx & 15;
                cpa16(vs_u + (uint32_t)(d * VTH * 2 + ch * 16),
                      vtbase + (size_t)d * Tn + sn + ch * 8);
            }
            CP_COMMIT;
            CP_WAIT1;  // K(it+1) done
            __syncthreads();
        }
    }

    // ---- epilogue: O / l -> fp16 ----
#pragma unroll
    for (int h = 0; h < 2; h++) {
        float inv = 1.f / l_r[h];
        int row = r0 + 8 * h;
        int tt = t0 + (row >> 2);
        int hh = g * Rn + (row & 3);
        __half* op = out + ((size_t)((size_t)b * Tn + tt) * Hn + hh) * Kn;
#pragma unroll
        for (int ni = 0; ni < 8; ni++) {
            int col = ni * 8 + fc * 2;
            *(__half2*)(op + col) =
                __floats2half2_rn(acco[ni][2 * h] * inv, acco[ni][2 * h + 1] * inv);
        }
    }
}

// ---------------- launch ----------------
static void hgemm(const __half* A, const __half* Wt, const float* aux, void* C,
                  int M, int N, int Kd, int mode, int ohalf) {
    dim3 grid(N / 128, M / 128);
    hgemm_k<<<grid, 256, HG_SMEM>>>(A, Wt, aux, C, N, Kd, mode, ohalf);
}

extern "C" void kernel_launch(void* const* d_in, const int* in_sizes, int n_in,
                              void* d_out, int out_size) {
    const float* hidden = (const float*)d_in[0];
    const float* sinp   = (const float*)d_in[1];
    const float* cosp   = (const float*)d_in[2];
    /* d_in[3] = mask (exact causal tril; applied analytically) */
    const float* ln1    = (const float*)d_in[4];
    const float* ln2    = (const float*)d_in[5];
    const float* qn     = (const float*)d_in[6];
    const float* kn     = (const float*)d_in[7];
    const float* q_w    = (const float*)d_in[8];
    const float* k_w    = (const float*)d_in[9];
    const float* v_w    = (const float*)d_in[10];
    const float* o_w    = (const float*)d_in[11];
    const float* gate_w = (const float*)d_in[12];
    const float* up_w   = (const float*)d_in[13];
    const float* down_w = (const float*)d_in[14];
    float* out = (float*)d_out;

    cudaFuncSetAttribute(hgemm_k, cudaFuncAttributeMaxDynamicSharedMemorySize, HG_SMEM);
    cudaFuncSetAttribute(hgemm_qkv_k, cudaFuncAttributeMaxDynamicSharedMemorySize, HG_SMEM);
    cudaFuncSetAttribute(flashattn_k, cudaFuncAttributeMaxDynamicSharedMemorySize, ATT_SMEM);

    __half *x, *v16, *q16, *k16, *vt, *attn, *y, *ff;
    float *q, *k, *h2, *gate;
    __half *tq, *tk, *tv, *to, *tg, *tu, *td;
    cudaGetSymbolAddress((void**)&x, g_x);
    cudaGetSymbolAddress((void**)&q, g_q);
    cudaGetSymbolAddress((void**)&k, g_k);
    cudaGetSymbolAddress((void**)&v16, g_v16);
    cudaGetSymbolAddress((void**)&q16, g_q16);
    cudaGetSymbolAddress((void**)&k16, g_k16);
    cudaGetSymbolAddress((void**)&vt, g_vt);
    cudaGetSymbolAddress((void**)&attn, g_attn);
    cudaGetSymbolAddress((void**)&h2, g_h2);
    cudaGetSymbolAddress((void**)&y, g_y);
    cudaGetSymbolAddress((void**)&gate, g_gate);
    cudaGetSymbolAddress((void**)&ff, g_ff);
    cudaGetSymbolAddress((void**)&tq, g_wt_q);
    cudaGetSymbolAddress((void**)&tk, g_wt_k);
    cudaGetSymbolAddress((void**)&tv, g_wt_v);
    cudaGetSymbolAddress((void**)&to, g_wt_o);
    cudaGetSymbolAddress((void**)&tg, g_wt_gate);
    cudaGetSymbolAddress((void**)&tu, g_wt_up);
    cudaGetSymbolAddress((void**)&td, g_wt_down);

    const int M = Mrows;

    // 0. transpose + fp16-convert all weights
    transpose_all_k<<<14848, 256>>>(q_w, k_w, v_w, o_w, gate_w, up_w, down_w,
                                    tq, tk, tv, to, tg, tu, td);

    // 1. x = rmsnorm(hidden) -> fp16
    rmsnorm_k<<<M, 256>>>(hidden, ln1, x);

    // 2. fused q/k/v projection (q,k fp32; v fp16)
    hgemm_qkv_k<<<dim3(12, M / 128), 256, HG_SMEM>>>(x, tq, tk, tv, q, k, v16);

    // 3. head norm + rope -> fp16 q/k; V^T build
    {
        int warps_q = Bn * Tn * Hn;
        norm_rope_k<<<(warps_q * 32) / 256, 256>>>(q, q16, qn, sinp, cosp, Hn);
        int warps_k = Bn * Tn * Gn;
        norm_rope_k<<<(warps_k * 32) / 256, 256>>>(k, k16, kn, sinp, cosp, Gn);
        vtrans_k<<<dim3(Tn / 32, Kn / 32, Bn * Gn), 256>>>(v16, vt);
    }

    // 4. attention (fp16 mma; fp16 out)
    flashattn_k<<<dim3(Tn / 32, Bn * Gn), 256, ATT_SMEM>>>(q16, k16, vt, attn);

    // 5. h2 = hidden + attn @ o_w (fp32 out)
    hgemm(attn, to, hidden, h2, M, Dn, Hn * Kn, 1, 0);

    // 6. y = rmsnorm(h2) -> fp16
    rmsnorm_k<<<M, 256>>>(h2, ln2, y);

    // 7. gate = y @ gate_w (fp32) ; ff = silu(gate) * (y @ up_w) -> fp16
    hgemm(y, tg, (const float*)0, gate, M, Fn, Dn, 0, 0);
    hgemm(y, tu, gate, ff, M, Fn, Dn, 2, 1);

    // 8. out = h2 + ff @ down_w (fp32)
    hgemm(ff, td, h2, out, M, Dn, Fn, 1, 0);
}

// round 10
// speedup vs baseline: 2.0261x; 1.1140x over previous
#include <cuda_runtime.h>
#include <cuda_fp16.h>
#include <math.h>
#include <stdint.h>

#define Bn 2
#define Tn 2048
#define Dn 1024
#define Hn 16
#define Gn 4
#define Kn 64
#define Rn (Hn / Gn)
#define Fn 4096
#define EPSF 1e-6f
#define Mrows (Bn * Tn)

// ---------------- scratch ----------------
__device__ __half g_x[Mrows * Dn];
__device__ float  g_q[Mrows * Hn * Kn];
__device__ float  g_k[Mrows * Gn * Kn];
__device__ __half g_v16[Mrows * Gn * Kn];
__device__ __half g_q16[Mrows * Hn * Kn];
__device__ __half g_k16[Mrows * Gn * Kn];
__device__ __half g_vt[Bn * Gn * Kn * Tn];
__device__ __half g_attn[Mrows * Hn * Kn];
__device__ float  g_h2[Mrows * Dn];
__device__ __half g_y[Mrows * Dn];
__device__ float  g_gate[Mrows * Fn];
__device__ __half g_ff[Mrows * Fn];
__device__ __half g_wt_q[1024 * 1024];
__device__ __half g_wt_k[256 * 1024];
__device__ __half g_wt_v[256 * 1024];
__device__ __half g_wt_o[1024 * 1024];
__device__ __half g_wt_gate[4096 * 1024];
__device__ __half g_wt_up[4096 * 1024];
__device__ __half g_wt_down[1024 * 4096];

// ---------------- helpers ----------------
__device__ __forceinline__ uint32_t smem_u32(const void* p) {
    return (uint32_t)__cvta_generic_to_shared(p);
}
__device__ __forceinline__ void cpa16(uint32_t dst, const void* src) {
    asm volatile("cp.async.cg.shared.global [%0], [%1], 16;" ::"r"(dst), "l"(src));
}
#define CP_COMMIT asm volatile("cp.async.commit_group;")
#define CP_WAIT0 asm volatile("cp.async.wait_group 0;")
#define CP_WAIT1 asm volatile("cp.async.wait_group 1;")

#define MMA_F16(d, a0, a1, a2, a3, b0, b1)                                    \
    asm volatile(                                                             \
        "mma.sync.aligned.m16n8k16.row.col.f32.f16.f16.f32 "                  \
        "{%0,%1,%2,%3}, {%4,%5,%6,%7}, {%8,%9}, {%0,%1,%2,%3};"               \
        : "+f"(d[0]), "+f"(d[1]), "+f"(d[2]), "+f"(d[3])                      \
        : "r"(a0), "r"(a1), "r"(a2), "r"(a3), "r"(b0), "r"(b1))

#define LDSM_X4(r0, r1, r2, r3, addr)                                         \
    asm volatile("ldmatrix.sync.aligned.m8n8.x4.shared.b16 {%0,%1,%2,%3}, [%4];" \
                 : "=r"(r0), "=r"(r1), "=r"(r2), "=r"(r3) : "r"(addr))

// ---------------- fused weight transpose (+fp16 cvt): W[K][N] -> Wt[N][K] ----------------
__global__ void transpose_all_k(
    const float* __restrict__ q_w, const float* __restrict__ k_w,
    const float* __restrict__ v_w, const float* __restrict__ o_w,
    const float* __restrict__ gate_w, const float* __restrict__ up_w,
    const float* __restrict__ down_w,
    __half* __restrict__ tq, __half* __restrict__ tk, __half* __restrict__ tv,
    __half* __restrict__ to, __half* __restrict__ tg, __half* __restrict__ tu,
    __half* __restrict__ td) {
    __shared__ float t[32][33];
    int b = blockIdx.x;
    const float* W; __half* Wt; int K, N, base;
    if (b < 1024)       { W = q_w;    Wt = tq; K = 1024; N = 1024; base = 0; }
    else if (b < 1280)  { W = k_w;    Wt = tk; K = 1024; N = 256;  base = 1024; }
    else if (b < 1536)  { W = v_w;    Wt = tv; K = 1024; N = 256;  base = 1280; }
    else if (b < 2560)  { W = o_w;    Wt = to; K = 1024; N = 1024; base = 1536; }
    else if (b < 6656)  { W = gate_w; Wt = tg; K = 1024; N = 4096; base = 2560; }
    else if (b < 10752) { W = up_w;   Wt = tu; K = 1024; N = 4096; base = 6656; }
    else                { W = down_w; Wt = td; K = 4096; N = 1024; base = 10752; }
    int local = b - base;
    int nb = N >> 5;
    int bx = local % nb, by = local / nb;
    int x = threadIdx.x & 31, y = threadIdx.x >> 5;
#pragma unroll
    for (int j = 0; j < 4; j++)
        t[y + j * 8][x] = W[(size_t)(by * 32 + y + j * 8) * N + bx * 32 + x];
    __syncthreads();
#pragma unroll
    for (int j = 0; j < 4; j++)
        Wt[(size_t)(bx * 32 + y + j * 8) * K + by * 32 + x] = __float2half(t[x][y + j * 8]);
}

// ---------------- V transpose ----------------
__global__ void vtrans_k(const __half* __restrict__ v16, __half* __restrict__ vt) {
    __shared__ __half t[32][33];
    int bg = blockIdx.z;
    int b = bg >> 2, g = bg & 3;
    int t0 = blockIdx.x * 32;
    int d0 = blockIdx.y * 32;
    int x = threadIdx.x & 31, y = threadIdx.x >> 5;
#pragma unroll
    for (int j = 0; j < 4; j++) {
        int tt = t0 + y + j * 8;
        t[y + j * 8][x] = v16[((size_t)((size_t)b * Tn + tt) * Gn + g) * Kn + d0 + x];
    }
    __syncthreads();
#pragma unroll
    for (int j = 0; j < 4; j++) {
        int dd = d0 + y + j * 8;
        vt[((size_t)bg * Kn + dd) * Tn + t0 + x] = t[x][y + j * 8];
    }
}

// ---------------- RMSNorm (fp32 in, fp16 out), float4 loads ----------------
__global__ void rmsnorm_k(const float* __restrict__ in, const float* __restrict__ sc,
                          __half* __restrict__ out) {
    int row = blockIdx.x;
    const float4* x4 = (const float4*)(in + (size_t)row * Dn);
    float4 v = x4[threadIdx.x];
    float ss = v.x * v.x + v.y * v.y + v.z * v.z + v.w * v.w;
    for (int o = 16; o; o >>= 1) ss += __shfl_xor_sync(0xFFFFFFFFu, ss, o);
    __shared__ float sm[8];
    int w = threadIdx.x >> 5;
    if ((threadIdx.x & 31) == 0) sm[w] = ss;
    __syncthreads();
    if (threadIdx.x == 0) {
        float tot = 0.f;
        for (int i = 0; i < 8; i++) tot += sm[i];
        sm[0] = tot;
    }
    __syncthreads();
    float inv = rsqrtf(sm[0] / (float)Dn + EPSF);
    float4 s4 = ((const float4*)sc)[threadIdx.x];
    __half2* o2 = (__half2*)(out + (size_t)row * Dn) + threadIdx.x * 2;
    o2[0] = __floats2half2_rn(v.x * inv * s4.x, v.y * inv * s4.y);
    o2[1] = __floats2half2_rn(v.z * inv * s4.z, v.w * inv * s4.w);
}

// ---------------- per-head RMSNorm + RoPE (fp32 in, fp16 out) ----------------
__global__ void norm_rope_k(const float* __restrict__ qk, __half* __restrict__ out16,
                            const float* __restrict__ nscale,
                            const float* __restrict__ sinp, const float* __restrict__ cosp,
                            int nheads) {
    int gw = (blockIdx.x * blockDim.x + threadIdx.x) >> 5;
    int lane = threadIdx.x & 31;
    int total = Bn * Tn * nheads;
    if (gw >= total) return;
    int bt = gw / nheads;
    const float* p = qk + (size_t)gw * Kn;
    float x1 = p[lane];
    float x2 = p[lane + 32];
    float ss = x1 * x1 + x2 * x2;
    for (int o = 16; o; o >>= 1) ss += __shfl_xor_sync(0xFFFFFFFFu, ss, o);
    float inv = rsqrtf(ss / (float)Kn + EPSF);
    x1 = x1 * inv * nscale[lane];
    x2 = x2 * inv * nscale[lane + 32];
    float s = sinp[bt * (Kn / 2) + lane];
    float c = cosp[bt * (Kn / 2) + lane];
    __half* o = out16 + (size_t)gw * Kn;
    o[lane]      = __float2half(x1 * c - x2 * s);
    o[lane + 32] = __float2half(x2 * c + x1 * s);
}

// ============================================================
// FP16 GEMM, ldmatrix fragments, single-sync 3-stage cp.async.
// 128x128x32 tile, 8 warps (2x4), warp tile 64x32.
// ============================================================
#define HBK 32
#define HAS 40                 // halves stride (80 B)
#define HG_STAGE 10240
#define HG_SMEM (2 * 3 * HG_STAGE)

__device__ __forceinline__ void hgemm_issue(uint32_t aB, uint32_t bB, int s,
                                            const __half* Arow, const __half* Brow,
                                            int k0, int Kd) {
    int tid = threadIdx.x;
#pragma unroll
    for (int j = 0; j < 2; j++) {
        int idx = tid + j * 256;
        int row = idx >> 2, ch = idx & 3;
        uint32_t dst = (uint32_t)(row * (HAS * 2) + ch * 16);
        cpa16(aB + s * HG_STAGE + dst, Arow + (size_t)row * Kd + k0 + ch * 8);
        cpa16(bB + s * HG_STAGE + dst, Brow + (size_t)row * Kd + k0 + ch * 8);
    }
}

__device__ __forceinline__ void hgemm_compute(uint32_t aAddr, uint32_t bAddr,
                                              float acc[4][4][4]) {
#pragma unroll
    for (int k2 = 0; k2 < 2; k2++) {  // two k16 chunks: byte offset k2*32
        uint32_t af[4][4], bf[4][2];
#pragma unroll
        for (int mi = 0; mi < 4; mi++)
            LDSM_X4(af[mi][0], af[mi][1], af[mi][2], af[mi][3],
                    aAddr + mi * 16 * 80 + k2 * 32);
#pragma unroll
        for (int p = 0; p < 2; p++)
            LDSM_X4(bf[2 * p][0], bf[2 * p][1], bf[2 * p + 1][0], bf[2 * p + 1][1],
                    bAddr + p * 16 * 80 + k2 * 32);
#pragma unroll
        for (int mi = 0; mi < 4; mi++)
#pragma unroll
            for (int ni = 0; ni < 4; ni++)
                MMA_F16(acc[mi][ni], af[mi][0], af[mi][1], af[mi][2], af[mi][3],
                        bf[ni][0], bf[ni][1]);
    }
}

__device__ __forceinline__ void hgemm_body(const __half* A, const __half* Wt,
                                           const float* aux, void* Cv,
                                           int N, int Kd, int bx, int by,
                                           int mode, int ohalf, char* smn) {
    uint32_t aB = smem_u32(smn);
    uint32_t bB = aB + 3 * HG_STAGE;
    int tid = threadIdx.x;
    int lane = tid & 31, wid = tid >> 5;
    int wm = wid >> 2, wn = wid & 3;
    int fr = lane >> 2, fc = lane & 3;

    // ldmatrix per-thread address components (bytes)
    int rA = (lane & 7) + ((lane >> 3) & 1) * 8;   // A: blocks rows0-7/rows8-15 x koff
    int cA = (lane >> 4) * 8;                      // halves
    uint32_t aOff = (uint32_t)((wm * 64 + rA) * 80 + cA * 2);
    int rB = (lane & 7) + (lane >> 4) * 8;         // B: blocks koff then rows+8
    int cB = ((lane >> 3) & 1) * 8;
    uint32_t bOff = (uint32_t)((wn * 32 + rB) * 80 + cB * 2);

    const __half* Arow = A + (size_t)(by * 128) * Kd;
    const __half* Brow = Wt + (size_t)(bx * 128) * Kd;

    float acc[4][4][4];
#pragma unroll
    for (int mi = 0; mi < 4; mi++)
#pragma unroll
        for (int ni = 0; ni < 4; ni++)
#pragma unroll
            for (int c = 0; c < 4; c++) acc[mi][ni][c] = 0.f;

    int nk = Kd / HBK;
    hgemm_issue(aB, bB, 0, Arow, Brow, 0, Kd); CP_COMMIT;
    hgemm_issue(aB, bB, 1, Arow, Brow, HBK, Kd); CP_COMMIT;

    for (int i = 0; i < nk; i++) {
        if (i + 1 < nk) { CP_WAIT1; } else { CP_WAIT0; }
        __syncthreads();
        if (i + 2 < nk) {
            hgemm_issue(aB, bB, (i + 2) % 3, Arow, Brow, (i + 2) * HBK, Kd);
            CP_COMMIT;
        }
        int s = i % 3;
        hgemm_compute(aB + s * HG_STAGE + aOff, bB + s * HG_STAGE + bOff, acc);
    }

#pragma unroll
    for (int mi = 0; mi < 4; mi++) {
#pragma unroll
        for (int ni = 0; ni < 4; ni++) {
            int row = by * 128 + wm * 64 + mi * 16 + fr;
            int col = bx * 128 + wn * 32 + ni * 8 + fc * 2;
            float2 r0 = make_float2(acc[mi][ni][0], acc[mi][ni][1]);
            float2 r1 = make_float2(acc[mi][ni][2], acc[mi][ni][3]);
            if (mode == 1) {
                float2 h0 = *(const float2*)(aux + (size_t)row * N + col);
                float2 h1 = *(const float2*)(aux + (size_t)(row + 8) * N + col);
                r0.x += h0.x; r0.y += h0.y;
                r1.x += h1.x; r1.y += h1.y;
            } else if (mode == 2) {
                float2 g0 = *(const float2*)(aux + (size_t)row * N + col);
                float2 g1 = *(const float2*)(aux + (size_t)(row + 8) * N + col);
                r0.x *= g0.x / (1.f + __expf(-g0.x));
                r0.y *= g0.y / (1.f + __expf(-g0.y));
                r1.x *= g1.x / (1.f + __expf(-g1.x));
                r1.y *= g1.y / (1.f + __expf(-g1.y));
            }
            if (ohalf) {
                __half* C = (__half*)Cv;
                *(__half2*)(C + (size_t)row * N + col) = __floats2half2_rn(r0.x, r0.y);
                *(__half2*)(C + (size_t)(row + 8) * N + col) = __floats2half2_rn(r1.x, r1.y);
            } else {
                float* C = (float*)Cv;
                *(float2*)(C + (size_t)row * N + col) = r0;
                *(float2*)(C + (size_t)(row + 8) * N + col) = r1;
            }
        }
    }
}

__global__ __launch_bounds__(256, 2) void hgemm_k(
    const __half* __restrict__ A, const __half* __restrict__ Wt,
    const float* __restrict__ aux, void* __restrict__ C,
    int N, int Kd, int mode, int ohalf) {
    extern __shared__ char smn[];
    hgemm_body(A, Wt, aux, C, N, Kd, blockIdx.x, blockIdx.y, mode, ohalf, smn);
}

__global__ __launch_bounds__(256, 2) void hgemm_qkv_k(
    const __half* __restrict__ A,
    const __half* __restrict__ Wtq, const __half* __restrict__ Wtk, const __half* __restrict__ Wtv,
    float* __restrict__ Cq, float* __restrict__ Ck, __half* __restrict__ Cv) {
    extern __shared__ char smn[];
    int bx = blockIdx.x;
    const __half* Wt; void* C; int N; int oh;
    if (bx < 8)       { Wt = Wtq; C = Cq; N = 1024; oh = 0; }
    else if (bx < 10) { Wt = Wtk; C = Ck; N = 256; bx -= 8; oh = 0; }
    else              { Wt = Wtv; C = Cv; N = 256; bx -= 10; oh = 1; }
    hgemm_body(A, Wt, (const float*)0, C, N, Dn, bx, blockIdx.y, 0, oh, smn);
}

// ============================================================
// Flash attention, fp16 MMA + ldmatrix fragments.
// ============================================================
#define QSH 72   // halves stride (144 B)
#define VTH 136  // halves stride (272 B)
#define PSH 136
#define ATT_SMEM ((128 * QSH + 128 * QSH + 64 * VTH + 128 * PSH) * 2)

__global__ __launch_bounds__(256, 2) void flashattn_k(
    const __half* __restrict__ q16, const __half* __restrict__ k16,
    const __half* __restrict__ vt, __half* __restrict__ out) {
    extern __shared__ __half smh[];
    __half* Qs = smh;
    __half* Ks = Qs + 128 * QSH;
    __half* Vs = Ks + 128 * QSH;
    __half* Ps = Vs + 64 * VTH;
    uint32_t qs_u = smem_u32(Qs), ks_u = smem_u32(Ks), vs_u = smem_u32(Vs);
    uint32_t ps_u = smem_u32(Ps);

    int tid = threadIdx.x;
    int lane = tid & 31, wid = tid >> 5;
    int fr = lane >> 2, fc = lane & 3;
    __half* Pw = Ps + wid * 16 * PSH;

    // ldmatrix address components (bytes)
    int rA = (lane & 7) + ((lane >> 3) & 1) * 8;
    int cA = (lane >> 4) * 8;
    int rB = (lane & 7) + (lane >> 4) * 8;
    int cB = ((lane >> 3) & 1) * 8;
    uint32_t qAddr = qs_u + (uint32_t)((wid * 16 + rA) * 144 + cA * 2);
    uint32_t kAddr = ks_u + (uint32_t)(rB * 144 + cB * 2);
    uint32_t pAddr = ps_u + (uint32_t)((wid * 16 + rA) * 272 + cA * 2);
    uint32_t vAddr = vs_u + (uint32_t)(rB * 272 + cB * 2);

    int bg = blockIdx.y;
    int b = bg >> 2, g = bg & 3;
    int t0 = (gridDim.x - 1 - blockIdx.x) * 32;
    int ntiles = (t0 >> 7) + 1;

    const __half* qbase = q16 + ((size_t)((size_t)b * Tn + t0) * Hn + g * Rn) * Kn;
    const __half* kbase = k16 + ((size_t)b * Tn * Gn + g) * Kn;
    const __half* vtbase = vt + (size_t)bg * Kn * Tn;

#pragma unroll
    for (int i = 0; i < 4; i++) {
        int idx = tid + (i << 8);
        int m = idx >> 3, ch = idx & 7;
        cpa16(qs_u + (uint32_t)(m * QSH * 2 + ch * 16),
              qbase + (size_t)(m >> 2) * (Hn * Kn) + (m & 3) * Kn + ch * 8);
    }
    CP_COMMIT;
#pragma unroll
    for (int i = 0; i < 4; i++) {
        int idx = tid + (i << 8);
        int j = idx >> 3, ch = idx & 7;
        cpa16(ks_u + (uint32_t)(j * QSH * 2 + ch * 16),
              kbase + (size_t)j * (Gn * Kn) + ch * 8);
    }
    CP_COMMIT;
#pragma unroll
    for (int i = 0; i < 4; i++) {
        int idx = tid + (i << 8);
        int d = idx >> 4, ch = idx & 15;
        cpa16(vs_u + (uint32_t)(d * VTH * 2 + ch * 16),
              vtbase + (size_t)d * Tn + 0 + ch * 8);
    }
    CP_COMMIT;
    CP_WAIT0;
    __syncthreads();

    float m_r[2], l_r[2], acco[8][4];
#pragma unroll
    for (int h = 0; h < 2; h++) { m_r[h] = -INFINITY; l_r[h] = 0.f; }
#pragma unroll
    for (int ni = 0; ni < 8; ni++)
#pragma unroll
        for (int c = 0; c < 4; c++) acco[ni][c] = 0.f;

    int r0 = wid * 16 + fr;

    for (int it = 0; it < ntiles; it++) {
        int s0 = it << 7;
        bool more = (it + 1 < ntiles);

        // ---- S = Q @ K^T ----
        float accs[16][4];
#pragma unroll
        for (int ni = 0; ni < 16; ni++)
#pragma unroll
            for (int c = 0; c < 4; c++) accs[ni][c] = 0.f;

#pragma unroll
        for (int k2 = 0; k2 < 2; k2++) {  // two k16 chunks over 64 halves: byte off k2*32? (64h = 4 chunks)
            ;
        }
#pragma unroll
        for (int k2 = 0; k2 < 4; k2++) {  // 4 k16 chunks over K=64: byte offset k2*32
            uint32_t af[4];
            LDSM_X4(af[0], af[1], af[2], af[3], qAddr + k2 * 32);
#pragma unroll
            for (int p = 0; p < 8; p++) {
                uint32_t b00, b01, b10, b11;
                LDSM_X4(b00, b01, b10, b11, kAddr + p * 16 * 144 + k2 * 32);
                MMA_F16(accs[2 * p], af[0], af[1], af[2], af[3], b00, b01);
                MMA_F16(accs[2 * p + 1], af[0], af[1], af[2], af[3], b10, b11);
            }
        }

#pragma unroll
        for (int ni = 0; ni < 16; ni++)
#pragma unroll
            for (int c = 0; c < 4; c++) accs[ni][c] *= 0.125f;
        if (it == ntiles - 1) {
#pragma unroll
            for (int ni = 0; ni < 16; ni++)
#pragma unroll
                for (int c = 0; c < 4; c++) {
                    int row = r0 + ((c >= 2) ? 8 : 0);
                    int tt = t0 + (row >> 2);
                    int ss = s0 + ni * 8 + fc * 2 + (c & 1);
                    if (ss > tt) accs[ni][c] = -1e30f;
                }
        }

        // ---- online softmax ----
#pragma unroll
        for (int h = 0; h < 2; h++) {
            float mx = -1e30f;
#pragma unroll
            for (int ni = 0; ni < 16; ni++) {
                mx = fmaxf(mx, accs[ni][2 * h]);
                mx = fmaxf(mx, accs[ni][2 * h + 1]);
            }
            mx = fmaxf(mx, __shfl_xor_sync(0xFFFFFFFFu, mx, 1));
            mx = fmaxf(mx, __shfl_xor_sync(0xFFFFFFFFu, mx, 2));
            float mnew = fmaxf(m_r[h], mx);
            float corr = __expf(m_r[h] - mnew);
            m_r[h] = mnew;
            float sum = 0.f;
#pragma unroll
            for (int ni = 0; ni < 16; ni++) {
                float p0 = __expf(accs[ni][2 * h] - mnew);
                float p1 = __expf(accs[ni][2 * h + 1] - mnew);
                accs[ni][2 * h] = p0;
                accs[ni][2 * h + 1] = p1;
                sum += p0 + p1;
            }
            sum += __shfl_xor_sync(0xFFFFFFFFu, sum, 1);
            sum += __shfl_xor_sync(0xFFFFFFFFu, sum, 2);
            l_r[h] = l_r[h] * corr + sum;
#pragma unroll
            for (int ni = 0; ni < 8; ni++) {
                acco[ni][2 * h] *= corr;
                acco[ni][2 * h + 1] *= corr;
            }
        }

        // ---- P -> warp-private smem (fp16) ----
#pragma unroll
        for (int ni = 0; ni < 16; ni++) {
            int cc = ni * 8 + fc * 2;
            *(__half2*)(Pw + fr * PSH + cc) = __floats2half2_rn(accs[ni][0], accs[ni][1]);
            *(__half2*)(Pw + (fr + 8) * PSH + cc) = __floats2half2_rn(accs[ni][2], accs[ni][3]);
        }

        __syncthreads();
        if (more) {
            int sn = s0 + 128;
#pragma unroll
            for (int i = 0; i < 4; i++) {
                int idx = tid + (i << 8);
                int j = idx >> 3, ch = idx & 7;
                cpa16(ks_u + (uint32_t)(j * QSH * 2 + ch * 16),
                      kbase + (size_t)(sn + j) * (Gn * Kn) + ch * 8);
            }
            CP_COMMIT;
            CP_WAIT1;
        } else {
            CP_WAIT0;
        }
        __syncthreads();

        // ---- O += P @ V ----
#pragma unroll
        for (int k2 = 0; k2 < 8; k2++) {  // 8 k16 chunks over 128 halves
            uint32_t af[4];
            LDSM_X4(af[0], af[1], af[2], af[3], pAddr + k2 * 32);
#pragma unroll
            for (int p = 0; p < 4; p++) {
                uint32_t b00, b01, b10, b11;
                LDSM_X4(b00, b01, b10, b11, vAddr + p * 16 * 272 + k2 * 32);
                MMA_F16(acco[2 * p], af[0], af[1], af[2], af[3], b00, b01);
                MMA_F16(acco[2 * p + 1], af[0], af[1], af[2], af[3], b10, b11);
            }
        }
        __syncthreads();

        if (more) {
            int sn = s0 + 128;
#pragma unroll
            for (int i = 0; i < 4; i++) {
                int idx = tid + (i << 8);
                int d = idx >> 4, ch = idx & 15;
                cpa16(vs_u + (uint32_t)(d * VTH * 2 + ch * 16),
                      vtbase + (size_t)d * Tn + sn + ch * 8);
            }
            CP_COMMIT;
            CP_WAIT1;
            __syncthreads();
        }
    }

    // ---- epilogue ----
#pragma unroll
    for (int h = 0; h < 2; h++) {
        float inv = 1.f / l_r[h];
        int row = r0 + 8 * h;
        int tt = t0 + (row >> 2);
        int hh = g * Rn + (row & 3);
        __half* op = out + ((size_t)((size_t)b * Tn + tt) * Hn + hh) * Kn;
#pragma unroll
        for (int ni = 0; ni < 8; ni++) {
            int col = ni * 8 + fc * 2;
            *(__half2*)(op + col) =
                __floats2half2_rn(acco[ni][2 * h] * inv, acco[ni][2 * h + 1] * inv);
        }
    }
}

// ---------------- launch ----------------
static void hgemm(const __half* A, const __half* Wt, const float* aux, void* C,
                  int M, int N, int Kd, int mode, int ohalf) {
    dim3 grid(N / 128, M / 128);
    hgemm_k<<<grid, 256, HG_SMEM>>>(A, Wt, aux, C, N, Kd, mode, ohalf);
}

extern "C" void kernel_launch(void* const* d_in, const int* in_sizes, int n_in,
                              void* d_out, int out_size) {
    const float* hidden = (const float*)d_in[0];
    const float* sinp   = (const float*)d_in[1];
    const float* cosp   = (const float*)d_in[2];
    /* d_in[3] = mask (exact causal tril; applied analytically) */
    const float* ln1    = (const float*)d_in[4];
    const float* ln2    = (const float*)d_in[5];
    const float* qn     = (const float*)d_in[6];
    const float* kn     = (const float*)d_in[7];
    const float* q_w    = (const float*)d_in[8];
    const float* k_w    = (const float*)d_in[9];
    const float* v_w    = (const float*)d_in[10];
    const float* o_w    = (const float*)d_in[11];
    const float* gate_w = (const float*)d_in[12];
    const float* up_w   = (const float*)d_in[13];
    const float* down_w = (const float*)d_in[14];
    float* out = (float*)d_out;

    cudaFuncSetAttribute(hgemm_k, cudaFuncAttributeMaxDynamicSharedMemorySize, HG_SMEM);
    cudaFuncSetAttribute(hgemm_qkv_k, cudaFuncAttributeMaxDynamicSharedMemorySize, HG_SMEM);
    cudaFuncSetAttribute(flashattn_k, cudaFuncAttributeMaxDynamicSharedMemorySize, ATT_SMEM);

    __half *x, *v16, *q16, *k16, *vt, *attn, *y, *ff;
    float *q, *k, *h2, *gate;
    __half *tq, *tk, *tv, *to, *tg, *tu, *td;
    cudaGetSymbolAddress((void**)&x, g_x);
    cudaGetSymbolAddress((void**)&q, g_q);
    cudaGetSymbolAddress((void**)&k, g_k);
    cudaGetSymbolAddress((void**)&v16, g_v16);
    cudaGetSymbolAddress((void**)&q16, g_q16);
    cudaGetSymbolAddress((void**)&k16, g_k16);
    cudaGetSymbolAddress((void**)&vt, g_vt);
    cudaGetSymbolAddress((void**)&attn, g_attn);
    cudaGetSymbolAddress((void**)&h2, g_h2);
    cudaGetSymbolAddress((void**)&y, g_y);
    cudaGetSymbolAddress((void**)&gate, g_gate);
    cudaGetSymbolAddress((void**)&ff, g_ff);
    cudaGetSymbolAddress((void**)&tq, g_wt_q);
    cudaGetSymbolAddress((void**)&tk, g_wt_k);
    cudaGetSymbolAddress((void**)&tv, g_wt_v);
    cudaGetSymbolAddress((void**)&to, g_wt_o);
    cudaGetSymbolAddress((void**)&tg, g_wt_gate);
    cudaGetSymbolAddress((void**)&tu, g_wt_up);
    cudaGetSymbolAddress((void**)&td, g_wt_down);

    const int M = Mrows;

    transpose_all_k<<<14848, 256>>>(q_w, k_w, v_w, o_w, gate_w, up_w, down_w,
                                    tq, tk, tv, to, tg, tu, td);

    rmsnorm_k<<<M, 256>>>(hidden, ln1, x);

    hgemm_qkv_k<<<dim3(12, M / 128), 256, HG_SMEM>>>(x, tq, tk, tv, q, k, v16);

    {
        int warps_q = Bn * Tn * Hn;
        norm_rope_k<<<(warps_q * 32) / 256, 256>>>(q, q16, qn, sinp, cosp, Hn);
        int warps_k = Bn * Tn * Gn;
        norm_rope_k<<<(warps_k * 32) / 256, 256>>>(k, k16, kn, sinp, cosp, Gn);
        vtrans_k<<<dim3(Tn / 32, Kn / 32, Bn * Gn), 256>>>(v16, vt);
    }

    flashattn_k<<<dim3(Tn / 32, Bn * Gn), 256, ATT_SMEM>>>(q16, k16, vt, attn);

    hgemm(attn, to, hidden, h2, M, Dn, Hn * Kn, 1, 0);

    rmsnorm_k<<<M, 256>>>(h2, ln2, y);

    hgemm(y, tg, (const float*)0, gate, M, Fn, Dn, 0, 0);
    hgemm(y, tu, gate, ff, M, Fn, Dn, 2, 1);

    hgemm(ff, td, h2, out, M, Dn, Fn, 1, 0);
}

// round 11
// speedup vs baseline: 2.0598x; 1.0167x over previous
#include <cuda_runtime.h>
#include <cuda_fp16.h>
#include <math.h>
#include <stdint.h>

#define Bn 2
#define Tn 2048
#define Dn 1024
#define Hn 16
#define Gn 4
#define Kn 64
#define Rn (Hn / Gn)
#define Fn 4096
#define EPSF 1e-6f
#define Mrows (Bn * Tn)

// ---------------- scratch ----------------
__device__ __half g_x[Mrows * Dn];
__device__ __half g_qp[Mrows * Hn * Kn];   // q proj fp16 (pre-norm/rope)
__device__ __half g_kp[Mrows * Gn * Kn];   // k proj fp16 (pre-norm/rope)
__device__ __half g_v16[Mrows * Gn * Kn];
__device__ __half g_q16[Mrows * Hn * Kn];
__device__ __half g_k16[Mrows * Gn * Kn];
__device__ __half g_vt[Bn * Gn * Kn * Tn];
__device__ __half g_attn[Mrows * Hn * Kn];
__device__ float  g_h2[Mrows * Dn];
__device__ __half g_y[Mrows * Dn];
__device__ __half g_gate16[Mrows * Fn];
__device__ __half g_ff[Mrows * Fn];
__device__ __half g_wt_q[1024 * 1024];
__device__ __half g_wt_k[256 * 1024];
__device__ __half g_wt_v[256 * 1024];
__device__ __half g_wt_o[1024 * 1024];
__device__ __half g_wt_gate[4096 * 1024];
__device__ __half g_wt_up[4096 * 1024];
__device__ __half g_wt_down[1024 * 4096];

// ---------------- helpers ----------------
__device__ __forceinline__ uint32_t smem_u32(const void* p) {
    return (uint32_t)__cvta_generic_to_shared(p);
}
__device__ __forceinline__ void cpa16(uint32_t dst, const void* src) {
    asm volatile("cp.async.cg.shared.global [%0], [%1], 16;" ::"r"(dst), "l"(src));
}
#define CP_COMMIT asm volatile("cp.async.commit_group;")
#define CP_WAIT0 asm volatile("cp.async.wait_group 0;")
#define CP_WAIT1 asm volatile("cp.async.wait_group 1;")
#define CP_WAIT2 asm volatile("cp.async.wait_group 2;")

#define MMA_F16(d, a0, a1, a2, a3, b0, b1)                                    \
    asm volatile(                                                             \
        "mma.sync.aligned.m16n8k16.row.col.f32.f16.f16.f32 "                  \
        "{%0,%1,%2,%3}, {%4,%5,%6,%7}, {%8,%9}, {%0,%1,%2,%3};"               \
        : "+f"(d[0]), "+f"(d[1]), "+f"(d[2]), "+f"(d[3])                      \
        : "r"(a0), "r"(a1), "r"(a2), "r"(a3), "r"(b0), "r"(b1))

#define LDSM_X4(r0, r1, r2, r3, addr)                                         \
    asm volatile("ldmatrix.sync.aligned.m8n8.x4.shared.b16 {%0,%1,%2,%3}, [%4];" \
                 : "=r"(r0), "=r"(r1), "=r"(r2), "=r"(r3) : "r"(addr))

// ---------------- fused weight transpose (+fp16 cvt): W[K][N] -> Wt[N][K] ----------------
__global__ void transpose_all_k(
    const float* __restrict__ q_w, const float* __restrict__ k_w,
    const float* __restrict__ v_w, const float* __restrict__ o_w,
    const float* __restrict__ gate_w, const float* __restrict__ up_w,
    const float* __restrict__ down_w,
    __half* __restrict__ tq, __half* __restrict__ tk, __half* __restrict__ tv,
    __half* __restrict__ to, __half* __restrict__ tg, __half* __restrict__ tu,
    __half* __restrict__ td) {
    __shared__ float t[32][33];
    int b = blockIdx.x;
    const float* W; __half* Wt; int K, N, base;
    if (b < 1024)       { W = q_w;    Wt = tq; K = 1024; N = 1024; base = 0; }
    else if (b < 1280)  { W = k_w;    Wt = tk; K = 1024; N = 256;  base = 1024; }
    else if (b < 1536)  { W = v_w;    Wt = tv; K = 1024; N = 256;  base = 1280; }
    else if (b < 2560)  { W = o_w;    Wt = to; K = 1024; N = 1024; base = 1536; }
    else if (b < 6656)  { W = gate_w; Wt = tg; K = 1024; N = 4096; base = 2560; }
    else if (b < 10752) { W = up_w;   Wt = tu; K = 1024; N = 4096; base = 6656; }
    else                { W = down_w; Wt = td; K = 4096; N = 1024; base = 10752; }
    int local = b - base;
    int nb = N >> 5;
    int bx = local % nb, by = local / nb;
    int x = threadIdx.x & 31, y = threadIdx.x >> 5;
#pragma unroll
    for (int j = 0; j < 4; j++)
        t[y + j * 8][x] = W[(size_t)(by * 32 + y + j * 8) * N + bx * 32 + x];
    __syncthreads();
#pragma unroll
    for (int j = 0; j < 4; j++)
        Wt[(size_t)(bx * 32 + y + j * 8) * K + by * 32 + x] = __float2half(t[x][y + j * 8]);
}

// ---------------- V transpose ----------------
__global__ void vtrans_k(const __half* __restrict__ v16, __half* __restrict__ vt) {
    __shared__ __half t[32][33];
    int bg = blockIdx.z;
    int b = bg >> 2, g = bg & 3;
    int t0 = blockIdx.x * 32;
    int d0 = blockIdx.y * 32;
    int x = threadIdx.x & 31, y = threadIdx.x >> 5;
#pragma unroll
    for (int j = 0; j < 4; j++) {
        int tt = t0 + y + j * 8;
        t[y + j * 8][x] = v16[((size_t)((size_t)b * Tn + tt) * Gn + g) * Kn + d0 + x];
    }
    __syncthreads();
#pragma unroll
    for (int j = 0; j < 4; j++) {
        int dd = d0 + y + j * 8;
        vt[((size_t)bg * Kn + dd) * Tn + t0 + x] = t[x][y + j * 8];
    }
}

// ---------------- RMSNorm (fp32 in, fp16 out), float4 loads ----------------
__global__ void rmsnorm_k(const float* __restrict__ in, const float* __restrict__ sc,
                          __half* __restrict__ out) {
    int row = blockIdx.x;
    const float4* x4 = (const float4*)(in + (size_t)row * Dn);
    float4 v = x4[threadIdx.x];
    float ss = v.x * v.x + v.y * v.y + v.z * v.z + v.w * v.w;
    for (int o = 16; o; o >>= 1) ss += __shfl_xor_sync(0xFFFFFFFFu, ss, o);
    __shared__ float sm[8];
    int w = threadIdx.x >> 5;
    if ((threadIdx.x & 31) == 0) sm[w] = ss;
    __syncthreads();
    if (threadIdx.x == 0) {
        float tot = 0.f;
        for (int i = 0; i < 8; i++) tot += sm[i];
        sm[0] = tot;
    }
    __syncthreads();
    float inv = rsqrtf(sm[0] / (float)Dn + EPSF);
    float4 s4 = ((const float4*)sc)[threadIdx.x];
    __half2* o2 = (__half2*)(out + (size_t)row * Dn) + threadIdx.x * 2;
    o2[0] = __floats2half2_rn(v.x * inv * s4.x, v.y * inv * s4.y);
    o2[1] = __floats2half2_rn(v.z * inv * s4.z, v.w * inv * s4.w);
}

// ---------------- per-head RMSNorm + RoPE (fp16 in, fp16 out) ----------------
__global__ void norm_rope_k(const __half* __restrict__ qk, __half* __restrict__ out16,
                            const float* __restrict__ nscale,
                            const float* __restrict__ sinp, const float* __restrict__ cosp,
                            int nheads) {
    int gw = (blockIdx.x * blockDim.x + threadIdx.x) >> 5;
    int lane = threadIdx.x & 31;
    int total = Bn * Tn * nheads;
    if (gw >= total) return;
    int bt = gw / nheads;
    const __half* p = qk + (size_t)gw * Kn;
    float x1 = __half2float(p[lane]);
    float x2 = __half2float(p[lane + 32]);
    float ss = x1 * x1 + x2 * x2;
    for (int o = 16; o; o >>= 1) ss += __shfl_xor_sync(0xFFFFFFFFu, ss, o);
    float inv = rsqrtf(ss / (float)Kn + EPSF);
    x1 = x1 * inv * nscale[lane];
    x2 = x2 * inv * nscale[lane + 32];
    float s = sinp[bt * (Kn / 2) + lane];
    float c = cosp[bt * (Kn / 2) + lane];
    __half* o = out16 + (size_t)gw * Kn;
    o[lane]      = __float2half(x1 * c - x2 * s);
    o[lane + 32] = __float2half(x2 * c + x1 * s);
}

// ============================================================
// FP16 GEMM, ldmatrix fragments, single-sync 4-stage cp.async.
// 128x128x32 tile, 8 warps (2x4), warp tile 64x32.
// Modes: 0 plain, 1 +aux(fp32), 2 silu(aux fp16)*acc.
// ============================================================
#define HAS 40                 // halves stride (80 B)
#define HG_STAGE 10240
#define HSTG 4
#define HG_SMEM (2 * HSTG * HG_STAGE)

__device__ __forceinline__ void hgemm_issue(uint32_t aB, uint32_t bB, int s,
                                            const __half* Arow, const __half* Brow,
                                            int k0, int Kd) {
    int tid = threadIdx.x;
#pragma unroll
    for (int j = 0; j < 2; j++) {
        int idx = tid + j * 256;
        int row = idx >> 2, ch = idx & 3;
        uint32_t dst = (uint32_t)(row * (HAS * 2) + ch * 16);
        cpa16(aB + s * HG_STAGE + dst, Arow + (size_t)row * Kd + k0 + ch * 8);
        cpa16(bB + s * HG_STAGE + dst, Brow + (size_t)row * Kd + k0 + ch * 8);
    }
}

__device__ __forceinline__ void hgemm_compute(uint32_t aAddr, uint32_t bAddr,
                                              float acc[4][4][4]) {
#pragma unroll
    for (int k2 = 0; k2 < 2; k2++) {
        uint32_t af[4][4], bf[4][2];
#pragma unroll
        for (int mi = 0; mi < 4; mi++)
            LDSM_X4(af[mi][0], af[mi][1], af[mi][2], af[mi][3],
                    aAddr + mi * 16 * 80 + k2 * 32);
#pragma unroll
        for (int p = 0; p < 2; p++)
            LDSM_X4(bf[2 * p][0], bf[2 * p][1], bf[2 * p + 1][0], bf[2 * p + 1][1],
                    bAddr + p * 16 * 80 + k2 * 32);
#pragma unroll
        for (int mi = 0; mi < 4; mi++)
#pragma unroll
            for (int ni = 0; ni < 4; ni++)
                MMA_F16(acc[mi][ni], af[mi][0], af[mi][1], af[mi][2], af[mi][3],
                        bf[ni][0], bf[ni][1]);
    }
}

__device__ __forceinline__ void hgemm_body(const __half* A, const __half* Wt,
                                           const void* aux, void* Cv,
                                           int N, int Kd, int bx, int by,
                                           int mode, int ohalf, char* smn) {
    uint32_t aB = smem_u32(smn);
    uint32_t bB = aB + HSTG * HG_STAGE;
    int tid = threadIdx.x;
    int lane = tid & 31, wid = tid >> 5;
    int wm = wid >> 2, wn = wid & 3;
    int fr = lane >> 2, fc = lane & 3;

    int rA = (lane & 7) + ((lane >> 3) & 1) * 8;
    int cA = (lane >> 4) * 8;
    uint32_t aOff = (uint32_t)((wm * 64 + rA) * 80 + cA * 2);
    int rB = (lane & 7) + (lane >> 4) * 8;
    int cB = ((lane >> 3) & 1) * 8;
    uint32_t bOff = (uint32_t)((wn * 32 + rB) * 80 + cB * 2);

    const __half* Arow = A + (size_t)(by * 128) * Kd;
    const __half* Brow = Wt + (size_t)(bx * 128) * Kd;

    float acc[4][4][4];
#pragma unroll
    for (int mi = 0; mi < 4; mi++)
#pragma unroll
        for (int ni = 0; ni < 4; ni++)
#pragma unroll
            for (int c = 0; c < 4; c++) acc[mi][ni][c] = 0.f;

    int nk = Kd / 32;
    hgemm_issue(aB, bB, 0, Arow, Brow, 0, Kd); CP_COMMIT;
    hgemm_issue(aB, bB, 1, Arow, Brow, 32, Kd); CP_COMMIT;
    hgemm_issue(aB, bB, 2, Arow, Brow, 64, Kd); CP_COMMIT;

    for (int i = 0; i < nk; i++) {
        if (i + 3 <= nk) { CP_WAIT2; }       // groups i..i+2 outstanding
        else if (i + 2 == nk) { CP_WAIT1; }
        else { CP_WAIT0; }
        __syncthreads();
        if (i + 3 < nk) {
            hgemm_issue(aB, bB, (i + 3) % HSTG, Arow, Brow, (i + 3) * 32, Kd);
            CP_COMMIT;
        }
        int s = i % HSTG;
        hgemm_compute(aB + s * HG_STAGE + aOff, bB + s * HG_STAGE + bOff, acc);
    }

#pragma unroll
    for (int mi = 0; mi < 4; mi++) {
#pragma unroll
        for (int ni = 0; ni < 4; ni++) {
            int row = by * 128 + wm * 64 + mi * 16 + fr;
            int col = bx * 128 + wn * 32 + ni * 8 + fc * 2;
            float2 r0 = make_float2(acc[mi][ni][0], acc[mi][ni][1]);
            float2 r1 = make_float2(acc[mi][ni][2], acc[mi][ni][3]);
            if (mode == 1) {
                const float* ap = (const float*)aux;
                float2 h0 = *(const float2*)(ap + (size_t)row * N + col);
                float2 h1 = *(const float2*)(ap + (size_t)(row + 8) * N + col);
                r0.x += h0.x; r0.y += h0.y;
                r1.x += h1.x; r1.y += h1.y;
            } else if (mode == 2) {
                const __half* gp = (const __half*)aux;
                __half2 g0h = *(const __half2*)(gp + (size_t)row * N + col);
                __half2 g1h = *(const __half2*)(gp + (size_t)(row + 8) * N + col);
                float g0x = __half2float(g0h.x), g0y = __half2float(g0h.y);
                float g1x = __half2float(g1h.x), g1y = __half2float(g1h.y);
                r0.x *= g0x / (1.f + __expf(-g0x));
                r0.y *= g0y / (1.f + __expf(-g0y));
                r1.x *= g1x / (1.f + __expf(-g1x));
                r1.y *= g1y / (1.f + __expf(-g1y));
            }
            if (ohalf) {
                __half* C = (__half*)Cv;
                *(__half2*)(C + (size_t)row * N + col) = __floats2half2_rn(r0.x, r0.y);
                *(__half2*)(C + (size_t)(row + 8) * N + col) = __floats2half2_rn(r1.x, r1.y);
            } else {
                float* C = (float*)Cv;
                *(float2*)(C + (size_t)row * N + col) = r0;
                *(float2*)(C + (size_t)(row + 8) * N + col) = r1;
            }
        }
    }
}

__global__ __launch_bounds__(256, 2) void hgemm_k(
    const __half* __restrict__ A, const __half* __restrict__ Wt,
    const void* __restrict__ aux, void* __restrict__ C,
    int N, int Kd, int mode, int ohalf) {
    extern __shared__ char smn[];
    hgemm_body(A, Wt, aux, C, N, Kd, blockIdx.x, blockIdx.y, mode, ohalf, smn);
}

// fused q/k/v: all fp16 out
__global__ __launch_bounds__(256, 2) void hgemm_qkv_k(
    const __half* __restrict__ A,
    const __half* __restrict__ Wtq, const __half* __restrict__ Wtk, const __half* __restrict__ Wtv,
    __half* __restrict__ Cq, __half* __restrict__ Ck, __half* __restrict__ Cv) {
    extern __shared__ char smn[];
    int bx = blockIdx.x;
    const __half* Wt; __half* C; int N;
    if (bx < 8)       { Wt = Wtq; C = Cq; N = 1024; }
    else if (bx < 10) { Wt = Wtk; C = Ck; N = 256; bx -= 8; }
    else              { Wt = Wtv; C = Cv; N = 256; bx -= 10; }
    hgemm_body(A, Wt, (const void*)0, C, N, Dn, bx, blockIdx.y, 0, 1, smn);
}

// ============================================================
// Flash attention, fp16 MMA + ldmatrix fragments.
// ============================================================
#define QSH 72
#define VTH 136
#define PSH 136
#define ATT_SMEM ((128 * QSH + 128 * QSH + 64 * VTH + 128 * PSH) * 2)

__global__ __launch_bounds__(256, 2) void flashattn_k(
    const __half* __restrict__ q16, const __half* __restrict__ k16,
    const __half* __restrict__ vt, __half* __restrict__ out) {
    extern __shared__ __half smh[];
    __half* Qs = smh;
    __half* Ks = Qs + 128 * QSH;
    __half* Vs = Ks + 128 * QSH;
    __half* Ps = Vs + 64 * VTH;
    uint32_t qs_u = smem_u32(Qs), ks_u = smem_u32(Ks), vs_u = smem_u32(Vs);
    uint32_t ps_u = smem_u32(Ps);

    int tid = threadIdx.x;
    int lane = tid & 31, wid = tid >> 5;
    int fr = lane >> 2, fc = lane & 3;
    __half* Pw = Ps + wid * 16 * PSH;

    int rA = (lane & 7) + ((lane >> 3) & 1) * 8;
    int cA = (lane >> 4) * 8;
    int rB = (lane & 7) + (lane >> 4) * 8;
    int cB = ((lane >> 3) & 1) * 8;
    uint32_t qAddr = qs_u + (uint32_t)((wid * 16 + rA) * 144 + cA * 2);
    uint32_t kAddr = ks_u + (uint32_t)(rB * 144 + cB * 2);
    uint32_t pAddr = ps_u + (uint32_t)((wid * 16 + rA) * 272 + cA * 2);
    uint32_t vAddr = vs_u + (uint32_t)(rB * 272 + cB * 2);

    int bg = blockIdx.y;
    int b = bg >> 2, g = bg & 3;
    int t0 = (gridDim.x - 1 - blockIdx.x) * 32;
    int ntiles = (t0 >> 7) + 1;

    const __half* qbase = q16 + ((size_t)((size_t)b * Tn + t0) * Hn + g * Rn) * Kn;
    const __half* kbase = k16 + ((size_t)b * Tn * Gn + g) * Kn;
    const __half* vtbase = vt + (size_t)bg * Kn * Tn;

#pragma unroll
    for (int i = 0; i < 4; i++) {
        int idx = tid + (i << 8);
        int m = idx >> 3, ch = idx & 7;
        cpa16(qs_u + (uint32_t)(m * QSH * 2 + ch * 16),
              qbase + (size_t)(m >> 2) * (Hn * Kn) + (m & 3) * Kn + ch * 8);
    }
    CP_COMMIT;
#pragma unroll
    for (int i = 0; i < 4; i++) {
        int idx = tid + (i << 8);
        int j = idx >> 3, ch = idx & 7;
        cpa16(ks_u + (uint32_t)(j * QSH * 2 + ch * 16),
              kbase + (size_t)j * (Gn * Kn) + ch * 8);
    }
    CP_COMMIT;
#pragma unroll
    for (int i = 0; i < 4; i++) {
        int idx = tid + (i << 8);
        int d = idx >> 4, ch = idx & 15;
        cpa16(vs_u + (uint32_t)(d * VTH * 2 + ch * 16),
              vtbase + (size_t)d * Tn + 0 + ch * 8);
    }
    CP_COMMIT;
    CP_WAIT0;
    __syncthreads();

    float m_r[2], l_r[2], acco[8][4];
#pragma unroll
    for (int h = 0; h < 2; h++) { m_r[h] = -INFINITY; l_r[h] = 0.f; }
#pragma unroll
    for (int ni = 0; ni < 8; ni++)
#pragma unroll
        for (int c = 0; c < 4; c++) acco[ni][c] = 0.f;

    int r0 = wid * 16 + fr;

    for (int it = 0; it < ntiles; it++) {
        int s0 = it << 7;
        bool more = (it + 1 < ntiles);

        float accs[16][4];
#pragma unroll
        for (int ni = 0; ni < 16; ni++)
#pragma unroll
            for (int c = 0; c < 4; c++) accs[ni][c] = 0.f;

#pragma unroll
        for (int k2 = 0; k2 < 4; k2++) {
            uint32_t af[4];
            LDSM_X4(af[0], af[1], af[2], af[3], qAddr + k2 * 32);
#pragma unroll
            for (int p = 0; p < 8; p++) {
                uint32_t b00, b01, b10, b11;
                LDSM_X4(b00, b01, b10, b11, kAddr + p * 16 * 144 + k2 * 32);
                MMA_F16(accs[2 * p], af[0], af[1], af[2], af[3], b00, b01);
                MMA_F16(accs[2 * p + 1], af[0], af[1], af[2], af[3], b10, b11);
            }
        }

#pragma unroll
        for (int ni = 0; ni < 16; ni++)
#pragma unroll
            for (int c = 0; c < 4; c++) accs[ni][c] *= 0.125f;
        if (it == ntiles - 1) {
#pragma unroll
            for (int ni = 0; ni < 16; ni++)
#pragma unroll
                for (int c = 0; c < 4; c++) {
                    int row = r0 + ((c >= 2) ? 8 : 0);
                    int tt = t0 + (row >> 2);
                    int ss = s0 + ni * 8 + fc * 2 + (c & 1);
                    if (ss > tt) accs[ni][c] = -1e30f;
                }
        }

#pragma unroll
        for (int h = 0; h < 2; h++) {
            float mx = -1e30f;
#pragma unroll
            for (int ni = 0; ni < 16; ni++) {
                mx = fmaxf(mx, accs[ni][2 * h]);
                mx = fmaxf(mx, accs[ni][2 * h + 1]);
            }
            mx = fmaxf(mx, __shfl_xor_sync(0xFFFFFFFFu, mx, 1));
            mx = fmaxf(mx, __shfl_xor_sync(0xFFFFFFFFu, mx, 2));
            float mnew = fmaxf(m_r[h], mx);
            float corr = __expf(m_r[h] - mnew);
            m_r[h] = mnew;
            float sum = 0.f;
#pragma unroll
            for (int ni = 0; ni < 16; ni++) {
                float p0 = __expf(accs[ni][2 * h] - mnew);
                float p1 = __expf(accs[ni][2 * h + 1] - mnew);
                accs[ni][2 * h] = p0;
                accs[ni][2 * h + 1] = p1;
                sum += p0 + p1;
            }
            sum += __shfl_xor_sync(0xFFFFFFFFu, sum, 1);
            sum += __shfl_xor_sync(0xFFFFFFFFu, sum, 2);
            l_r[h] = l_r[h] * corr + sum;
#pragma unroll
            for (int ni = 0; ni < 8; ni++) {
                acco[ni][2 * h] *= corr;
                acco[ni][2 * h + 1] *= corr;
            }
        }

#pragma unroll
        for (int ni = 0; ni < 16; ni++) {
            int cc = ni * 8 + fc * 2;
            *(__half2*)(Pw + fr * PSH + cc) = __floats2half2_rn(accs[ni][0], accs[ni][1]);
            *(__half2*)(Pw + (fr + 8) * PSH + cc) = __floats2half2_rn(accs[ni][2], accs[ni][3]);
        }

        __syncthreads();
        if (more) {
            int sn = s0 + 128;
#pragma unroll
            for (int i = 0; i < 4; i++) {
                int idx = tid + (i << 8);
                int j = idx >> 3, ch = idx & 7;
                cpa16(ks_u + (uint32_t)(j * QSH * 2 + ch * 16),
                      kbase + (size_t)(sn + j) * (Gn * Kn) + ch * 8);
            }
            CP_COMMIT;
            CP_WAIT1;
        } else {
            CP_WAIT0;
        }
        __syncthreads();

#pragma unroll
        for (int k2 = 0; k2 < 8; k2++) {
            uint32_t af[4];
            LDSM_X4(af[0], af[1], af[2], af[3], pAddr + k2 * 32);
#pragma unroll
            for (int p = 0; p < 4; p++) {
                uint32_t b00, b01, b10, b11;
                LDSM_X4(b00, b01, b10, b11, vAddr + p * 16 * 272 + k2 * 32);
                MMA_F16(acco[2 * p], af[0], af[1], af[2], af[3], b00, b01);
                MMA_F16(acco[2 * p + 1], af[0], af[1], af[2], af[3], b10, b11);
            }
        }
        __syncthreads();

        if (more) {
            int sn = s0 + 128;
#pragma unroll
            for (int i = 0; i < 4; i++) {
                int idx = tid + (i << 8);
                int d = idx >> 4, ch = idx & 15;
                cpa16(vs_u + (uint32_t)(d * VTH * 2 + ch * 16),
                      vtbase + (size_t)d * Tn + sn + ch * 8);
            }
            CP_COMMIT;
            CP_WAIT1;
            __syncthreads();
        }
    }

#pragma unroll
    for (int h = 0; h < 2; h++) {
        float inv = 1.f / l_r[h];
        int row = r0 + 8 * h;
        int tt = t0 + (row >> 2);
        int hh = g * Rn + (row & 3);
        __half* op = out + ((size_t)((size_t)b * Tn + tt) * Hn + hh) * Kn;
#pragma unroll
        for (int ni = 0; ni < 8; ni++) {
            int col = ni * 8 + fc * 2;
            *(__half2*)(op + col) =
                __floats2half2_rn(acco[ni][2 * h] * inv, acco[ni][2 * h + 1] * inv);
        }
    }
}

// ---------------- launch ----------------
static void hgemm(const __half* A, const __half* Wt, const void* aux, void* C,
                  int M, int N, int Kd, int mode, int ohalf) {
    dim3 grid(N / 128, M / 128);
    hgemm_k<<<grid, 256, HG_SMEM>>>(A, Wt, aux, C, N, Kd, mode, ohalf);
}

extern "C" void kernel_launch(void* const* d_in, const int* in_sizes, int n_in,
                              void* d_out, int out_size) {
    const float* hidden = (const float*)d_in[0];
    const float* sinp   = (const float*)d_in[1];
    const float* cosp   = (const float*)d_in[2];
    /* d_in[3] = mask (exact causal tril; applied analytically) */
    const float* ln1    = (const float*)d_in[4];
    const float* ln2    = (const float*)d_in[5];
    const float* qn     = (const float*)d_in[6];
    const float* kn     = (const float*)d_in[7];
    const float* q_w    = (const float*)d_in[8];
    const float* k_w    = (const float*)d_in[9];
    const float* v_w    = (const float*)d_in[10];
    const float* o_w    = (const float*)d_in[11];
    const float* gate_w = (const float*)d_in[12];
    const float* up_w   = (const float*)d_in[13];
    const float* down_w = (const float*)d_in[14];
    float* out = (float*)d_out;

    cudaFuncSetAttribute(hgemm_k, cudaFuncAttributeMaxDynamicSharedMemorySize, HG_SMEM);
    cudaFuncSetAttribute(hgemm_qkv_k, cudaFuncAttributeMaxDynamicSharedMemorySize, HG_SMEM);
    cudaFuncSetAttribute(flashattn_k, cudaFuncAttributeMaxDynamicSharedMemorySize, ATT_SMEM);

    __half *x, *qp, *kp, *v16, *q16, *k16, *vt, *attn, *y, *gate16, *ff;
    float *h2;
    __half *tq, *tk, *tv, *to, *tg, *tu, *td;
    cudaGetSymbolAddress((void**)&x, g_x);
    cudaGetSymbolAddress((void**)&qp, g_qp);
    cudaGetSymbolAddress((void**)&kp, g_kp);
    cudaGetSymbolAddress((void**)&v16, g_v16);
    cudaGetSymbolAddress((void**)&q16, g_q16);
    cudaGetSymbolAddress((void**)&k16, g_k16);
    cudaGetSymbolAddress((void**)&vt, g_vt);
    cudaGetSymbolAddress((void**)&attn, g_attn);
    cudaGetSymbolAddress((void**)&h2, g_h2);
    cudaGetSymbolAddress((void**)&y, g_y);
    cudaGetSymbolAddress((void**)&gate16, g_gate16);
    cudaGetSymbolAddress((void**)&ff, g_ff);
    cudaGetSymbolAddress((void**)&tq, g_wt_q);
    cudaGetSymbolAddress((void**)&tk, g_wt_k);
    cudaGetSymbolAddress((void**)&tv, g_wt_v);
    cudaGetSymbolAddress((void**)&to, g_wt_o);
    cudaGetSymbolAddress((void**)&tg, g_wt_gate);
    cudaGetSymbolAddress((void**)&tu, g_wt_up);
    cudaGetSymbolAddress((void**)&td, g_wt_down);

    const int M = Mrows;

    transpose_all_k<<<14848, 256>>>(q_w, k_w, v_w, o_w, gate_w, up_w, down_w,
                                    tq, tk, tv, to, tg, tu, td);

    rmsnorm_k<<<M, 256>>>(hidden, ln1, x);

    hgemm_qkv_k<<<dim3(12, M / 128), 256, HG_SMEM>>>(x, tq, tk, tv, qp, kp, v16);

    {
        int warps_q = Bn * Tn * Hn;
        norm_rope_k<<<(warps_q * 32) / 256, 256>>>(qp, q16, qn, sinp, cosp, Hn);
        int warps_k = Bn * Tn * Gn;
        norm_rope_k<<<(warps_k * 32) / 256, 256>>>(kp, k16, kn, sinp, cosp, Gn);
        vtrans_k<<<dim3(Tn / 32, Kn / 32, Bn * Gn), 256>>>(v16, vt);
    }

    flashattn_k<<<dim3(Tn / 32, Bn * Gn), 256, ATT_SMEM>>>(q16, k16, vt, attn);

    hgemm(attn, to, hidden, h2, M, Dn, Hn * Kn, 1, 0);

    rmsnorm_k<<<M, 256>>>(h2, ln2, y);

    hgemm(y, tg, (const void*)0, gate16, M, Fn, Dn, 0, 1);
    hgemm(y, tu, gate16, ff, M, Fn, Dn, 2, 1);

    hgemm(ff, td, h2, out, M, Dn, Fn, 1, 0);
}

// round 12
// speedup vs baseline: 2.0927x; 1.0160x over previous
#include <cuda_runtime.h>
#include <cuda_fp16.h>
#include <math.h>
#include <stdint.h>

#define Bn 2
#define Tn 2048
#define Dn 1024
#define Hn 16
#define Gn 4
#define Kn 64
#define Rn (Hn / Gn)
#define Fn 4096
#define EPSF 1e-6f
#define Mrows (Bn * Tn)

// ---------------- scratch ----------------
__device__ __half g_x[Mrows * Dn];
__device__ __half g_qp[Mrows * Hn * Kn];
__device__ __half g_kp[Mrows * Gn * Kn];
__device__ __half g_v16[Mrows * Gn * Kn];
__device__ __half g_q16[Mrows * Hn * Kn];
__device__ __half g_k16[Mrows * Gn * Kn];
__device__ __half g_vt[Bn * Gn * Kn * Tn];
__device__ __half g_attn[Mrows * Hn * Kn];
__device__ float  g_h2[Mrows * Dn];
__device__ __half g_y[Mrows * Dn];
__device__ __half g_gate16[Mrows * Fn];
__device__ __half g_ff[Mrows * Fn];
__device__ __half g_wt_q[1024 * 1024];
__device__ __half g_wt_k[256 * 1024];
__device__ __half g_wt_v[256 * 1024];
__device__ __half g_wt_o[1024 * 1024];
__device__ __half g_wt_gate[4096 * 1024];
__device__ __half g_wt_up[4096 * 1024];
__device__ __half g_wt_down[1024 * 4096];

// ---------------- helpers ----------------
__device__ __forceinline__ uint32_t smem_u32(const void* p) {
    return (uint32_t)__cvta_generic_to_shared(p);
}
__device__ __forceinline__ void cpa16(uint32_t dst, const void* src) {
    asm volatile("cp.async.cg.shared.global [%0], [%1], 16;" ::"r"(dst), "l"(src));
}
#define CP_COMMIT asm volatile("cp.async.commit_group;")
#define CP_WAIT0 asm volatile("cp.async.wait_group 0;")
#define CP_WAIT1 asm volatile("cp.async.wait_group 1;")
#define CP_WAIT2 asm volatile("cp.async.wait_group 2;")

#define MMA_F16(d, a0, a1, a2, a3, b0, b1)                                    \
    asm volatile(                                                             \
        "mma.sync.aligned.m16n8k16.row.col.f32.f16.f16.f32 "                  \
        "{%0,%1,%2,%3}, {%4,%5,%6,%7}, {%8,%9}, {%0,%1,%2,%3};"               \
        : "+f"(d[0]), "+f"(d[1]), "+f"(d[2]), "+f"(d[3])                      \
        : "r"(a0), "r"(a1), "r"(a2), "r"(a3), "r"(b0), "r"(b1))

#define LDSM_X4(r0, r1, r2, r3, addr)                                         \
    asm volatile("ldmatrix.sync.aligned.m8n8.x4.shared.b16 {%0,%1,%2,%3}, [%4];" \
                 : "=r"(r0), "=r"(r1), "=r"(r2), "=r"(r3) : "r"(addr))

// ---------------- fused weight transpose, 64x64 tiles, coalesced both sides ----------------
// W[K][N] fp32 -> Wt[N][K] fp16
__global__ void transpose_all_k(
    const float* __restrict__ q_w, const float* __restrict__ k_w,
    const float* __restrict__ v_w, const float* __restrict__ o_w,
    const float* __restrict__ gate_w, const float* __restrict__ up_w,
    const float* __restrict__ down_w,
    __half* __restrict__ tq, __half* __restrict__ tk, __half* __restrict__ tv,
    __half* __restrict__ to, __half* __restrict__ tg, __half* __restrict__ tu,
    __half* __restrict__ td) {
    __shared__ float t[64][65];
    int b = blockIdx.x;
    const float* W; __half* Wt; int K, N, base;
    if (b < 256)        { W = q_w;    Wt = tq; K = 1024; N = 1024; base = 0; }
    else if (b < 320)   { W = k_w;    Wt = tk; K = 1024; N = 256;  base = 256; }
    else if (b < 384)   { W = v_w;    Wt = tv; K = 1024; N = 256;  base = 320; }
    else if (b < 640)   { W = o_w;    Wt = to; K = 1024; N = 1024; base = 384; }
    else if (b < 1664)  { W = gate_w; Wt = tg; K = 1024; N = 4096; base = 640; }
    else if (b < 2688)  { W = up_w;   Wt = tu; K = 1024; N = 4096; base = 1664; }
    else                { W = down_w; Wt = td; K = 4096; N = 1024; base = 2688; }
    int local = b - base;
    int nb = N >> 6;
    int bx = local % nb, by = local / nb;  // bx: n-tile, by: k-tile
    // read: 4 k-rows per pass, 64 n per row (256 B coalesced)
    {
        int x = threadIdx.x & 63, y = threadIdx.x >> 6;
#pragma unroll
        for (int j = 0; j < 16; j++)
            t[y + j * 4][x] = W[(size_t)(by * 64 + y + j * 4) * N + bx * 64 + x];
    }
    __syncthreads();
    // write: rows of 64 halves (128 B coalesced) via half2
    {
        int x = threadIdx.x & 31, y = threadIdx.x >> 5;  // x: k half2, y: n
#pragma unroll
        for (int j = 0; j < 8; j++) {
            int n = y + j * 8;
            __half2 v = __floats2half2_rn(t[2 * x][n], t[2 * x + 1][n]);
            *(__half2*)(Wt + (size_t)(bx * 64 + n) * K + by * 64 + 2 * x) = v;
        }
    }
}

// ---------------- V transpose ----------------
__global__ void vtrans_k(const __half* __restrict__ v16, __half* __restrict__ vt) {
    __shared__ __half t[32][33];
    int bg = blockIdx.z;
    int b = bg >> 2, g = bg & 3;
    int t0 = blockIdx.x * 32;
    int d0 = blockIdx.y * 32;
    int x = threadIdx.x & 31, y = threadIdx.x >> 5;
#pragma unroll
    for (int j = 0; j < 4; j++) {
        int tt = t0 + y + j * 8;
        t[y + j * 8][x] = v16[((size_t)((size_t)b * Tn + tt) * Gn + g) * Kn + d0 + x];
    }
    __syncthreads();
#pragma unroll
    for (int j = 0; j < 4; j++) {
        int dd = d0 + y + j * 8;
        vt[((size_t)bg * Kn + dd) * Tn + t0 + x] = t[x][y + j * 8];
    }
}

// ---------------- RMSNorm (fp32 in, fp16 out) ----------------
__global__ void rmsnorm_k(const float* __restrict__ in, const float* __restrict__ sc,
                          __half* __restrict__ out) {
    int row = blockIdx.x;
    const float4* x4 = (const float4*)(in + (size_t)row * Dn);
    float4 v = x4[threadIdx.x];
    float ss = v.x * v.x + v.y * v.y + v.z * v.z + v.w * v.w;
    for (int o = 16; o; o >>= 1) ss += __shfl_xor_sync(0xFFFFFFFFu, ss, o);
    __shared__ float sm[8];
    int w = threadIdx.x >> 5;
    if ((threadIdx.x & 31) == 0) sm[w] = ss;
    __syncthreads();
    if (threadIdx.x == 0) {
        float tot = 0.f;
        for (int i = 0; i < 8; i++) tot += sm[i];
        sm[0] = tot;
    }
    __syncthreads();
    float inv = rsqrtf(sm[0] / (float)Dn + EPSF);
    float4 s4 = ((const float4*)sc)[threadIdx.x];
    __half2* o2 = (__half2*)(out + (size_t)row * Dn) + threadIdx.x * 2;
    o2[0] = __floats2half2_rn(v.x * inv * s4.x, v.y * inv * s4.y);
    o2[1] = __floats2half2_rn(v.z * inv * s4.z, v.w * inv * s4.w);
}

// ---------------- fused per-head RMSNorm + RoPE for q AND k (fp16 in/out) ----------------
#define QWARPS (Bn * Tn * Hn)
#define KWARPS (Bn * Tn * Gn)
__global__ void norm_rope_qk_k(const __half* __restrict__ qp, __half* __restrict__ q16,
                               const __half* __restrict__ kp, __half* __restrict__ k16,
                               const float* __restrict__ qscale, const float* __restrict__ kscale,
                               const float* __restrict__ sinp, const float* __restrict__ cosp) {
    int gw = (blockIdx.x * blockDim.x + threadIdx.x) >> 5;
    int lane = threadIdx.x & 31;
    const __half* src; __half* dst; const float* nscale; int bt;
    if (gw < QWARPS) {
        src = qp + (size_t)gw * Kn;
        dst = q16 + (size_t)gw * Kn;
        nscale = qscale;
        bt = gw / Hn;
    } else {
        int g2 = gw - QWARPS;
        if (g2 >= KWARPS) return;
        src = kp + (size_t)g2 * Kn;
        dst = k16 + (size_t)g2 * Kn;
        nscale = kscale;
        bt = g2 / Gn;
    }
    float x1 = __half2float(src[lane]);
    float x2 = __half2float(src[lane + 32]);
    float ss = x1 * x1 + x2 * x2;
    for (int o = 16; o; o >>= 1) ss += __shfl_xor_sync(0xFFFFFFFFu, ss, o);
    float inv = rsqrtf(ss / (float)Kn + EPSF);
    x1 = x1 * inv * nscale[lane];
    x2 = x2 * inv * nscale[lane + 32];
    float s = sinp[bt * (Kn / 2) + lane];
    float c = cosp[bt * (Kn / 2) + lane];
    dst[lane]      = __float2half(x1 * c - x2 * s);
    dst[lane + 32] = __float2half(x2 * c + x1 * s);
}

// ============================================================
// FP16 GEMM, ldmatrix fragments, single-sync 4-stage cp.async.
// ============================================================
#define HAS 40
#define HG_STAGE 10240
#define HSTG 4
#define HG_SMEM (2 * HSTG * HG_STAGE)

__device__ __forceinline__ void hgemm_issue(uint32_t aB, uint32_t bB, int s,
                                            const __half* Arow, const __half* Brow,
                                            int k0, int Kd) {
    int tid = threadIdx.x;
#pragma unroll
    for (int j = 0; j < 2; j++) {
        int idx = tid + j * 256;
        int row = idx >> 2, ch = idx & 3;
        uint32_t dst = (uint32_t)(row * (HAS * 2) + ch * 16);
        cpa16(aB + s * HG_STAGE + dst, Arow + (size_t)row * Kd + k0 + ch * 8);
        cpa16(bB + s * HG_STAGE + dst, Brow + (size_t)row * Kd + k0 + ch * 8);
    }
}

__device__ __forceinline__ void hgemm_compute(uint32_t aAddr, uint32_t bAddr,
                                              float acc[4][4][4]) {
#pragma unroll
    for (int k2 = 0; k2 < 2; k2++) {
        uint32_t af[4][4], bf[4][2];
#pragma unroll
        for (int mi = 0; mi < 4; mi++)
            LDSM_X4(af[mi][0], af[mi][1], af[mi][2], af[mi][3],
                    aAddr + mi * 16 * 80 + k2 * 32);
#pragma unroll
        for (int p = 0; p < 2; p++)
            LDSM_X4(bf[2 * p][0], bf[2 * p][1], bf[2 * p + 1][0], bf[2 * p + 1][1],
                    bAddr + p * 16 * 80 + k2 * 32);
#pragma unroll
        for (int mi = 0; mi < 4; mi++)
#pragma unroll
            for (int ni = 0; ni < 4; ni++)
                MMA_F16(acc[mi][ni], af[mi][0], af[mi][1], af[mi][2], af[mi][3],
                        bf[ni][0], bf[ni][1]);
    }
}

__device__ __forceinline__ void hgemm_body(const __half* A, const __half* Wt,
                                           const void* aux, void* Cv,
                                           int N, int Kd, int bx, int by,
                                           int mode, int ohalf, char* smn) {
    uint32_t aB = smem_u32(smn);
    uint32_t bB = aB + HSTG * HG_STAGE;
    int tid = threadIdx.x;
    int lane = tid & 31, wid = tid >> 5;
    int wm = wid >> 2, wn = wid & 3;
    int fr = lane >> 2, fc = lane & 3;

    int rA = (lane & 7) + ((lane >> 3) & 1) * 8;
    int cA = (lane >> 4) * 8;
    uint32_t aOff = (uint32_t)((wm * 64 + rA) * 80 + cA * 2);
    int rB = (lane & 7) + (lane >> 4) * 8;
    int cB = ((lane >> 3) & 1) * 8;
    uint32_t bOff = (uint32_t)((wn * 32 + rB) * 80 + cB * 2);

    const __half* Arow = A + (size_t)(by * 128) * Kd;
    const __half* Brow = Wt + (size_t)(bx * 128) * Kd;

    float acc[4][4][4];
#pragma unroll
    for (int mi = 0; mi < 4; mi++)
#pragma unroll
        for (int ni = 0; ni < 4; ni++)
#pragma unroll
            for (int c = 0; c < 4; c++) acc[mi][ni][c] = 0.f;

    int nk = Kd / 32;
    hgemm_issue(aB, bB, 0, Arow, Brow, 0, Kd); CP_COMMIT;
    hgemm_issue(aB, bB, 1, Arow, Brow, 32, Kd); CP_COMMIT;
    hgemm_issue(aB, bB, 2, Arow, Brow, 64, Kd); CP_COMMIT;

    for (int i = 0; i < nk; i++) {
        if (i + 3 <= nk) { CP_WAIT2; }
        else if (i + 2 == nk) { CP_WAIT1; }
        else { CP_WAIT0; }
        __syncthreads();
        if (i + 3 < nk) {
            hgemm_issue(aB, bB, (i + 3) % HSTG, Arow, Brow, (i + 3) * 32, Kd);
            CP_COMMIT;
        }
        int s = i % HSTG;
        hgemm_compute(aB + s * HG_STAGE + aOff, bB + s * HG_STAGE + bOff, acc);
    }

#pragma unroll
    for (int mi = 0; mi < 4; mi++) {
#pragma unroll
        for (int ni = 0; ni < 4; ni++) {
            int row = by * 128 + wm * 64 + mi * 16 + fr;
            int col = bx * 128 + wn * 32 + ni * 8 + fc * 2;
            float2 r0 = make_float2(acc[mi][ni][0], acc[mi][ni][1]);
            float2 r1 = make_float2(acc[mi][ni][2], acc[mi][ni][3]);
            if (mode == 1) {
                const float* ap = (const float*)aux;
                float2 h0 = *(const float2*)(ap + (size_t)row * N + col);
                float2 h1 = *(const float2*)(ap + (size_t)(row + 8) * N + col);
                r0.x += h0.x; r0.y += h0.y;
                r1.x += h1.x; r1.y += h1.y;
            } else if (mode == 2) {
                const __half* gp = (const __half*)aux;
                __half2 g0h = *(const __half2*)(gp + (size_t)row * N + col);
                __half2 g1h = *(const __half2*)(gp + (size_t)(row + 8) * N + col);
                float g0x = __half2float(g0h.x), g0y = __half2float(g0h.y);
                float g1x = __half2float(g1h.x), g1y = __half2float(g1h.y);
                r0.x *= g0x / (1.f + __expf(-g0x));
                r0.y *= g0y / (1.f + __expf(-g0y));
                r1.x *= g1x / (1.f + __expf(-g1x));
                r1.y *= g1y / (1.f + __expf(-g1y));
            }
            if (ohalf) {
                __half* C = (__half*)Cv;
                *(__half2*)(C + (size_t)row * N + col) = __floats2half2_rn(r0.x, r0.y);
                *(__half2*)(C + (size_t)(row + 8) * N + col) = __floats2half2_rn(r1.x, r1.y);
            } else {
                float* C = (float*)Cv;
                *(float2*)(C + (size_t)row * N + col) = r0;
                *(float2*)(C + (size_t)(row + 8) * N + col) = r1;
            }
        }
    }
}

__global__ __launch_bounds__(256, 2) void hgemm_k(
    const __half* __restrict__ A, const __half* __restrict__ Wt,
    const void* __restrict__ aux, void* __restrict__ C,
    int N, int Kd, int mode, int ohalf) {
    extern __shared__ char smn[];
    hgemm_body(A, Wt, aux, C, N, Kd, blockIdx.x, blockIdx.y, mode, ohalf, smn);
}

__global__ __launch_bounds__(256, 2) void hgemm_qkv_k(
    const __half* __restrict__ A,
    const __half* __restrict__ Wtq, const __half* __restrict__ Wtk, const __half* __restrict__ Wtv,
    __half* __restrict__ Cq, __half* __restrict__ Ck, __half* __restrict__ Cv) {
    extern __shared__ char smn[];
    int bx = blockIdx.x;
    const __half* Wt; __half* C; int N;
    if (bx < 8)       { Wt = Wtq; C = Cq; N = 1024; }
    else if (bx < 10) { Wt = Wtk; C = Ck; N = 256; bx -= 8; }
    else              { Wt = Wtv; C = Cv; N = 256; bx -= 10; }
    hgemm_body(A, Wt, (const void*)0, C, N, Dn, bx, blockIdx.y, 0, 1, smn);
}

// ============================================================
// Flash attention, fp16 MMA + ldmatrix fragments.
// ============================================================
#define QSH 72
#define VTH 136
#define PSH 136
#define ATT_SMEM ((128 * QSH + 128 * QSH + 64 * VTH + 128 * PSH) * 2)

__global__ __launch_bounds__(256, 2) void flashattn_k(
    const __half* __restrict__ q16, const __half* __restrict__ k16,
    const __half* __restrict__ vt, __half* __restrict__ out) {
    extern __shared__ __half smh[];
    __half* Qs = smh;
    __half* Ks = Qs + 128 * QSH;
    __half* Vs = Ks + 128 * QSH;
    __half* Ps = Vs + 64 * VTH;
    uint32_t qs_u = smem_u32(Qs), ks_u = smem_u32(Ks), vs_u = smem_u32(Vs);
    uint32_t ps_u = smem_u32(Ps);

    int tid = threadIdx.x;
    int lane = tid & 31, wid = tid >> 5;
    int fr = lane >> 2, fc = lane & 3;
    __half* Pw = Ps + wid * 16 * PSH;

    int rA = (lane & 7) + ((lane >> 3) & 1) * 8;
    int cA = (lane >> 4) * 8;
    int rB = (lane & 7) + (lane >> 4) * 8;
    int cB = ((lane >> 3) & 1) * 8;
    uint32_t qAddr = qs_u + (uint32_t)((wid * 16 + rA) * 144 + cA * 2);
    uint32_t kAddr = ks_u + (uint32_t)(rB * 144 + cB * 2);
    uint32_t pAddr = ps_u + (uint32_t)((wid * 16 + rA) * 272 + cA * 2);
    uint32_t vAddr = vs_u + (uint32_t)(rB * 272 + cB * 2);

    int bg = blockIdx.y;
    int b = bg >> 2, g = bg & 3;
    int t0 = (gridDim.x - 1 - blockIdx.x) * 32;
    int ntiles = (t0 >> 7) + 1;

    const __half* qbase = q16 + ((size_t)((size_t)b * Tn + t0) * Hn + g * Rn) * Kn;
    const __half* kbase = k16 + ((size_t)b * Tn * Gn + g) * Kn;
    const __half* vtbase = vt + (size_t)bg * Kn * Tn;

#pragma unroll
    for (int i = 0; i < 4; i++) {
        int idx = tid + (i << 8);
        int m = idx >> 3, ch = idx & 7;
        cpa16(qs_u + (uint32_t)(m * QSH * 2 + ch * 16),
              qbase + (size_t)(m >> 2) * (Hn * Kn) + (m & 3) * Kn + ch * 8);
    }
    CP_COMMIT;
#pragma unroll
    for (int i = 0; i < 4; i++) {
        int idx = tid + (i << 8);
        int j = idx >> 3, ch = idx & 7;
        cpa16(ks_u + (uint32_t)(j * QSH * 2 + ch * 16),
              kbase + (size_t)j * (Gn * Kn) + ch * 8);
    }
    CP_COMMIT;
#pragma unroll
    for (int i = 0; i < 4; i++) {
        int idx = tid + (i << 8);
        int d = idx >> 4, ch = idx & 15;
        cpa16(vs_u + (uint32_t)(d * VTH * 2 + ch * 16),
              vtbase + (size_t)d * Tn + 0 + ch * 8);
    }
    CP_COMMIT;
    CP_WAIT0;
    __syncthreads();

    float m_r[2], l_r[2], acco[8][4];
#pragma unroll
    for (int h = 0; h < 2; h++) { m_r[h] = -INFINITY; l_r[h] = 0.f; }
#pragma unroll
    for (int ni = 0; ni < 8; ni++)
#pragma unroll
        for (int c = 0; c < 4; c++) acco[ni][c] = 0.f;

    int r0 = wid * 16 + fr;

    for (int it = 0; it < ntiles; it++) {
        int s0 = it << 7;
        bool more = (it + 1 < ntiles);

        float accs[16][4];
#pragma unroll
        for (int ni = 0; ni < 16; ni++)
#pragma unroll
            for (int c = 0; c < 4; c++) accs[ni][c] = 0.f;

#pragma unroll
        for (int k2 = 0; k2 < 4; k2++) {
            uint32_t af[4];
            LDSM_X4(af[0], af[1], af[2], af[3], qAddr + k2 * 32);
#pragma unroll
            for (int p = 0; p < 8; p++) {
                uint32_t b00, b01, b10, b11;
                LDSM_X4(b00, b01, b10, b11, kAddr + p * 16 * 144 + k2 * 32);
                MMA_F16(accs[2 * p], af[0], af[1], af[2], af[3], b00, b01);
                MMA_F16(accs[2 * p + 1], af[0], af[1], af[2], af[3], b10, b11);
            }
        }

#pragma unroll
        for (int ni = 0; ni < 16; ni++)
#pragma unroll
            for (int c = 0; c < 4; c++) accs[ni][c] *= 0.125f;
        if (it == ntiles - 1) {
#pragma unroll
            for (int ni = 0; ni < 16; ni++)
#pragma unroll
                for (int c = 0; c < 4; c++) {
                    int row = r0 + ((c >= 2) ? 8 : 0);
                    int tt = t0 + (row >> 2);
                    int ss = s0 + ni * 8 + fc * 2 + (c & 1);
                    if (ss > tt) accs[ni][c] = -1e30f;
                }
        }

#pragma unroll
        for (int h = 0; h < 2; h++) {
            float mx = -1e30f;
#pragma unroll
            for (int ni = 0; ni < 16; ni++) {
                mx = fmaxf(mx, accs[ni][2 * h]);
                mx = fmaxf(mx, accs[ni][2 * h + 1]);
            }
            mx = fmaxf(mx, __shfl_xor_sync(0xFFFFFFFFu, mx, 1));
            mx = fmaxf(mx, __shfl_xor_sync(0xFFFFFFFFu, mx, 2));
            float mnew = fmaxf(m_r[h], mx);
            float corr = __expf(m_r[h] - mnew);
            m_r[h] = mnew;
            float sum = 0.f;
#pragma unroll
            for (int ni = 0; ni < 16; ni++) {
                float p0 = __expf(accs[ni][2 * h] - mnew);
                float p1 = __expf(accs[ni][2 * h + 1] - mnew);
                accs[ni][2 * h] = p0;
                accs[ni][2 * h + 1] = p1;
                sum += p0 + p1;
            }
            sum += __shfl_xor_sync(0xFFFFFFFFu, sum, 1);
            sum += __shfl_xor_sync(0xFFFFFFFFu, sum, 2);
            l_r[h] = l_r[h] * corr + sum;
#pragma unroll
            for (int ni = 0; ni < 8; ni++) {
                acco[ni][2 * h] *= corr;
                acco[ni][2 * h + 1] *= corr;
            }
        }

#pragma unroll
        for (int ni = 0; ni < 16; ni++) {
            int cc = ni * 8 + fc * 2;
            *(__half2*)(Pw + fr * PSH + cc) = __floats2half2_rn(accs[ni][0], accs[ni][1]);
            *(__half2*)(Pw + (fr + 8) * PSH + cc) = __floats2half2_rn(accs[ni][2], accs[ni][3]);
        }

        __syncthreads();
        if (more) {
            int sn = s0 + 128;
#pragma unroll
            for (int i = 0; i < 4; i++) {
                int idx = tid + (i << 8);
                int j = idx >> 3, ch = idx & 7;
                cpa16(ks_u + (uint32_t)(j * QSH * 2 + ch * 16),
                      kbase + (size_t)(sn + j) * (Gn * Kn) + ch * 8);
            }
            CP_COMMIT;
            CP_WAIT1;
        } else {
            CP_WAIT0;
        }
        __syncthreads();

#pragma unroll
        for (int k2 = 0; k2 < 8; k2++) {
            uint32_t af[4];
            LDSM_X4(af[0], af[1], af[2], af[3], pAddr + k2 * 32);
#pragma unroll
            for (int p = 0; p < 4; p++) {
                uint32_t b00, b01, b10, b11;
                LDSM_X4(b00, b01, b10, b11, vAddr + p * 16 * 272 + k2 * 32);
                MMA_F16(acco[2 * p], af[0], af[1], af[2], af[3], b00, b01);
                MMA_F16(acco[2 * p + 1], af[0], af[1], af[2], af[3], b10, b11);
            }
        }
        __syncthreads();

        if (more) {
            int sn = s0 + 128;
#pragma unroll
            for (int i = 0; i < 4; i++) {
                int idx = tid + (i << 8);
                int d = idx >> 4, ch = idx & 15;
                cpa16(vs_u + (uint32_t)(d * VTH * 2 + ch * 16),
                      vtbase + (size_t)d * Tn + sn + ch * 8);
            }
            CP_COMMIT;
            CP_WAIT1;
            __syncthreads();
        }
    }

#pragma unroll
    for (int h = 0; h < 2; h++) {
        float inv = 1.f / l_r[h];
        int row = r0 + 8 * h;
        int tt = t0 + (row >> 2);
        int hh = g * Rn + (row & 3);
        __half* op = out + ((size_t)((size_t)b * Tn + tt) * Hn + hh) * Kn;
#pragma unroll
        for (int ni = 0; ni < 8; ni++) {
            int col = ni * 8 + fc * 2;
            *(__half2*)(op + col) =
                __floats2half2_rn(acco[ni][2 * h] * inv, acco[ni][2 * h + 1] * inv);
        }
    }
}

// ---------------- launch ----------------
static void hgemm(const __half* A, const __half* Wt, const void* aux, void* C,
                  int M, int N, int Kd, int mode, int ohalf) {
    dim3 grid(N / 128, M / 128);
    hgemm_k<<<grid, 256, HG_SMEM>>>(A, Wt, aux, C, N, Kd, mode, ohalf);
}

extern "C" void kernel_launch(void* const* d_in, const int* in_sizes, int n_in,
                              void* d_out, int out_size) {
    const float* hidden = (const float*)d_in[0];
    const float* sinp   = (const float*)d_in[1];
    const float* cosp   = (const float*)d_in[2];
    /* d_in[3] = mask (exact causal tril; applied analytically) */
    const float* ln1    = (const float*)d_in[4];
    const float* ln2    = (const float*)d_in[5];
    const float* qn     = (const float*)d_in[6];
    const float* kn     = (const float*)d_in[7];
    const float* q_w    = (const float*)d_in[8];
    const float* k_w    = (const float*)d_in[9];
    const float* v_w    = (const float*)d_in[10];
    const float* o_w    = (const float*)d_in[11];
    const float* gate_w = (const float*)d_in[12];
    const float* up_w   = (const float*)d_in[13];
    const float* down_w = (const float*)d_in[14];
    float* out = (float*)d_out;

    cudaFuncSetAttribute(hgemm_k, cudaFuncAttributeMaxDynamicSharedMemorySize, HG_SMEM);
    cudaFuncSetAttribute(hgemm_qkv_k, cudaFuncAttributeMaxDynamicSharedMemorySize, HG_SMEM);
    cudaFuncSetAttribute(flashattn_k, cudaFuncAttributeMaxDynamicSharedMemorySize, ATT_SMEM);

    __half *x, *qp, *kp, *v16, *q16, *k16, *vt, *attn, *y, *gate16, *ff;
    float *h2;
    __half *tq, *tk, *tv, *to, *tg, *tu, *td;
    cudaGetSymbolAddress((void**)&x, g_x);
    cudaGetSymbolAddress((void**)&qp, g_qp);
    cudaGetSymbolAddress((void**)&kp, g_kp);
    cudaGetSymbolAddress((void**)&v16, g_v16);
    cudaGetSymbolAddress((void**)&q16, g_q16);
    cudaGetSymbolAddress((void**)&k16, g_k16);
    cudaGetSymbolAddress((void**)&vt, g_vt);
    cudaGetSymbolAddress((void**)&attn, g_attn);
    cudaGetSymbolAddress((void**)&h2, g_h2);
    cudaGetSymbolAddress((void**)&y, g_y);
    cudaGetSymbolAddress((void**)&gate16, g_gate16);
    cudaGetSymbolAddress((void**)&ff, g_ff);
    cudaGetSymbolAddress((void**)&tq, g_wt_q);
    cudaGetSymbolAddress((void**)&tk, g_wt_k);
    cudaGetSymbolAddress((void**)&tv, g_wt_v);
    cudaGetSymbolAddress((void**)&to, g_wt_o);
    cudaGetSymbolAddress((void**)&tg, g_wt_gate);
    cudaGetSymbolAddress((void**)&tu, g_wt_up);
    cudaGetSymbolAddress((void**)&td, g_wt_down);

    const int M = Mrows;

    transpose_all_k<<<3712, 256>>>(q_w, k_w, v_w, o_w, gate_w, up_w, down_w,
                                   tq, tk, tv, to, tg, tu, td);

    rmsnorm_k<<<M, 256>>>(hidden, ln1, x);

    hgemm_qkv_k<<<dim3(12, M / 128), 256, HG_SMEM>>>(x, tq, tk, tv, qp, kp, v16);

    {
        int total_warps = QWARPS + KWARPS;
        norm_rope_qk_k<<<(total_warps * 32 + 255) / 256, 256>>>(qp, q16, kp, k16,
                                                                qn, kn, sinp, cosp);
        vtrans_k<<<dim3(Tn / 32, Kn / 32, Bn * Gn), 256>>>(v16, vt);
    }

    flashattn_k<<<dim3(Tn / 32, Bn * Gn), 256, ATT_SMEM>>>(q16, k16, vt, attn);

    hgemm(attn, to, hidden, h2, M, Dn, Hn * Kn, 1, 0);

    rmsnorm_k<<<M, 256>>>(h2, ln2, y);

    hgemm(y, tg, (const void*)0, gate16, M, Fn, Dn, 0, 1);
    hgemm(y, tu, gate16, ff, M, Fn, Dn, 2, 1);

    hgemm(ff, td, h2, out, M, Dn, Fn, 1, 0);
}

// round 13
// speedup vs baseline: 2.1214x; 1.0137x over previous
#include <cuda_runtime.h>
#include <cuda_fp16.h>
#include <math.h>
#include <stdint.h>

#define Bn 2
#define Tn 2048
#define Dn 1024
#define Hn 16
#define Gn 4
#define Kn 64
#define Rn (Hn / Gn)
#define Fn 4096
#define EPSF 1e-6f
#define Mrows (Bn * Tn)

// ---------------- scratch ----------------
__device__ __half g_x[Mrows * Dn];
__device__ __half g_qp[Mrows * Hn * Kn];
__device__ __half g_kp[Mrows * Gn * Kn];
__device__ __half g_v16[Mrows * Gn * Kn];
__device__ __half g_q16[Mrows * Hn * Kn];
__device__ __half g_k16[Mrows * Gn * Kn];
__device__ __half g_vt[Bn * Gn * Kn * Tn];
__device__ __half g_attn[Mrows * Hn * Kn];
__device__ float  g_h2[Mrows * Dn];
__device__ __half g_y[Mrows * Dn];
__device__ __half g_gate16[Mrows * Fn];
__device__ __half g_up16[Mrows * Fn];
__device__ __half g_ff[Mrows * Fn];
__device__ __half g_wt_q[1024 * 1024];
__device__ __half g_wt_k[256 * 1024];
__device__ __half g_wt_v[256 * 1024];
__device__ __half g_wt_o[1024 * 1024];
__device__ __half g_wt_gate[4096 * 1024];
__device__ __half g_wt_up[4096 * 1024];
__device__ __half g_wt_down[1024 * 4096];

// ---------------- helpers ----------------
__device__ __forceinline__ uint32_t smem_u32(const void* p) {
    return (uint32_t)__cvta_generic_to_shared(p);
}
__device__ __forceinline__ void cpa16(uint32_t dst, const void* src) {
    asm volatile("cp.async.cg.shared.global [%0], [%1], 16;" ::"r"(dst), "l"(src));
}
#define CP_COMMIT asm volatile("cp.async.commit_group;")
#define CP_WAIT0 asm volatile("cp.async.wait_group 0;")
#define CP_WAIT1 asm volatile("cp.async.wait_group 1;")
#define CP_WAIT2 asm volatile("cp.async.wait_group 2;")

#define MMA_F16(d, a0, a1, a2, a3, b0, b1)                                    \
    asm volatile(                                                             \
        "mma.sync.aligned.m16n8k16.row.col.f32.f16.f16.f32 "                  \
        "{%0,%1,%2,%3}, {%4,%5,%6,%7}, {%8,%9}, {%0,%1,%2,%3};"               \
        : "+f"(d[0]), "+f"(d[1]), "+f"(d[2]), "+f"(d[3])                      \
        : "r"(a0), "r"(a1), "r"(a2), "r"(a3), "r"(b0), "r"(b1))

#define LDSM_X4(r0, r1, r2, r3, addr)                                         \
    asm volatile("ldmatrix.sync.aligned.m8n8.x4.shared.b16 {%0,%1,%2,%3}, [%4];" \
                 : "=r"(r0), "=r"(r1), "=r"(r2), "=r"(r3) : "r"(addr))

// ---------------- 64x64 transpose tile helper (fp32 W[K][N] -> fp16 Wt[N][K]) ----------------
__device__ __forceinline__ void trans_tile(const float* W, __half* Wt, int K, int N,
                                           int bx, int by, float (*t)[65]) {
    {
        int x = threadIdx.x & 63, y = threadIdx.x >> 6;
#pragma unroll
        for (int j = 0; j < 16; j++)
            t[y + j * 4][x] = W[(size_t)(by * 64 + y + j * 4) * N + bx * 64 + x];
    }
    __syncthreads();
    {
        int x = threadIdx.x & 31, y = threadIdx.x >> 5;
#pragma unroll
        for (int j = 0; j < 8; j++) {
            int n = y + j * 8;
            __half2 v = __floats2half2_rn(t[2 * x][n], t[2 * x + 1][n]);
            *(__half2*)(Wt + (size_t)(bx * 64 + n) * K + by * 64 + 2 * x) = v;
        }
    }
}

// ---------------- RMSNorm body (fp32 in, fp16 out) ----------------
__device__ __forceinline__ void rmsnorm_body(const float* __restrict__ in,
                                             const float* __restrict__ sc,
                                             __half* __restrict__ out, int row,
                                             float* sm) {
    const float4* x4 = (const float4*)(in + (size_t)row * Dn);
    float4 v = x4[threadIdx.x];
    float ss = v.x * v.x + v.y * v.y + v.z * v.z + v.w * v.w;
    for (int o = 16; o; o >>= 1) ss += __shfl_xor_sync(0xFFFFFFFFu, ss, o);
    int w = threadIdx.x >> 5;
    if ((threadIdx.x & 31) == 0) sm[w] = ss;
    __syncthreads();
    if (threadIdx.x == 0) {
        float tot = 0.f;
        for (int i = 0; i < 8; i++) tot += sm[i];
        sm[0] = tot;
    }
    __syncthreads();
    float inv = rsqrtf(sm[0] / (float)Dn + EPSF);
    float4 s4 = ((const float4*)sc)[threadIdx.x];
    __half2* o2 = (__half2*)(out + (size_t)row * Dn) + threadIdx.x * 2;
    o2[0] = __floats2half2_rn(v.x * inv * s4.x, v.y * inv * s4.y);
    o2[1] = __floats2half2_rn(v.z * inv * s4.z, v.w * inv * s4.w);
}

// ---------------- pre: rmsnorm(ln1) + q/k/v weight transposes, one launch ----------------
__global__ __launch_bounds__(256) void pre_k(
    const float* __restrict__ hidden, const float* __restrict__ ln1,
    __half* __restrict__ x,
    const float* __restrict__ q_w, const float* __restrict__ k_w,
    const float* __restrict__ v_w,
    __half* __restrict__ tq, __half* __restrict__ tk, __half* __restrict__ tv) {
    __shared__ float t[64][65];
    int b = blockIdx.x;
    if (b < Mrows) {
        rmsnorm_body(hidden, ln1, x, b, &t[0][0]);
        return;
    }
    int b2 = b - Mrows;
    const float* W; __half* Wt; int K, N, base;
    if (b2 < 256)      { W = q_w; Wt = tq; K = 1024; N = 1024; base = 0; }
    else if (b2 < 320) { W = k_w; Wt = tk; K = 1024; N = 256;  base = 256; }
    else               { W = v_w; Wt = tv; K = 1024; N = 256;  base = 320; }
    int local = b2 - base;
    int nb = N >> 6;
    trans_tile(W, Wt, K, N, local % nb, local / nb, t);
}

// ---------------- standalone RMSNorm (for ln2) ----------------
__global__ void rmsnorm_k(const float* __restrict__ in, const float* __restrict__ sc,
                          __half* __restrict__ out) {
    __shared__ float sm[8];
    rmsnorm_body(in, sc, out, blockIdx.x, sm);
}

// ---------------- V transpose ----------------
__global__ void vtrans_k(const __half* __restrict__ v16, __half* __restrict__ vt) {
    __shared__ __half t[32][33];
    int bg = blockIdx.z;
    int b = bg >> 2, g = bg & 3;
    int t0 = blockIdx.x * 32;
    int d0 = blockIdx.y * 32;
    int x = threadIdx.x & 31, y = threadIdx.x >> 5;
#pragma unroll
    for (int j = 0; j < 4; j++) {
        int tt = t0 + y + j * 8;
        t[y + j * 8][x] = v16[((size_t)((size_t)b * Tn + tt) * Gn + g) * Kn + d0 + x];
    }
    __syncthreads();
#pragma unroll
    for (int j = 0; j < 4; j++) {
        int dd = d0 + y + j * 8;
        vt[((size_t)bg * Kn + dd) * Tn + t0 + x] = t[x][y + j * 8];
    }
}

// ---------------- fused per-head RMSNorm + RoPE for q AND k ----------------
#define QWARPS (Bn * Tn * Hn)
#define KWARPS (Bn * Tn * Gn)
__global__ void norm_rope_qk_k(const __half* __restrict__ qp, __half* __restrict__ q16,
                               const __half* __restrict__ kp, __half* __restrict__ k16,
                               const float* __restrict__ qscale, const float* __restrict__ kscale,
                               const float* __restrict__ sinp, const float* __restrict__ cosp) {
    int gw = (blockIdx.x * blockDim.x + threadIdx.x) >> 5;
    int lane = threadIdx.x & 31;
    const __half* src; __half* dst; const float* nscale; int bt;
    if (gw < QWARPS) {
        src = qp + (size_t)gw * Kn;
        dst = q16 + (size_t)gw * Kn;
        nscale = qscale;
        bt = gw / Hn;
    } else {
        int g2 = gw - QWARPS;
        if (g2 >= KWARPS) return;
        src = kp + (size_t)g2 * Kn;
        dst = k16 + (size_t)g2 * Kn;
        nscale = kscale;
        bt = g2 / Gn;
    }
    float x1 = __half2float(src[lane]);
    float x2 = __half2float(src[lane + 32]);
    float ss = x1 * x1 + x2 * x2;
    for (int o = 16; o; o >>= 1) ss += __shfl_xor_sync(0xFFFFFFFFu, ss, o);
    float inv = rsqrtf(ss / (float)Kn + EPSF);
    x1 = x1 * inv * nscale[lane];
    x2 = x2 * inv * nscale[lane + 32];
    float s = sinp[bt * (Kn / 2) + lane];
    float c = cosp[bt * (Kn / 2) + lane];
    dst[lane]      = __float2half(x1 * c - x2 * s);
    dst[lane + 32] = __float2half(x2 * c + x1 * s);
}

// ============================================================
// FP16 GEMM core (ldmatrix, single-sync 4-stage cp.async)
// ============================================================
#define HAS 40
#define HG_STAGE 10240
#define HSTG 4
#define HG_SMEM (2 * HSTG * HG_STAGE)

__device__ __forceinline__ void hgemm_issue(uint32_t aB, uint32_t bB, int s,
                                            const __half* Arow, const __half* Brow,
                                            int k0, int Kd) {
    int tid = threadIdx.x;
#pragma unroll
    for (int j = 0; j < 2; j++) {
        int idx = tid + j * 256;
        int row = idx >> 2, ch = idx & 3;
        uint32_t dst = (uint32_t)(row * (HAS * 2) + ch * 16);
        cpa16(aB + s * HG_STAGE + dst, Arow + (size_t)row * Kd + k0 + ch * 8);
        cpa16(bB + s * HG_STAGE + dst, Brow + (size_t)row * Kd + k0 + ch * 8);
    }
}

__device__ __forceinline__ void hgemm_compute(uint32_t aAddr, uint32_t bAddr,
                                              float acc[4][4][4]) {
#pragma unroll
    for (int k2 = 0; k2 < 2; k2++) {
        uint32_t af[4][4], bf[4][2];
#pragma unroll
        for (int mi = 0; mi < 4; mi++)
            LDSM_X4(af[mi][0], af[mi][1], af[mi][2], af[mi][3],
                    aAddr + mi * 16 * 80 + k2 * 32);
#pragma unroll
        for (int p = 0; p < 2; p++)
            LDSM_X4(bf[2 * p][0], bf[2 * p][1], bf[2 * p + 1][0], bf[2 * p + 1][1],
                    bAddr + p * 16 * 80 + k2 * 32);
#pragma unroll
        for (int mi = 0; mi < 4; mi++)
#pragma unroll
            for (int ni = 0; ni < 4; ni++)
                MMA_F16(acc[mi][ni], af[mi][0], af[mi][1], af[mi][2], af[mi][3],
                        bf[ni][0], bf[ni][1]);
    }
}

__device__ __forceinline__ void hgemm_body(const __half* A, const __half* Wt,
                                           const void* aux, void* Cv,
                                           int N, int Kd, int bx, int by,
                                           int mode, int ohalf, char* smn) {
    uint32_t aB = smem_u32(smn);
    uint32_t bB = aB + HSTG * HG_STAGE;
    int tid = threadIdx.x;
    int lane = tid & 31, wid = tid >> 5;
    int wm = wid >> 2, wn = wid & 3;
    int fr = lane >> 2, fc = lane & 3;

    int rA = (lane & 7) + ((lane >> 3) & 1) * 8;
    int cA = (lane >> 4) * 8;
    uint32_t aOff = (uint32_t)((wm * 64 + rA) * 80 + cA * 2);
    int rB = (lane & 7) + (lane >> 4) * 8;
    int cB = ((lane >> 3) & 1) * 8;
    uint32_t bOff = (uint32_t)((wn * 32 + rB) * 80 + cB * 2);

    const __half* Arow = A + (size_t)(by * 128) * Kd;
    const __half* Brow = Wt + (size_t)(bx * 128) * Kd;

    float acc[4][4][4];
#pragma unroll
    for (int mi = 0; mi < 4; mi++)
#pragma unroll
        for (int ni = 0; ni < 4; ni++)
#pragma unroll
            for (int c = 0; c < 4; c++) acc[mi][ni][c] = 0.f;

    int nk = Kd / 32;
    hgemm_issue(aB, bB, 0, Arow, Brow, 0, Kd); CP_COMMIT;
    hgemm_issue(aB, bB, 1, Arow, Brow, 32, Kd); CP_COMMIT;
    hgemm_issue(aB, bB, 2, Arow, Brow, 64, Kd); CP_COMMIT;

    for (int i = 0; i < nk; i++) {
        if (i + 3 <= nk) { CP_WAIT2; }
        else if (i + 2 == nk) { CP_WAIT1; }
        else { CP_WAIT0; }
        __syncthreads();
        if (i + 3 < nk) {
            hgemm_issue(aB, bB, (i + 3) % HSTG, Arow, Brow, (i + 3) * 32, Kd);
            CP_COMMIT;
        }
        int s = i % HSTG;
        hgemm_compute(aB + s * HG_STAGE + aOff, bB + s * HG_STAGE + bOff, acc);
    }

#pragma unroll
    for (int mi = 0; mi < 4; mi++) {
#pragma unroll
        for (int ni = 0; ni < 4; ni++) {
            int row = by * 128 + wm * 64 + mi * 16 + fr;
            int col = bx * 128 + wn * 32 + ni * 8 + fc * 2;
            float2 r0 = make_float2(acc[mi][ni][0], acc[mi][ni][1]);
            float2 r1 = make_float2(acc[mi][ni][2], acc[mi][ni][3]);
            if (mode == 1) {
                const float* ap = (const float*)aux;
                float2 h0 = *(const float2*)(ap + (size_t)row * N + col);
                float2 h1 = *(const float2*)(ap + (size_t)(row + 8) * N + col);
                r0.x += h0.x; r0.y += h0.y;
                r1.x += h1.x; r1.y += h1.y;
            }
            if (ohalf) {
                __half* C = (__half*)Cv;
                *(__half2*)(C + (size_t)row * N + col) = __floats2half2_rn(r0.x, r0.y);
                *(__half2*)(C + (size_t)(row + 8) * N + col) = __floats2half2_rn(r1.x, r1.y);
            } else {
                float* C = (float*)Cv;
                *(float2*)(C + (size_t)row * N + col) = r0;
                *(float2*)(C + (size_t)(row + 8) * N + col) = r1;
            }
        }
    }
}

__global__ __launch_bounds__(256, 2) void hgemm_k(
    const __half* __restrict__ A, const __half* __restrict__ Wt,
    const void* __restrict__ aux, void* __restrict__ C,
    int N, int Kd, int mode, int ohalf) {
    extern __shared__ char smn[];
    hgemm_body(A, Wt, aux, C, N, Kd, blockIdx.x, blockIdx.y, mode, ohalf, smn);
}

// ---- merged: qkv GEMM (384 blocks) + o/gate/up/down weight transposes (3328) ----
__global__ __launch_bounds__(256, 2) void qkv_trans_k(
    const __half* __restrict__ A,
    const __half* __restrict__ Wtq, const __half* __restrict__ Wtk, const __half* __restrict__ Wtv,
    __half* __restrict__ Cq, __half* __restrict__ Ck, __half* __restrict__ Cv,
    const float* __restrict__ o_w, const float* __restrict__ gate_w,
    const float* __restrict__ up_w, const float* __restrict__ down_w,
    __half* __restrict__ to, __half* __restrict__ tg,
    __half* __restrict__ tu, __half* __restrict__ td) {
    extern __shared__ char smn[];
    int b = blockIdx.x;
    if (b < 384) {
        int bx = b % 12, by = b / 12;
        const __half* Wt; __half* C; int N;
        if (bx < 8)       { Wt = Wtq; C = Cq; N = 1024; }
        else if (bx < 10) { Wt = Wtk; C = Ck; N = 256; bx -= 8; }
        else              { Wt = Wtv; C = Cv; N = 256; bx -= 10; }
        hgemm_body(A, Wt, (const void*)0, C, N, Dn, bx, by, 0, 1, smn);
        return;
    }
    int b2 = b - 384;
    float (*t)[65] = (float(*)[65])smn;
    const float* W; __half* Wt; int K, N, base;
    if (b2 < 256)       { W = o_w;    Wt = to; K = 1024; N = 1024; base = 0; }
    else if (b2 < 1280) { W = gate_w; Wt = tg; K = 1024; N = 4096; base = 256; }
    else if (b2 < 2304) { W = up_w;   Wt = tu; K = 1024; N = 4096; base = 1280; }
    else                { W = down_w; Wt = td; K = 4096; N = 1024; base = 2304; }
    int local = b2 - base;
    int nb = N >> 6;
    trans_tile(W, Wt, K, N, local % nb, local / nb, t);
}

// ---- merged gate + up GEMM (2048 blocks, raw fp16 outputs) ----
__global__ __launch_bounds__(256, 2) void gateup_k(
    const __half* __restrict__ y,
    const __half* __restrict__ Wtg, const __half* __restrict__ Wtu,
    __half* __restrict__ gate16, __half* __restrict__ up16) {
    extern __shared__ char smn[];
    int b = blockIdx.x;
    if (b < 1024)
        hgemm_body(y, Wtg, (const void*)0, gate16, Fn, Dn, b % 32, b / 32, 0, 1, smn);
    else {
        b -= 1024;
        hgemm_body(y, Wtu, (const void*)0, up16, Fn, Dn, b % 32, b / 32, 0, 1, smn);
    }
}

// ---- ff = silu(gate16) * up16, half2x4 vectorized ----
__global__ void silu_mul_k(const __half* __restrict__ gate16,
                           const __half* __restrict__ up16,
                           __half* __restrict__ ff) {
    int i = (blockIdx.x * blockDim.x + threadIdx.x) * 4;  // half2 quads
    const __half2* g2 = (const __half2*)gate16 + i;
    const __half2* u2 = (const __half2*)up16 + i;
    __half2* f2 = (__half2*)ff + i;
#pragma unroll
    for (int j = 0; j < 4; j++) {
        __half2 gh = g2[j], uh = u2[j];
        float gx = __half2float(gh.x), gy = __half2float(gh.y);
        float ux = __half2float(uh.x), uy = __half2float(uh.y);
        f2[j] = __floats2half2_rn(gx / (1.f + __expf(-gx)) * ux,
                                  gy / (1.f + __expf(-gy)) * uy);
    }
}

// ============================================================
// Flash attention, fp16 MMA + ldmatrix fragments (unchanged).
// ============================================================
#define QSH 72
#define VTH 136
#define PSH 136
#define ATT_SMEM ((128 * QSH + 128 * QSH + 64 * VTH + 128 * PSH) * 2)

__global__ __launch_bounds__(256, 2) void flashattn_k(
    const __half* __restrict__ q16, const __half* __restrict__ k16,
    const __half* __restrict__ vt, __half* __restrict__ out) {
    extern __shared__ __half smh[];
    __half* Qs = smh;
    __half* Ks = Qs + 128 * QSH;
    __half* Vs = Ks + 128 * QSH;
    __half* Ps = Vs + 64 * VTH;
    uint32_t qs_u = smem_u32(Qs), ks_u = smem_u32(Ks), vs_u = smem_u32(Vs);
    uint32_t ps_u = smem_u32(Ps);

    int tid = threadIdx.x;
    int lane = tid & 31, wid = tid >> 5;
    int fr = lane >> 2, fc = lane & 3;
    __half* Pw = Ps + wid * 16 * PSH;

    int rA = (lane & 7) + ((lane >> 3) & 1) * 8;
    int cA = (lane >> 4) * 8;
    int rB = (lane & 7) + (lane >> 4) * 8;
    int cB = ((lane >> 3) & 1) * 8;
    uint32_t qAddr = qs_u + (uint32_t)((wid * 16 + rA) * 144 + cA * 2);
    uint32_t kAddr = ks_u + (uint32_t)(rB * 144 + cB * 2);
    uint32_t pAddr = ps_u + (uint32_t)((wid * 16 + rA) * 272 + cA * 2);
    uint32_t vAddr = vs_u + (uint32_t)(rB * 272 + cB * 2);

    int bg = blockIdx.y;
    int b = bg >> 2, g = bg & 3;
    int t0 = (gridDim.x - 1 - blockIdx.x) * 32;
    int ntiles = (t0 >> 7) + 1;

    const __half* qbase = q16 + ((size_t)((size_t)b * Tn + t0) * Hn + g * Rn) * Kn;
    const __half* kbase = k16 + ((size_t)b * Tn * Gn + g) * Kn;
    const __half* vtbase = vt + (size_t)bg * Kn * Tn;

#pragma unroll
    for (int i = 0; i < 4; i++) {
        int idx = tid + (i << 8);
        int m = idx >> 3, ch = idx & 7;
        cpa16(qs_u + (uint32_t)(m * QSH * 2 + ch * 16),
              qbase + (size_t)(m >> 2) * (Hn * Kn) + (m & 3) * Kn + ch * 8);
    }
    CP_COMMIT;
#pragma unroll
    for (int i = 0; i < 4; i++) {
        int idx = tid + (i << 8);
        int j = idx >> 3, ch = idx & 7;
        cpa16(ks_u + (uint32_t)(j * QSH * 2 + ch * 16),
              kbase + (size_t)j * (Gn * Kn) + ch * 8);
    }
    CP_COMMIT;
#pragma unroll
    for (int i = 0; i < 4; i++) {
        int idx = tid + (i << 8);
        int d = idx >> 4, ch = idx & 15;
        cpa16(vs_u + (uint32_t)(d * VTH * 2 + ch * 16),
              vtbase + (size_t)d * Tn + 0 + ch * 8);
    }
    CP_COMMIT;
    CP_WAIT0;
    __syncthreads();

    float m_r[2], l_r[2], acco[8][4];
#pragma unroll
    for (int h = 0; h < 2; h++) { m_r[h] = -INFINITY; l_r[h] = 0.f; }
#pragma unroll
    for (int ni = 0; ni < 8; ni++)
#pragma unroll
        for (int c = 0; c < 4; c++) acco[ni][c] = 0.f;

    int r0 = wid * 16 + fr;

    for (int it = 0; it < ntiles; it++) {
        int s0 = it << 7;
        bool more = (it + 1 < ntiles);

        float accs[16][4];
#pragma unroll
        for (int ni = 0; ni < 16; ni++)
#pragma unroll
            for (int c = 0; c < 4; c++) accs[ni][c] = 0.f;

#pragma unroll
        for (int k2 = 0; k2 < 4; k2++) {
            uint32_t af[4];
            LDSM_X4(af[0], af[1], af[2], af[3], qAddr + k2 * 32);
#pragma unroll
            for (int p = 0; p < 8; p++) {
                uint32_t b00, b01, b10, b11;
                LDSM_X4(b00, b01, b10, b11, kAddr + p * 16 * 144 + k2 * 32);
                MMA_F16(accs[2 * p], af[0], af[1], af[2], af[3], b00, b01);
                MMA_F16(accs[2 * p + 1], af[0], af[1], af[2], af[3], b10, b11);
            }
        }

#pragma unroll
        for (int ni = 0; ni < 16; ni++)
#pragma unroll
            for (int c = 0; c < 4; c++) accs[ni][c] *= 0.125f;
        if (it == ntiles - 1) {
#pragma unroll
            for (int ni = 0; ni < 16; ni++)
#pragma unroll
                for (int c = 0; c < 4; c++) {
                    int row = r0 + ((c >= 2) ? 8 : 0);
                    int tt = t0 + (row >> 2);
                    int ss = s0 + ni * 8 + fc * 2 + (c & 1);
                    if (ss > tt) accs[ni][c] = -1e30f;
                }
        }

#pragma unroll
        for (int h = 0; h < 2; h++) {
            float mx = -1e30f;
#pragma unroll
            for (int ni = 0; ni < 16; ni++) {
                mx = fmaxf(mx, accs[ni][2 * h]);
                mx = fmaxf(mx, accs[ni][2 * h + 1]);
            }
            mx = fmaxf(mx, __shfl_xor_sync(0xFFFFFFFFu, mx, 1));
            mx = fmaxf(mx, __shfl_xor_sync(0xFFFFFFFFu, mx, 2));
            float mnew = fmaxf(m_r[h], mx);
            float corr = __expf(m_r[h] - mnew);
            m_r[h] = mnew;
            float sum = 0.f;
#pragma unroll
            for (int ni = 0; ni < 16; ni++) {
                float p0 = __expf(accs[ni][2 * h] - mnew);
                float p1 = __expf(accs[ni][2 * h + 1] - mnew);
                accs[ni][2 * h] = p0;
                accs[ni][2 * h + 1] = p1;
                sum += p0 + p1;
            }
            sum += __shfl_xor_sync(0xFFFFFFFFu, sum, 1);
            sum += __shfl_xor_sync(0xFFFFFFFFu, sum, 2);
            l_r[h] = l_r[h] * corr + sum;
#pragma unroll
            for (int ni = 0; ni < 8; ni++) {
                acco[ni][2 * h] *= corr;
                acco[ni][2 * h + 1] *= corr;
            }
        }

#pragma unroll
        for (int ni = 0; ni < 16; ni++) {
            int cc = ni * 8 + fc * 2;
            *(__half2*)(Pw + fr * PSH + cc) = __floats2half2_rn(accs[ni][0], accs[ni][1]);
            *(__half2*)(Pw + (fr + 8) * PSH + cc) = __floats2half2_rn(accs[ni][2], accs[ni][3]);
        }

        __syncthreads();
        if (more) {
            int sn = s0 + 128;
#pragma unroll
            for (int i = 0; i < 4; i++) {
                int idx = tid + (i << 8);
                int j = idx >> 3, ch = idx & 7;
                cpa16(ks_u + (uint32_t)(j * QSH * 2 + ch * 16),
                      kbase + (size_t)(sn + j) * (Gn * Kn) + ch * 8);
            }
            CP_COMMIT;
            CP_WAIT1;
        } else {
            CP_WAIT0;
        }
        __syncthreads();

#pragma unroll
        for (int k2 = 0; k2 < 8; k2++) {
            uint32_t af[4];
            LDSM_X4(af[0], af[1], af[2], af[3], pAddr + k2 * 32);
#pragma unroll
            for (int p = 0; p < 4; p++) {
                uint32_t b00, b01, b10, b11;
                LDSM_X4(b00, b01, b10, b11, vAddr + p * 16 * 272 + k2 * 32);
                MMA_F16(acco[2 * p], af[0], af[1], af[2], af[3], b00, b01);
                MMA_F16(acco[2 * p + 1], af[0], af[1], af[2], af[3], b10, b11);
            }
        }
        __syncthreads();

        if (more) {
            int sn = s0 + 128;
#pragma unroll
            for (int i = 0; i < 4; i++) {
                int idx = tid + (i << 8);
                int d = idx >> 4, ch = idx & 15;
                cpa16(vs_u + (uint32_t)(d * VTH * 2 + ch * 16),
                      vtbase + (size_t)d * Tn + sn + ch * 8);
            }
            CP_COMMIT;
            CP_WAIT1;
            __syncthreads();
        }
    }

#pragma unroll
    for (int h = 0; h < 2; h++) {
        float inv = 1.f / l_r[h];
        int row = r0 + 8 * h;
        int tt = t0 + (row >> 2);
        int hh = g * Rn + (row & 3);
        __half* op = out + ((size_t)((size_t)b * Tn + tt) * Hn + hh) * Kn;
#pragma unroll
        for (int ni = 0; ni < 8; ni++) {
            int col = ni * 8 + fc * 2;
            *(__half2*)(op + col) =
                __floats2half2_rn(acco[ni][2 * h] * inv, acco[ni][2 * h + 1] * inv);
        }
    }
}

// ---------------- launch ----------------
static void hgemm(const __half* A, const __half* Wt, const void* aux, void* C,
                  int M, int N, int Kd, int mode, int ohalf) {
    dim3 grid(N / 128, M / 128);
    hgemm_k<<<grid, 256, HG_SMEM>>>(A, Wt, aux, C, N, Kd, mode, ohalf);
}

extern "C" void kernel_launch(void* const* d_in, const int* in_sizes, int n_in,
                              void* d_out, int out_size) {
    const float* hidden = (const float*)d_in[0];
    const float* sinp   = (const float*)d_in[1];
    const float* cosp   = (const float*)d_in[2];
    /* d_in[3] = mask (exact causal tril; applied analytically) */
    const float* ln1    = (const float*)d_in[4];
    const float* ln2    = (const float*)d_in[5];
    const float* qn     = (const float*)d_in[6];
    const float* kn     = (const float*)d_in[7];
    const float* q_w    = (const float*)d_in[8];
    const float* k_w    = (const float*)d_in[9];
    const float* v_w    = (const float*)d_in[10];
    const float* o_w    = (const float*)d_in[11];
    const float* gate_w = (const float*)d_in[12];
    const float* up_w   = (const float*)d_in[13];
    const float* down_w = (const float*)d_in[14];
    float* out = (float*)d_out;

    cudaFuncSetAttribute(hgemm_k, cudaFuncAttributeMaxDynamicSharedMemorySize, HG_SMEM);
    cudaFuncSetAttribute(qkv_trans_k, cudaFuncAttributeMaxDynamicSharedMemorySize, HG_SMEM);
    cudaFuncSetAttribute(gateup_k, cudaFuncAttributeMaxDynamicSharedMemorySize, HG_SMEM);
    cudaFuncSetAttribute(flashattn_k, cudaFuncAttributeMaxDynamicSharedMemorySize, ATT_SMEM);

    __half *x, *qp, *kp, *v16, *q16, *k16, *vt, *attn, *y, *gate16, *up16, *ff;
    float *h2;
    __half *tq, *tk, *tv, *to, *tg, *tu, *td;
    cudaGetSymbolAddress((void**)&x, g_x);
    cudaGetSymbolAddress((void**)&qp, g_qp);
    cudaGetSymbolAddress((void**)&kp, g_kp);
    cudaGetSymbolAddress((void**)&v16, g_v16);
    cudaGetSymbolAddress((void**)&q16, g_q16);
    cudaGetSymbolAddress((void**)&k16, g_k16);
    cudaGetSymbolAddress((void**)&vt, g_vt);
    cudaGetSymbolAddress((void**)&attn, g_attn);
    cudaGetSymbolAddress((void**)&h2, g_h2);
    cudaGetSymbolAddress((void**)&y, g_y);
    cudaGetSymbolAddress((void**)&gate16, g_gate16);
    cudaGetSymbolAddress((void**)&up16, g_up16);
    cudaGetSymbolAddress((void**)&ff, g_ff);
    cudaGetSymbolAddress((void**)&tq, g_wt_q);
    cudaGetSymbolAddress((void**)&tk, g_wt_k);
    cudaGetSymbolAddress((void**)&tv, g_wt_v);
    cudaGetSymbolAddress((void**)&to, g_wt_o);
    cudaGetSymbolAddress((void**)&tg, g_wt_gate);
    cudaGetSymbolAddress((void**)&tu, g_wt_up);
    cudaGetSymbolAddress((void**)&td, g_wt_down);

    const int M = Mrows;

    // 1. rmsnorm(ln1) + q/k/v weight transposes (one launch)
    pre_k<<<Mrows + 384, 256>>>(hidden, ln1, x, q_w, k_w, v_w, tq, tk, tv);

    // 2. qkv GEMM + o/gate/up/down weight transposes (tail-filled)
    qkv_trans_k<<<384 + 3328, 256, HG_SMEM>>>(x, tq, tk, tv, qp, kp, v16,
                                              o_w, gate_w, up_w, down_w,
                                              to, tg, tu, td);

    // 3. head norm + rope (q & k fused) + V^T
    {
        int total_warps = QWARPS + KWARPS;
        norm_rope_qk_k<<<(total_warps * 32 + 255) / 256, 256>>>(qp, q16, kp, k16,
                                                                qn, kn, sinp, cosp);
        vtrans_k<<<dim3(Tn / 32, Kn / 32, Bn * Gn), 256>>>(v16, vt);
    }

    // 4. attention
    flashattn_k<<<dim3(Tn / 32, Bn * Gn), 256, ATT_SMEM>>>(q16, k16, vt, attn);

    // 5. h2 = hidden + attn @ o_w
    hgemm(attn, to, hidden, h2, M, Dn, Hn * Kn, 1, 0);

    // 6. y = rmsnorm(h2)
    rmsnorm_k<<<M, 256>>>(h2, ln2, y);

    // 7. gate & up GEMMs in one launch (raw fp16)
    gateup_k<<<2048, 256, HG_SMEM>>>(y, tg, tu, gate16, up16);

    // 8. ff = silu(gate) * up
    silu_mul_k<<<(M * Fn / 8 + 255) / 256, 256>>>(gate16, up16, ff);

    // 9. out = h2 + ff @ down_w
    hgemm(ff, td, h2, out, M, Dn, Fn, 1, 0);
}

// round 14
// speedup vs baseline: 2.1498x; 1.0134x over previous
#include <cuda_runtime.h>
#include <cuda_fp16.h>
#include <math.h>
#include <stdint.h>

#define Bn 2
#define Tn 2048
#define Dn 1024
#define Hn 16
#define Gn 4
#define Kn 64
#define Rn (Hn / Gn)
#define Fn 4096
#define EPSF 1e-6f
#define Mrows (Bn * Tn)

// ---------------- scratch ----------------
__device__ __half g_x[Mrows * Dn];
__device__ __half g_qp[Mrows * Hn * Kn];
__device__ __half g_kp[Mrows * Gn * Kn];
__device__ __half g_v16[Mrows * Gn * Kn];
__device__ __half g_q16[Mrows * Hn * Kn];
__device__ __half g_k16[Mrows * Gn * Kn];
__device__ __half g_vt[Bn * Gn * Kn * Tn];
__device__ __half g_attn[Mrows * Hn * Kn];
__device__ float  g_h2[Mrows * Dn];
__device__ __half g_y[Mrows * Dn];
__device__ __half g_gate16[Mrows * Fn];
__device__ __half g_up16[Mrows * Fn];
__device__ __half g_ff[Mrows * Fn];
__device__ __half g_wt_q[1024 * 1024];
__device__ __half g_wt_k[256 * 1024];
__device__ __half g_wt_v[256 * 1024];
__device__ __half g_wt_o[1024 * 1024];
__device__ __half g_wt_gate[4096 * 1024];
__device__ __half g_wt_up[4096 * 1024];
__device__ __half g_wt_down[1024 * 4096];

// ---------------- helpers ----------------
__device__ __forceinline__ uint32_t smem_u32(const void* p) {
    return (uint32_t)__cvta_generic_to_shared(p);
}
__device__ __forceinline__ void cpa16(uint32_t dst, const void* src) {
    asm volatile("cp.async.cg.shared.global [%0], [%1], 16;" ::"r"(dst), "l"(src));
}
#define CP_COMMIT asm volatile("cp.async.commit_group;")
#define CP_WAIT0 asm volatile("cp.async.wait_group 0;")
#define CP_WAIT1 asm volatile("cp.async.wait_group 1;")
#define CP_WAIT2 asm volatile("cp.async.wait_group 2;")

#define MMA_F16(d, a0, a1, a2, a3, b0, b1)                                    \
    asm volatile(                                                             \
        "mma.sync.aligned.m16n8k16.row.col.f32.f16.f16.f32 "                  \
        "{%0,%1,%2,%3}, {%4,%5,%6,%7}, {%8,%9}, {%0,%1,%2,%3};"               \
        : "+f"(d[0]), "+f"(d[1]), "+f"(d[2]), "+f"(d[3])                      \
        : "r"(a0), "r"(a1), "r"(a2), "r"(a3), "r"(b0), "r"(b1))

#define LDSM_X4(r0, r1, r2, r3, addr)                                         \
    asm volatile("ldmatrix.sync.aligned.m8n8.x4.shared.b16 {%0,%1,%2,%3}, [%4];" \
                 : "=r"(r0), "=r"(r1), "=r"(r2), "=r"(r3) : "r"(addr))

// ---------------- 64x64 transpose tile helper ----------------
__device__ __forceinline__ void trans_tile(const float* W, __half* Wt, int K, int N,
                                           int bx, int by, float (*t)[65]) {
    {
        int x = threadIdx.x & 63, y = threadIdx.x >> 6;
#pragma unroll
        for (int j = 0; j < 16; j++)
            t[y + j * 4][x] = W[(size_t)(by * 64 + y + j * 4) * N + bx * 64 + x];
    }
    __syncthreads();
    {
        int x = threadIdx.x & 31, y = threadIdx.x >> 5;
#pragma unroll
        for (int j = 0; j < 8; j++) {
            int n = y + j * 8;
            __half2 v = __floats2half2_rn(t[2 * x][n], t[2 * x + 1][n]);
            *(__half2*)(Wt + (size_t)(bx * 64 + n) * K + by * 64 + 2 * x) = v;
        }
    }
}

// ---------------- RMSNorm body ----------------
__device__ __forceinline__ void rmsnorm_body(const float* __restrict__ in,
                                             const float* __restrict__ sc,
                                             __half* __restrict__ out, int row,
                                             float* sm) {
    const float4* x4 = (const float4*)(in + (size_t)row * Dn);
    float4 v = x4[threadIdx.x];
    float ss = v.x * v.x + v.y * v.y + v.z * v.z + v.w * v.w;
    for (int o = 16; o; o >>= 1) ss += __shfl_xor_sync(0xFFFFFFFFu, ss, o);
    int w = threadIdx.x >> 5;
    if ((threadIdx.x & 31) == 0) sm[w] = ss;
    __syncthreads();
    if (threadIdx.x == 0) {
        float tot = 0.f;
        for (int i = 0; i < 8; i++) tot += sm[i];
        sm[0] = tot;
    }
    __syncthreads();
    float inv = rsqrtf(sm[0] / (float)Dn + EPSF);
    float4 s4 = ((const float4*)sc)[threadIdx.x];
    __half2* o2 = (__half2*)(out + (size_t)row * Dn) + threadIdx.x * 2;
    o2[0] = __floats2half2_rn(v.x * inv * s4.x, v.y * inv * s4.y);
    o2[1] = __floats2half2_rn(v.z * inv * s4.z, v.w * inv * s4.w);
}

// ---------------- pre: rmsnorm(ln1) + q/k/v weight transposes ----------------
__global__ __launch_bounds__(256) void pre_k(
    const float* __restrict__ hidden, const float* __restrict__ ln1,
    __half* __restrict__ x,
    const float* __restrict__ q_w, const float* __restrict__ k_w,
    const float* __restrict__ v_w,
    __half* __restrict__ tq, __half* __restrict__ tk, __half* __restrict__ tv) {
    __shared__ float t[64][65];
    int b = blockIdx.x;
    if (b < Mrows) {
        rmsnorm_body(hidden, ln1, x, b, &t[0][0]);
        return;
    }
    int b2 = b - Mrows;
    const float* W; __half* Wt; int K, N, base;
    if (b2 < 256)      { W = q_w; Wt = tq; K = 1024; N = 1024; base = 0; }
    else if (b2 < 320) { W = k_w; Wt = tk; K = 1024; N = 256;  base = 256; }
    else               { W = v_w; Wt = tv; K = 1024; N = 256;  base = 320; }
    int local = b2 - base;
    int nb = N >> 6;
    trans_tile(W, Wt, K, N, local % nb, local / nb, t);
}

// ---------------- standalone RMSNorm (ln2) ----------------
__global__ void rmsnorm_k(const float* __restrict__ in, const float* __restrict__ sc,
                          __half* __restrict__ out) {
    __shared__ float sm[8];
    rmsnorm_body(in, sc, out, blockIdx.x, sm);
}

// ---------------- merged: per-head norm+rope (q,k) + V transpose ----------------
#define QWARPS (Bn * Tn * Hn)
#define KWARPS (Bn * Tn * Gn)
#define NR_BLOCKS ((QWARPS + KWARPS) / 8)   // 10240
__global__ void norm_vt_k(const __half* __restrict__ qp, __half* __restrict__ q16,
                          const __half* __restrict__ kp, __half* __restrict__ k16,
                          const float* __restrict__ qscale, const float* __restrict__ kscale,
                          const float* __restrict__ sinp, const float* __restrict__ cosp,
                          const __half* __restrict__ v16, __half* __restrict__ vt) {
    __shared__ __half t[32][33];
    int b = blockIdx.x;
    if (b >= NR_BLOCKS) {
        int b2 = b - NR_BLOCKS;  // vtrans: 1024 blocks
        int xb = b2 & 63, yb = (b2 >> 6) & 1, bg = b2 >> 7;
        int bb = bg >> 2, g = bg & 3;
        int t0 = xb * 32, d0 = yb * 32;
        int x = threadIdx.x & 31, y = threadIdx.x >> 5;
#pragma unroll
        for (int j = 0; j < 4; j++) {
            int tt = t0 + y + j * 8;
            t[y + j * 8][x] = v16[((size_t)((size_t)bb * Tn + tt) * Gn + g) * Kn + d0 + x];
        }
        __syncthreads();
#pragma unroll
        for (int j = 0; j < 4; j++) {
            int dd = d0 + y + j * 8;
            vt[((size_t)bg * Kn + dd) * Tn + t0 + x] = t[x][y + j * 8];
        }
        return;
    }
    int gw = b * 8 + (threadIdx.x >> 5);
    int lane = threadIdx.x & 31;
    const __half* src; __half* dst; const float* nscale; int bt;
    if (gw < QWARPS) {
        src = qp + (size_t)gw * Kn;
        dst = q16 + (size_t)gw * Kn;
        nscale = qscale;
        bt = gw / Hn;
    } else {
        int g2 = gw - QWARPS;
        src = kp + (size_t)g2 * Kn;
        dst = k16 + (size_t)g2 * Kn;
        nscale = kscale;
        bt = g2 / Gn;
    }
    float x1 = __half2float(src[lane]);
    float x2 = __half2float(src[lane + 32]);
    float ss = x1 * x1 + x2 * x2;
    for (int o = 16; o; o >>= 1) ss += __shfl_xor_sync(0xFFFFFFFFu, ss, o);
    float inv = rsqrtf(ss / (float)Kn + EPSF);
    x1 = x1 * inv * nscale[lane];
    x2 = x2 * inv * nscale[lane + 32];
    float s = sinp[bt * (Kn / 2) + lane];
    float c = cosp[bt * (Kn / 2) + lane];
    dst[lane]      = __float2half(x1 * c - x2 * s);
    dst[lane + 32] = __float2half(x2 * c + x1 * s);
}

// ============================================================
// FP16 GEMM core (ldmatrix, single-sync 4-stage cp.async)
// ============================================================
#define HAS 40
#define HG_STAGE 10240
#define HSTG 4
#define HG_SMEM (2 * HSTG * HG_STAGE)

__device__ __forceinline__ void hgemm_issue(uint32_t aB, uint32_t bB, int s,
                                            const __half* Arow, const __half* Brow,
                                            int k0, int Kd) {
    int tid = threadIdx.x;
#pragma unroll
    for (int j = 0; j < 2; j++) {
        int idx = tid + j * 256;
        int row = idx >> 2, ch = idx & 3;
        uint32_t dst = (uint32_t)(row * (HAS * 2) + ch * 16);
        cpa16(aB + s * HG_STAGE + dst, Arow + (size_t)row * Kd + k0 + ch * 8);
        cpa16(bB + s * HG_STAGE + dst, Brow + (size_t)row * Kd + k0 + ch * 8);
    }
}

__device__ __forceinline__ void hgemm_compute(uint32_t aAddr, uint32_t bAddr,
                                              float acc[4][4][4]) {
#pragma unroll
    for (int k2 = 0; k2 < 2; k2++) {
        uint32_t af[4][4], bf[4][2];
#pragma unroll
        for (int mi = 0; mi < 4; mi++)
            LDSM_X4(af[mi][0], af[mi][1], af[mi][2], af[mi][3],
                    aAddr + mi * 16 * 80 + k2 * 32);
#pragma unroll
        for (int p = 0; p < 2; p++)
            LDSM_X4(bf[2 * p][0], bf[2 * p][1], bf[2 * p + 1][0], bf[2 * p + 1][1],
                    bAddr + p * 16 * 80 + k2 * 32);
#pragma unroll
        for (int mi = 0; mi < 4; mi++)
#pragma unroll
            for (int ni = 0; ni < 4; ni++)
                MMA_F16(acc[mi][ni], af[mi][0], af[mi][1], af[mi][2], af[mi][3],
                        bf[ni][0], bf[ni][1]);
    }
}

__device__ __forceinline__ void hgemm_body(const __half* A, const __half* Wt,
                                           const void* aux, void* Cv,
                                           int N, int Kd, int bx, int by,
                                           int mode, int ohalf, char* smn) {
    uint32_t aB = smem_u32(smn);
    uint32_t bB = aB + HSTG * HG_STAGE;
    int tid = threadIdx.x;
    int lane = tid & 31, wid = tid >> 5;
    int wm = wid >> 2, wn = wid & 3;
    int fr = lane >> 2, fc = lane & 3;

    int rA = (lane & 7) + ((lane >> 3) & 1) * 8;
    int cA = (lane >> 4) * 8;
    uint32_t aOff = (uint32_t)((wm * 64 + rA) * 80 + cA * 2);
    int rB = (lane & 7) + (lane >> 4) * 8;
    int cB = ((lane >> 3) & 1) * 8;
    uint32_t bOff = (uint32_t)((wn * 32 + rB) * 80 + cB * 2);

    const __half* Arow = A + (size_t)(by * 128) * Kd;
    const __half* Brow = Wt + (size_t)(bx * 128) * Kd;

    float acc[4][4][4];
#pragma unroll
    for (int mi = 0; mi < 4; mi++)
#pragma unroll
        for (int ni = 0; ni < 4; ni++)
#pragma unroll
            for (int c = 0; c < 4; c++) acc[mi][ni][c] = 0.f;

    int nk = Kd / 32;
    hgemm_issue(aB, bB, 0, Arow, Brow, 0, Kd); CP_COMMIT;
    hgemm_issue(aB, bB, 1, Arow, Brow, 32, Kd); CP_COMMIT;
    hgemm_issue(aB, bB, 2, Arow, Brow, 64, Kd); CP_COMMIT;

    for (int i = 0; i < nk; i++) {
        if (i + 3 <= nk) { CP_WAIT2; }
        else if (i + 2 == nk) { CP_WAIT1; }
        else { CP_WAIT0; }
        __syncthreads();
        if (i + 3 < nk) {
            hgemm_issue(aB, bB, (i + 3) % HSTG, Arow, Brow, (i + 3) * 32, Kd);
            CP_COMMIT;
        }
        int s = i % HSTG;
        hgemm_compute(aB + s * HG_STAGE + aOff, bB + s * HG_STAGE + bOff, acc);
    }

#pragma unroll
    for (int mi = 0; mi < 4; mi++) {
#pragma unroll
        for (int ni = 0; ni < 4; ni++) {
            int row = by * 128 + wm * 64 + mi * 16 + fr;
            int col = bx * 128 + wn * 32 + ni * 8 + fc * 2;
            float2 r0 = make_float2(acc[mi][ni][0], acc[mi][ni][1]);
            float2 r1 = make_float2(acc[mi][ni][2], acc[mi][ni][3]);
            if (mode == 1) {
                const float* ap = (const float*)aux;
                float2 h0 = *(const float2*)(ap + (size_t)row * N + col);
                float2 h1 = *(const float2*)(ap + (size_t)(row + 8) * N + col);
                r0.x += h0.x; r0.y += h0.y;
                r1.x += h1.x; r1.y += h1.y;
            }
            if (ohalf) {
                __half* C = (__half*)Cv;
                *(__half2*)(C + (size_t)row * N + col) = __floats2half2_rn(r0.x, r0.y);
                *(__half2*)(C + (size_t)(row + 8) * N + col) = __floats2half2_rn(r1.x, r1.y);
            } else {
                float* C = (float*)Cv;
                *(float2*)(C + (size_t)row * N + col) = r0;
                *(float2*)(C + (size_t)(row + 8) * N + col) = r1;
            }
        }
    }
}

__global__ __launch_bounds__(256, 2) void hgemm_k(
    const __half* __restrict__ A, const __half* __restrict__ Wt,
    const void* __restrict__ aux, void* __restrict__ C,
    int N, int Kd, int mode, int ohalf) {
    extern __shared__ char smn[];
    hgemm_body(A, Wt, aux, C, N, Kd, blockIdx.x, blockIdx.y, mode, ohalf, smn);
}

// ---- merged: qkv GEMM (384) + o_w transpose (256) ----
__global__ __launch_bounds__(256, 2) void qkv_trans_k(
    const __half* __restrict__ A,
    const __half* __restrict__ Wtq, const __half* __restrict__ Wtk, const __half* __restrict__ Wtv,
    __half* __restrict__ Cq, __half* __restrict__ Ck, __half* __restrict__ Cv,
    const float* __restrict__ o_w, __half* __restrict__ to) {
    extern __shared__ char smn[];
    int b = blockIdx.x;
    if (b < 384) {
        int bx = b % 12, by = b / 12;
        const __half* Wt; __half* C; int N;
        if (bx < 8)       { Wt = Wtq; C = Cq; N = 1024; }
        else if (bx < 10) { Wt = Wtk; C = Ck; N = 256; bx -= 8; }
        else              { Wt = Wtv; C = Cv; N = 256; bx -= 10; }
        hgemm_body(A, Wt, (const void*)0, C, N, Dn, bx, by, 0, 1, smn);
        return;
    }
    int b2 = b - 384;  // 256 o_w tiles
    float (*t)[65] = (float(*)[65])smn;
    trans_tile(o_w, to, 1024, 1024, b2 % 16, b2 / 16, t);
}

// ---- merged gate + up GEMM ----
__global__ __launch_bounds__(256, 2) void gateup_k(
    const __half* __restrict__ y,
    const __half* __restrict__ Wtg, const __half* __restrict__ Wtu,
    __half* __restrict__ gate16, __half* __restrict__ up16) {
    extern __shared__ char smn[];
    int b = blockIdx.x;
    if (b < 1024)
        hgemm_body(y, Wtg, (const void*)0, gate16, Fn, Dn, b % 32, b / 32, 0, 1, smn);
    else {
        b -= 1024;
        hgemm_body(y, Wtu, (const void*)0, up16, Fn, Dn, b % 32, b / 32, 0, 1, smn);
    }
}

// ---- ff = silu(gate16) * up16 ----
__global__ void silu_mul_k(const __half* __restrict__ gate16,
                           const __half* __restrict__ up16,
                           __half* __restrict__ ff) {
    int i = (blockIdx.x * blockDim.x + threadIdx.x) * 4;
    const __half2* g2 = (const __half2*)gate16 + i;
    const __half2* u2 = (const __half2*)up16 + i;
    __half2* f2 = (__half2*)ff + i;
#pragma unroll
    for (int j = 0; j < 4; j++) {
        __half2 gh = g2[j], uh = u2[j];
        float gx = __half2float(gh.x), gy = __half2float(gh.y);
        float ux = __half2float(uh.x), uy = __half2float(uh.y);
        f2[j] = __floats2half2_rn(gx / (1.f + __expf(-gx)) * ux,
                                  gy / (1.f + __expf(-gy)) * uy);
    }
}

// ============================================================
// Flash attention body (fp16 MMA + ldmatrix)
// ============================================================
#define QSH 72
#define VTH 136
#define PSH 136
#define ATT_SMEM ((128 * QSH + 128 * QSH + 64 * VTH + 128 * PSH) * 2)

__device__ __forceinline__ void flashattn_body(
    const __half* __restrict__ q16, const __half* __restrict__ k16,
    const __half* __restrict__ vt, __half* __restrict__ out,
    int bxi, int bg, int nbx, __half* smh) {
    __half* Qs = smh;
    __half* Ks = Qs + 128 * QSH;
    __half* Vs = Ks + 128 * QSH;
    __half* Ps = Vs + 64 * VTH;
    uint32_t qs_u = smem_u32(Qs), ks_u = smem_u32(Ks), vs_u = smem_u32(Vs);
    uint32_t ps_u = smem_u32(Ps);

    int tid = threadIdx.x;
    int lane = tid & 31, wid = tid >> 5;
    int fr = lane >> 2, fc = lane & 3;
    __half* Pw = Ps + wid * 16 * PSH;

    int rA = (lane & 7) + ((lane >> 3) & 1) * 8;
    int cA = (lane >> 4) * 8;
    int rB = (lane & 7) + (lane >> 4) * 8;
    int cB = ((lane >> 3) & 1) * 8;
    uint32_t qAddr = qs_u + (uint32_t)((wid * 16 + rA) * 144 + cA * 2);
    uint32_t kAddr = ks_u + (uint32_t)(rB * 144 + cB * 2);
    uint32_t pAddr = ps_u + (uint32_t)((wid * 16 + rA) * 272 + cA * 2);
    uint32_t vAddr = vs_u + (uint32_t)(rB * 272 + cB * 2);

    int b = bg >> 2, g = bg & 3;
    int t0 = (nbx - 1 - bxi) * 32;
    int ntiles = (t0 >> 7) + 1;

    const __half* qbase = q16 + ((size_t)((size_t)b * Tn + t0) * Hn + g * Rn) * Kn;
    const __half* kbase = k16 + ((size_t)b * Tn * Gn + g) * Kn;
    const __half* vtbase = vt + (size_t)bg * Kn * Tn;

#pragma unroll
    for (int i = 0; i < 4; i++) {
        int idx = tid + (i << 8);
        int m = idx >> 3, ch = idx & 7;
        cpa16(qs_u + (uint32_t)(m * QSH * 2 + ch * 16),
              qbase + (size_t)(m >> 2) * (Hn * Kn) + (m & 3) * Kn + ch * 8);
    }
    CP_COMMIT;
#pragma unroll
    for (int i = 0; i < 4; i++) {
        int idx = tid + (i << 8);
        int j = idx >> 3, ch = idx & 7;
        cpa16(ks_u + (uint32_t)(j * QSH * 2 + ch * 16),
              kbase + (size_t)j * (Gn * Kn) + ch * 8);
    }
    CP_COMMIT;
#pragma unroll
    for (int i = 0; i < 4; i++) {
        int idx = tid + (i << 8);
        int d = idx >> 4, ch = idx & 15;
        cpa16(vs_u + (uint32_t)(d * VTH * 2 + ch * 16),
              vtbase + (size_t)d * Tn + 0 + ch * 8);
    }
    CP_COMMIT;
    CP_WAIT0;
    __syncthreads();

    float m_r[2], l_r[2], acco[8][4];
#pragma unroll
    for (int h = 0; h < 2; h++) { m_r[h] = -INFINITY; l_r[h] = 0.f; }
#pragma unroll
    for (int ni = 0; ni < 8; ni++)
#pragma unroll
        for (int c = 0; c < 4; c++) acco[ni][c] = 0.f;

    int r0 = wid * 16 + fr;

    for (int it = 0; it < ntiles; it++) {
        int s0 = it << 7;
        bool more = (it + 1 < ntiles);

        float accs[16][4];
#pragma unroll
        for (int ni = 0; ni < 16; ni++)
#pragma unroll
            for (int c = 0; c < 4; c++) accs[ni][c] = 0.f;

#pragma unroll
        for (int k2 = 0; k2 < 4; k2++) {
            uint32_t af[4];
            LDSM_X4(af[0], af[1], af[2], af[3], qAddr + k2 * 32);
#pragma unroll
            for (int p = 0; p < 8; p++) {
                uint32_t b00, b01, b10, b11;
                LDSM_X4(b00, b01, b10, b11, kAddr + p * 16 * 144 + k2 * 32);
                MMA_F16(accs[2 * p], af[0], af[1], af[2], af[3], b00, b01);
                MMA_F16(accs[2 * p + 1], af[0], af[1], af[2], af[3], b10, b11);
            }
        }

#pragma unroll
        for (int ni = 0; ni < 16; ni++)
#pragma unroll
            for (int c = 0; c < 4; c++) accs[ni][c] *= 0.125f;
        if (it == ntiles - 1) {
#pragma unroll
            for (int ni = 0; ni < 16; ni++)
#pragma unroll
                for (int c = 0; c < 4; c++) {
                    int row = r0 + ((c >= 2) ? 8 : 0);
                    int tt = t0 + (row >> 2);
                    int ss = s0 + ni * 8 + fc * 2 + (c & 1);
                    if (ss > tt) accs[ni][c] = -1e30f;
                }
        }

#pragma unroll
        for (int h = 0; h < 2; h++) {
            float mx = -1e30f;
#pragma unroll
            for (int ni = 0; ni < 16; ni++) {
                mx = fmaxf(mx, accs[ni][2 * h]);
                mx = fmaxf(mx, accs[ni][2 * h + 1]);
            }
            mx = fmaxf(mx, __shfl_xor_sync(0xFFFFFFFFu, mx, 1));
            mx = fmaxf(mx, __shfl_xor_sync(0xFFFFFFFFu, mx, 2));
            float mnew = fmaxf(m_r[h], mx);
            float corr = __expf(m_r[h] - mnew);
            m_r[h] = mnew;
            float sum = 0.f;
#pragma unroll
            for (int ni = 0; ni < 16; ni++) {
                float p0 = __expf(accs[ni][2 * h] - mnew);
                float p1 = __expf(accs[ni][2 * h + 1] - mnew);
                accs[ni][2 * h] = p0;
                accs[ni][2 * h + 1] = p1;
                sum += p0 + p1;
            }
            sum += __shfl_xor_sync(0xFFFFFFFFu, sum, 1);
            sum += __shfl_xor_sync(0xFFFFFFFFu, sum, 2);
            l_r[h] = l_r[h] * corr + sum;
#pragma unroll
            for (int ni = 0; ni < 8; ni++) {
                acco[ni][2 * h] *= corr;
                acco[ni][2 * h + 1] *= corr;
            }
        }

#pragma unroll
        for (int ni = 0; ni < 16; ni++) {
            int cc = ni * 8 + fc * 2;
            *(__half2*)(Pw + fr * PSH + cc) = __floats2half2_rn(accs[ni][0], accs[ni][1]);
            *(__half2*)(Pw + (fr + 8) * PSH + cc) = __floats2half2_rn(accs[ni][2], accs[ni][3]);
        }

        __syncthreads();
        if (more) {
            int sn = s0 + 128;
#pragma unroll
            for (int i = 0; i < 4; i++) {
                int idx = tid + (i << 8);
                int j = idx >> 3, ch = idx & 7;
                cpa16(ks_u + (uint32_t)(j * QSH * 2 + ch * 16),
                      kbase + (size_t)(sn + j) * (Gn * Kn) + ch * 8);
            }
            CP_COMMIT;
            CP_WAIT1;
        } else {
            CP_WAIT0;
        }
        __syncthreads();

#pragma unroll
        for (int k2 = 0; k2 < 8; k2++) {
            uint32_t af[4];
            LDSM_X4(af[0], af[1], af[2], af[3], pAddr + k2 * 32);
#pragma unroll
            for (int p = 0; p < 4; p++) {
                uint32_t b00, b01, b10, b11;
                LDSM_X4(b00, b01, b10, b11, vAddr + p * 16 * 272 + k2 * 32);
                MMA_F16(acco[2 * p], af[0], af[1], af[2], af[3], b00, b01);
                MMA_F16(acco[2 * p + 1], af[0], af[1], af[2], af[3], b10, b11);
            }
        }
        __syncthreads();

        if (more) {
            int sn = s0 + 128;
#pragma unroll
            for (int i = 0; i < 4; i++) {
                int idx = tid + (i << 8);
                int d = idx >> 4, ch = idx & 15;
                cpa16(vs_u + (uint32_t)(d * VTH * 2 + ch * 16),
                      vtbase + (size_t)d * Tn + sn + ch * 8);
            }
            CP_COMMIT;
            CP_WAIT1;
            __syncthreads();
        }
    }

#pragma unroll
    for (int h = 0; h < 2; h++) {
        float inv = 1.f / l_r[h];
        int row = r0 + 8 * h;
        int tt = t0 + (row >> 2);
        int hh = g * Rn + (row & 3);
        __half* op = out + ((size_t)((size_t)b * Tn + tt) * Hn + hh) * Kn;
#pragma unroll
        for (int ni = 0; ni < 8; ni++) {
            int col = ni * 8 + fc * 2;
            *(__half2*)(op + col) =
                __floats2half2_rn(acco[ni][2 * h] * inv, acco[ni][2 * h + 1] * inv);
        }
    }
}

// ---- merged: attention (512 blocks) + gate/up/down weight transposes (3072) ----
__global__ __launch_bounds__(256, 2) void attn_trans_k(
    const __half* __restrict__ q16, const __half* __restrict__ k16,
    const __half* __restrict__ vt, __half* __restrict__ attn,
    const float* __restrict__ gate_w, const float* __restrict__ up_w,
    const float* __restrict__ down_w,
    __half* __restrict__ tg, __half* __restrict__ tu, __half* __restrict__ td) {
    extern __shared__ char smraw[];
    int b = blockIdx.x;
    if (b < 512) {
        flashattn_body(q16, k16, vt, attn, b & 63, b >> 6, 64, (__half*)smraw);
        return;
    }
    int b2 = b - 512;
    float (*t)[65] = (float(*)[65])smraw;
    const float* W; __half* Wt; int K, N, base;
    if (b2 < 1024)      { W = gate_w; Wt = tg; K = 1024; N = 4096; base = 0; }
    else if (b2 < 2048) { W = up_w;   Wt = tu; K = 1024; N = 4096; base = 1024; }
    else                { W = down_w; Wt = td; K = 4096; N = 1024; base = 2048; }
    int local = b2 - base;
    int nb = N >> 6;
    trans_tile(W, Wt, K, N, local % nb, local / nb, t);
}

// ---------------- launch ----------------
static void hgemm(const __half* A, const __half* Wt, const void* aux, void* C,
                  int M, int N, int Kd, int mode, int ohalf) {
    dim3 grid(N / 128, M / 128);
    hgemm_k<<<grid, 256, HG_SMEM>>>(A, Wt, aux, C, N, Kd, mode, ohalf);
}

extern "C" void kernel_launch(void* const* d_in, const int* in_sizes, int n_in,
                              void* d_out, int out_size) {
    const float* hidden = (const float*)d_in[0];
    const float* sinp   = (const float*)d_in[1];
    const float* cosp   = (const float*)d_in[2];
    /* d_in[3] = mask (exact causal tril; applied analytically) */
    const float* ln1    = (const float*)d_in[4];
    const float* ln2    = (const float*)d_in[5];
    const float* qn     = (const float*)d_in[6];
    const float* kn     = (const float*)d_in[7];
    const float* q_w    = (const float*)d_in[8];
    const float* k_w    = (const float*)d_in[9];
    const float* v_w    = (const float*)d_in[10];
    const float* o_w    = (const float*)d_in[11];
    const float* gate_w = (const float*)d_in[12];
    const float* up_w   = (const float*)d_in[13];
    const float* down_w = (const float*)d_in[14];
    float* out = (float*)d_out;

    cudaFuncSetAttribute(hgemm_k, cudaFuncAttributeMaxDynamicSharedMemorySize, HG_SMEM);
    cudaFuncSetAttribute(qkv_trans_k, cudaFuncAttributeMaxDynamicSharedMemorySize, HG_SMEM);
    cudaFuncSetAttribute(gateup_k, cudaFuncAttributeMaxDynamicSharedMemorySize, HG_SMEM);
    cudaFuncSetAttribute(attn_trans_k, cudaFuncAttributeMaxDynamicSharedMemorySize, ATT_SMEM);

    __half *x, *qp, *kp, *v16, *q16, *k16, *vt, *attn, *y, *gate16, *up16, *ff;
    float *h2;
    __half *tq, *tk, *tv, *to, *tg, *tu, *td;
    cudaGetSymbolAddress((void**)&x, g_x);
    cudaGetSymbolAddress((void**)&qp, g_qp);
    cudaGetSymbolAddress((void**)&kp, g_kp);
    cudaGetSymbolAddress((void**)&v16, g_v16);
    cudaGetSymbolAddress((void**)&q16, g_q16);
    cudaGetSymbolAddress((void**)&k16, g_k16);
    cudaGetSymbolAddress((void**)&vt, g_vt);
    cudaGetSymbolAddress((void**)&attn, g_attn);
    cudaGetSymbolAddress((void**)&h2, g_h2);
    cudaGetSymbolAddress((void**)&y, g_y);
    cudaGetSymbolAddress((void**)&gate16, g_gate16);
    cudaGetSymbolAddress((void**)&up16, g_up16);
    cudaGetSymbolAddress((void**)&ff, g_ff);
    cudaGetSymbolAddress((void**)&tq, g_wt_q);
    cudaGetSymbolAddress((void**)&tk, g_wt_k);
    cudaGetSymbolAddress((void**)&tv, g_wt_v);
    cudaGetSymbolAddress((void**)&to, g_wt_o);
    cudaGetSymbolAddress((void**)&tg, g_wt_gate);
    cudaGetSymbolAddress((void**)&tu, g_wt_up);
    cudaGetSymbolAddress((void**)&td, g_wt_down);

    const int M = Mrows;

    // 1. rmsnorm(ln1) + q/k/v weight transposes
    pre_k<<<Mrows + 384, 256>>>(hidden, ln1, x, q_w, k_w, v_w, tq, tk, tv);

    // 2. qkv GEMM + o_w transpose
    qkv_trans_k<<<384 + 256, 256, HG_SMEM>>>(x, tq, tk, tv, qp, kp, v16, o_w, to);

    // 3. head norm+rope (q,k) + V^T (one launch)
    norm_vt_k<<<NR_BLOCKS + 1024, 256>>>(qp, q16, kp, k16, qn, kn, sinp, cosp, v16, vt);

    // 4. attention + gate/up/down weight transposes (tail-filled)
    attn_trans_k<<<512 + 3072, 256, ATT_SMEM>>>(q16, k16, vt, attn,
                                                gate_w, up_w, down_w, tg, tu, td);

    // 5. h2 = hidden + attn @ o_w
    hgemm(attn, to, hidden, h2, M, Dn, Hn * Kn, 1, 0);

    // 6. y = rmsnorm(h2)
    rmsnorm_k<<<M, 256>>>(h2, ln2, y);

    // 7. gate & up GEMMs
    gateup_k<<<2048, 256, HG_SMEM>>>(y, tg, tu, gate16, up16);

    // 8. ff = silu(gate) * up
    silu_mul_k<<<(M * Fn / 8 + 255) / 256, 256>>>(gate16, up16, ff);

    // 9. out = h2 + ff @ down_w
    hgemm(ff, td, h2, out, M, Dn, Fn, 1, 0);
}

// round 15
// speedup vs baseline: 2.1723x; 1.0105x over previous
#include <cuda_runtime.h>
#include <cuda_fp16.h>
#include <math.h>
#include <stdint.h>

#define Bn 2
#define Tn 2048
#define Dn 1024
#define Hn 16
#define Gn 4
#define Kn 64
#define Rn (Hn / Gn)
#define Fn 4096
#define EPSF 1e-6f
#define Mrows (Bn * Tn)

// ---------------- scratch ----------------
__device__ __half g_x[Mrows * Dn];
__device__ __half g_qp[Mrows * Hn * Kn];
__device__ __half g_kp[Mrows * Gn * Kn];
__device__ __half g_v16[Mrows * Gn * Kn];
__device__ __half g_q16[Mrows * Hn * Kn];
__device__ __half g_k16[Mrows * Gn * Kn];
__device__ __half g_vt[Bn * Gn * Kn * Tn];
__device__ __half g_attn[Mrows * Hn * Kn];
__device__ float  g_h2[Mrows * Dn];
__device__ __half g_y[Mrows * Dn];
__device__ __half g_gate16[Mrows * Fn];
__device__ __half g_up16[Mrows * Fn];
__device__ __half g_ff[Mrows * Fn];
__device__ __half g_wt_q[1024 * 1024];
__device__ __half g_wt_k[256 * 1024];
__device__ __half g_wt_v[256 * 1024];
__device__ __half g_wt_o[1024 * 1024];
__device__ __half g_wt_gate[4096 * 1024];
__device__ __half g_wt_up[4096 * 1024];
__device__ __half g_wt_down[1024 * 4096];

// ---------------- helpers ----------------
__device__ __forceinline__ uint32_t smem_u32(const void* p) {
    return (uint32_t)__cvta_generic_to_shared(p);
}
__device__ __forceinline__ void cpa16(uint32_t dst, const void* src) {
    asm volatile("cp.async.cg.shared.global [%0], [%1], 16;" ::"r"(dst), "l"(src));
}
#define CP_COMMIT asm volatile("cp.async.commit_group;")
#define CP_WAIT0 asm volatile("cp.async.wait_group 0;")
#define CP_WAIT1 asm volatile("cp.async.wait_group 1;")
#define CP_WAIT2 asm volatile("cp.async.wait_group 2;")

#define MMA_F16(d, a0, a1, a2, a3, b0, b1)                                    \
    asm volatile(                                                             \
        "mma.sync.aligned.m16n8k16.row.col.f32.f16.f16.f32 "                  \
        "{%0,%1,%2,%3}, {%4,%5,%6,%7}, {%8,%9}, {%0,%1,%2,%3};"               \
        : "+f"(d[0]), "+f"(d[1]), "+f"(d[2]), "+f"(d[3])                      \
        : "r"(a0), "r"(a1), "r"(a2), "r"(a3), "r"(b0), "r"(b1))

#define LDSM_X4(r0, r1, r2, r3, addr)                                         \
    asm volatile("ldmatrix.sync.aligned.m8n8.x4.shared.b16 {%0,%1,%2,%3}, [%4];" \
                 : "=r"(r0), "=r"(r1), "=r"(r2), "=r"(r3) : "r"(addr))

__device__ __forceinline__ uint32_t pack_h2(float a, float b) {
    __half2 h = __floats2half2_rn(a, b);
    return *reinterpret_cast<uint32_t*>(&h);
}

// ---------------- 64x64 transpose tile helper ----------------
__device__ __forceinline__ void trans_tile(const float* W, __half* Wt, int K, int N,
                                           int bx, int by, float (*t)[65]) {
    {
        int x = threadIdx.x & 63, y = threadIdx.x >> 6;
#pragma unroll
        for (int j = 0; j < 16; j++)
            t[y + j * 4][x] = W[(size_t)(by * 64 + y + j * 4) * N + bx * 64 + x];
    }
    __syncthreads();
    {
        int x = threadIdx.x & 31, y = threadIdx.x >> 5;
#pragma unroll
        for (int j = 0; j < 8; j++) {
            int n = y + j * 8;
            __half2 v = __floats2half2_rn(t[2 * x][n], t[2 * x + 1][n]);
            *(__half2*)(Wt + (size_t)(bx * 64 + n) * K + by * 64 + 2 * x) = v;
        }
    }
}

// ---------------- RMSNorm body ----------------
__device__ __forceinline__ void rmsnorm_body(const float* __restrict__ in,
                                             const float* __restrict__ sc,
                                             __half* __restrict__ out, int row,
                                             float* sm) {
    const float4* x4 = (const float4*)(in + (size_t)row * Dn);
    float4 v = x4[threadIdx.x];
    float ss = v.x * v.x + v.y * v.y + v.z * v.z + v.w * v.w;
    for (int o = 16; o; o >>= 1) ss += __shfl_xor_sync(0xFFFFFFFFu, ss, o);
    int w = threadIdx.x >> 5;
    if ((threadIdx.x & 31) == 0) sm[w] = ss;
    __syncthreads();
    if (threadIdx.x == 0) {
        float tot = 0.f;
        for (int i = 0; i < 8; i++) tot += sm[i];
        sm[0] = tot;
    }
    __syncthreads();
    float inv = rsqrtf(sm[0] / (float)Dn + EPSF);
    float4 s4 = ((const float4*)sc)[threadIdx.x];
    __half2* o2 = (__half2*)(out + (size_t)row * Dn) + threadIdx.x * 2;
    o2[0] = __floats2half2_rn(v.x * inv * s4.x, v.y * inv * s4.y);
    o2[1] = __floats2half2_rn(v.z * inv * s4.z, v.w * inv * s4.w);
}

// ---------------- pre: rmsnorm(ln1) + q/k/v weight transposes ----------------
__global__ __launch_bounds__(256) void pre_k(
    const float* __restrict__ hidden, const float* __restrict__ ln1,
    __half* __restrict__ x,
    const float* __restrict__ q_w, const float* __restrict__ k_w,
    const float* __restrict__ v_w,
    __half* __restrict__ tq, __half* __restrict__ tk, __half* __restrict__ tv) {
    __shared__ float t[64][65];
    int b = blockIdx.x;
    if (b < Mrows) {
        rmsnorm_body(hidden, ln1, x, b, &t[0][0]);
        return;
    }
    int b2 = b - Mrows;
    const float* W; __half* Wt; int K, N, base;
    if (b2 < 256)      { W = q_w; Wt = tq; K = 1024; N = 1024; base = 0; }
    else if (b2 < 320) { W = k_w; Wt = tk; K = 1024; N = 256;  base = 256; }
    else               { W = v_w; Wt = tv; K = 1024; N = 256;  base = 320; }
    int local = b2 - base;
    int nb = N >> 6;
    trans_tile(W, Wt, K, N, local % nb, local / nb, t);
}

// ---------------- standalone RMSNorm (ln2) ----------------
__global__ void rmsnorm_k(const float* __restrict__ in, const float* __restrict__ sc,
                          __half* __restrict__ out) {
    __shared__ float sm[8];
    rmsnorm_body(in, sc, out, blockIdx.x, sm);
}

// ---------------- merged: per-head norm+rope (q,k) + V transpose ----------------
#define QWARPS (Bn * Tn * Hn)
#define KWARPS (Bn * Tn * Gn)
#define NR_BLOCKS ((QWARPS + KWARPS) / 8)
__global__ void norm_vt_k(const __half* __restrict__ qp, __half* __restrict__ q16,
                          const __half* __restrict__ kp, __half* __restrict__ k16,
                          const float* __restrict__ qscale, const float* __restrict__ kscale,
                          const float* __restrict__ sinp, const float* __restrict__ cosp,
                          const __half* __restrict__ v16, __half* __restrict__ vt) {
    __shared__ __half t[32][33];
    int b = blockIdx.x;
    if (b >= NR_BLOCKS) {
        int b2 = b - NR_BLOCKS;
        int xb = b2 & 63, yb = (b2 >> 6) & 1, bg = b2 >> 7;
        int bb = bg >> 2, g = bg & 3;
        int t0 = xb * 32, d0 = yb * 32;
        int x = threadIdx.x & 31, y = threadIdx.x >> 5;
#pragma unroll
        for (int j = 0; j < 4; j++) {
            int tt = t0 + y + j * 8;
            t[y + j * 8][x] = v16[((size_t)((size_t)bb * Tn + tt) * Gn + g) * Kn + d0 + x];
        }
        __syncthreads();
#pragma unroll
        for (int j = 0; j < 4; j++) {
            int dd = d0 + y + j * 8;
            vt[((size_t)bg * Kn + dd) * Tn + t0 + x] = t[x][y + j * 8];
        }
        return;
    }
    int gw = b * 8 + (threadIdx.x >> 5);
    int lane = threadIdx.x & 31;
    const __half* src; __half* dst; const float* nscale; int bt;
    if (gw < QWARPS) {
        src = qp + (size_t)gw * Kn;
        dst = q16 + (size_t)gw * Kn;
        nscale = qscale;
        bt = gw / Hn;
    } else {
        int g2 = gw - QWARPS;
        src = kp + (size_t)g2 * Kn;
        dst = k16 + (size_t)g2 * Kn;
        nscale = kscale;
        bt = g2 / Gn;
    }
    float x1 = __half2float(src[lane]);
    float x2 = __half2float(src[lane + 32]);
    float ss = x1 * x1 + x2 * x2;
    for (int o = 16; o; o >>= 1) ss += __shfl_xor_sync(0xFFFFFFFFu, ss, o);
    float inv = rsqrtf(ss / (float)Kn + EPSF);
    x1 = x1 * inv * nscale[lane];
    x2 = x2 * inv * nscale[lane + 32];
    float s = sinp[bt * (Kn / 2) + lane];
    float c = cosp[bt * (Kn / 2) + lane];
    dst[lane]      = __float2half(x1 * c - x2 * s);
    dst[lane + 32] = __float2half(x2 * c + x1 * s);
}

// ============================================================
// FP16 GEMM core (ldmatrix, single-sync 4-stage cp.async)
// ============================================================
#define HAS 40
#define HG_STAGE 10240
#define HSTG 4
#define HG_SMEM (2 * HSTG * HG_STAGE)

__device__ __forceinline__ void hgemm_issue(uint32_t aB, uint32_t bB, int s,
                                            const __half* Arow, const __half* Brow,
                                            int k0, int Kd) {
    int tid = threadIdx.x;
#pragma unroll
    for (int j = 0; j < 2; j++) {
        int idx = tid + j * 256;
        int row = idx >> 2, ch = idx & 3;
        uint32_t dst = (uint32_t)(row * (HAS * 2) + ch * 16);
        cpa16(aB + s * HG_STAGE + dst, Arow + (size_t)row * Kd + k0 + ch * 8);
        cpa16(bB + s * HG_STAGE + dst, Brow + (size_t)row * Kd + k0 + ch * 8);
    }
}

__device__ __forceinline__ void hgemm_compute(uint32_t aAddr, uint32_t bAddr,
                                              float acc[4][4][4]) {
#pragma unroll
    for (int k2 = 0; k2 < 2; k2++) {
        uint32_t af[4][4], bf[4][2];
#pragma unroll
        for (int mi = 0; mi < 4; mi++)
            LDSM_X4(af[mi][0], af[mi][1], af[mi][2], af[mi][3],
                    aAddr + mi * 16 * 80 + k2 * 32);
#pragma unroll
        for (int p = 0; p < 2; p++)
            LDSM_X4(bf[2 * p][0], bf[2 * p][1], bf[2 * p + 1][0], bf[2 * p + 1][1],
                    bAddr + p * 16 * 80 + k2 * 32);
#pragma unroll
        for (int mi = 0; mi < 4; mi++)
#pragma unroll
            for (int ni = 0; ni < 4; ni++)
                MMA_F16(acc[mi][ni], af[mi][0], af[mi][1], af[mi][2], af[mi][3],
                        bf[ni][0], bf[ni][1]);
    }
}

__device__ __forceinline__ void hgemm_body(const __half* A, const __half* Wt,
                                           const void* aux, void* Cv,
                                           int N, int Kd, int bx, int by,
                                           int mode, int ohalf, char* smn) {
    uint32_t aB = smem_u32(smn);
    uint32_t bB = aB + HSTG * HG_STAGE;
    int tid = threadIdx.x;
    int lane = tid & 31, wid = tid >> 5;
    int wm = wid >> 2, wn = wid & 3;
    int fr = lane >> 2, fc = lane & 3;

    int rA = (lane & 7) + ((lane >> 3) & 1) * 8;
    int cA = (lane >> 4) * 8;
    uint32_t aOff = (uint32_t)((wm * 64 + rA) * 80 + cA * 2);
    int rB = (lane & 7) + (lane >> 4) * 8;
    int cB = ((lane >> 3) & 1) * 8;
    uint32_t bOff = (uint32_t)((wn * 32 + rB) * 80 + cB * 2);

    const __half* Arow = A + (size_t)(by * 128) * Kd;
    const __half* Brow = Wt + (size_t)(bx * 128) * Kd;

    float acc[4][4][4];
#pragma unroll
    for (int mi = 0; mi < 4; mi++)
#pragma unroll
        for (int ni = 0; ni < 4; ni++)
#pragma unroll
            for (int c = 0; c < 4; c++) acc[mi][ni][c] = 0.f;

    int nk = Kd / 32;
    hgemm_issue(aB, bB, 0, Arow, Brow, 0, Kd); CP_COMMIT;
    hgemm_issue(aB, bB, 1, Arow, Brow, 32, Kd); CP_COMMIT;
    hgemm_issue(aB, bB, 2, Arow, Brow, 64, Kd); CP_COMMIT;

    for (int i = 0; i < nk; i++) {
        if (i + 3 <= nk) { CP_WAIT2; }
        else if (i + 2 == nk) { CP_WAIT1; }
        else { CP_WAIT0; }
        __syncthreads();
        if (i + 3 < nk) {
            hgemm_issue(aB, bB, (i + 3) % HSTG, Arow, Brow, (i + 3) * 32, Kd);
            CP_COMMIT;
        }
        int s = i % HSTG;
        hgemm_compute(aB + s * HG_STAGE + aOff, bB + s * HG_STAGE + bOff, acc);
    }

#pragma unroll
    for (int mi = 0; mi < 4; mi++) {
#pragma unroll
        for (int ni = 0; ni < 4; ni++) {
            int row = by * 128 + wm * 64 + mi * 16 + fr;
            int col = bx * 128 + wn * 32 + ni * 8 + fc * 2;
            float2 r0 = make_float2(acc[mi][ni][0], acc[mi][ni][1]);
            float2 r1 = make_float2(acc[mi][ni][2], acc[mi][ni][3]);
            if (mode == 1) {
                const float* ap = (const float*)aux;
                float2 h0 = *(const float2*)(ap + (size_t)row * N + col);
                float2 h1 = *(const float2*)(ap + (size_t)(row + 8) * N + col);
                r0.x += h0.x; r0.y += h0.y;
                r1.x += h1.x; r1.y += h1.y;
            }
            if (ohalf) {
                __half* C = (__half*)Cv;
                *(__half2*)(C + (size_t)row * N + col) = __floats2half2_rn(r0.x, r0.y);
                *(__half2*)(C + (size_t)(row + 8) * N + col) = __floats2half2_rn(r1.x, r1.y);
            } else {
                float* C = (float*)Cv;
                *(float2*)(C + (size_t)row * N + col) = r0;
                *(float2*)(C + (size_t)(row + 8) * N + col) = r1;
            }
        }
    }
}

__global__ __launch_bounds__(256, 2) void hgemm_k(
    const __half* __restrict__ A, const __half* __restrict__ Wt,
    const void* __restrict__ aux, void* __restrict__ C,
    int N, int Kd, int mode, int ohalf) {
    extern __shared__ char smn[];
    hgemm_body(A, Wt, aux, C, N, Kd, blockIdx.x, blockIdx.y, mode, ohalf, smn);
}

// ---- merged: qkv GEMM (384) + o_w transpose (256) ----
__global__ __launch_bounds__(256, 2) void qkv_trans_k(
    const __half* __restrict__ A,
    const __half* __restrict__ Wtq, const __half* __restrict__ Wtk, const __half* __restrict__ Wtv,
    __half* __restrict__ Cq, __half* __restrict__ Ck, __half* __restrict__ Cv,
    const float* __restrict__ o_w, __half* __restrict__ to) {
    extern __shared__ char smn[];
    int b = blockIdx.x;
    if (b < 384) {
        int bx = b % 12, by = b / 12;
        const __half* Wt; __half* C; int N;
        if (bx < 8)       { Wt = Wtq; C = Cq; N = 1024; }
        else if (bx < 10) { Wt = Wtk; C = Ck; N = 256; bx -= 8; }
        else              { Wt = Wtv; C = Cv; N = 256; bx -= 10; }
        hgemm_body(A, Wt, (const void*)0, C, N, Dn, bx, by, 0, 1, smn);
        return;
    }
    int b2 = b - 384;
    float (*t)[65] = (float(*)[65])smn;
    trans_tile(o_w, to, 1024, 1024, b2 % 16, b2 / 16, t);
}

// ---- merged gate + up GEMM ----
__global__ __launch_bounds__(256, 2) void gateup_k(
    const __half* __restrict__ y,
    const __half* __restrict__ Wtg, const __half* __restrict__ Wtu,
    __half* __restrict__ gate16, __half* __restrict__ up16) {
    extern __shared__ char smn[];
    int b = blockIdx.x;
    if (b < 1024)
        hgemm_body(y, Wtg, (const void*)0, gate16, Fn, Dn, b % 32, b / 32, 0, 1, smn);
    else {
        b -= 1024;
        hgemm_body(y, Wtu, (const void*)0, up16, Fn, Dn, b % 32, b / 32, 0, 1, smn);
    }
}

// ---- ff = silu(gate16) * up16 ----
__global__ void silu_mul_k(const __half* __restrict__ gate16,
                           const __half* __restrict__ up16,
                           __half* __restrict__ ff) {
    int i = (blockIdx.x * blockDim.x + threadIdx.x) * 4;
    const __half2* g2 = (const __half2*)gate16 + i;
    const __half2* u2 = (const __half2*)up16 + i;
    __half2* f2 = (__half2*)ff + i;
#pragma unroll
    for (int j = 0; j < 4; j++) {
        __half2 gh = g2[j], uh = u2[j];
        float gx = __half2float(gh.x), gy = __half2float(gh.y);
        float ux = __half2float(uh.x), uy = __half2float(uh.y);
        f2[j] = __floats2half2_rn(gx / (1.f + __expf(-gx)) * ux,
                                  gy / (1.f + __expf(-gy)) * uy);
    }
}

// ============================================================
// Flash attention body: fp16 MMA, register-resident P (no P smem).
// ============================================================
#define QSH 72
#define VTH 136
#define ATT_SMEM ((128 * QSH + 128 * QSH + 64 * VTH) * 2)

__device__ __forceinline__ void flashattn_body(
    const __half* __restrict__ q16, const __half* __restrict__ k16,
    const __half* __restrict__ vt, __half* __restrict__ out,
    int bxi, int bg, int nbx, __half* smh) {
    __half* Qs = smh;
    __half* Ks = Qs + 128 * QSH;
    __half* Vs = Ks + 128 * QSH;
    uint32_t qs_u = smem_u32(Qs), ks_u = smem_u32(Ks), vs_u = smem_u32(Vs);

    int tid = threadIdx.x;
    int lane = tid & 31, wid = tid >> 5;
    int fr = lane >> 2, fc = lane & 3;

    int rA = (lane & 7) + ((lane >> 3) & 1) * 8;
    int cA = (lane >> 4) * 8;
    int rB = (lane & 7) + (lane >> 4) * 8;
    int cB = ((lane >> 3) & 1) * 8;
    uint32_t qAddr = qs_u + (uint32_t)((wid * 16 + rA) * 144 + cA * 2);
    uint32_t kAddr = ks_u + (uint32_t)(rB * 144 + cB * 2);
    uint32_t vAddr = vs_u + (uint32_t)(rB * 272 + cB * 2);

    int b = bg >> 2, g = bg & 3;
    int t0 = (nbx - 1 - bxi) * 32;
    int ntiles = (t0 >> 7) + 1;

    const __half* qbase = q16 + ((size_t)((size_t)b * Tn + t0) * Hn + g * Rn) * Kn;
    const __half* kbase = k16 + ((size_t)b * Tn * Gn + g) * Kn;
    const __half* vtbase = vt + (size_t)bg * Kn * Tn;

#pragma unroll
    for (int i = 0; i < 4; i++) {
        int idx = tid + (i << 8);
        int m = idx >> 3, ch = idx & 7;
        cpa16(qs_u + (uint32_t)(m * QSH * 2 + ch * 16),
              qbase + (size_t)(m >> 2) * (Hn * Kn) + (m & 3) * Kn + ch * 8);
    }
    CP_COMMIT;
#pragma unroll
    for (int i = 0; i < 4; i++) {
        int idx = tid + (i << 8);
        int j = idx >> 3, ch = idx & 7;
        cpa16(ks_u + (uint32_t)(j * QSH * 2 + ch * 16),
              kbase + (size_t)j * (Gn * Kn) + ch * 8);
    }
    CP_COMMIT;
#pragma unroll
    for (int i = 0; i < 4; i++) {
        int idx = tid + (i << 8);
        int d = idx >> 4, ch = idx & 15;
        cpa16(vs_u + (uint32_t)(d * VTH * 2 + ch * 16),
              vtbase + (size_t)d * Tn + 0 + ch * 8);
    }
    CP_COMMIT;
    CP_WAIT0;
    __syncthreads();

    float m_r[2], l_r[2], acco[8][4];
#pragma unroll
    for (int h = 0; h < 2; h++) { m_r[h] = -INFINITY; l_r[h] = 0.f; }
#pragma unroll
    for (int ni = 0; ni < 8; ni++)
#pragma unroll
        for (int c = 0; c < 4; c++) acco[ni][c] = 0.f;

    int r0 = wid * 16 + fr;

    for (int it = 0; it < ntiles; it++) {
        int s0 = it << 7;
        bool more = (it + 1 < ntiles);

        // ---- S = Q @ K^T ----
        float accs[16][4];
#pragma unroll
        for (int ni = 0; ni < 16; ni++)
#pragma unroll
            for (int c = 0; c < 4; c++) accs[ni][c] = 0.f;

#pragma unroll
        for (int k2 = 0; k2 < 4; k2++) {
            uint32_t af[4];
            LDSM_X4(af[0], af[1], af[2], af[3], qAddr + k2 * 32);
#pragma unroll
            for (int p = 0; p < 8; p++) {
                uint32_t b00, b01, b10, b11;
                LDSM_X4(b00, b01, b10, b11, kAddr + p * 16 * 144 + k2 * 32);
                MMA_F16(accs[2 * p], af[0], af[1], af[2], af[3], b00, b01);
                MMA_F16(accs[2 * p + 1], af[0], af[1], af[2], af[3], b10, b11);
            }
        }

#pragma unroll
        for (int ni = 0; ni < 16; ni++)
#pragma unroll
            for (int c = 0; c < 4; c++) accs[ni][c] *= 0.125f;
        if (it == ntiles - 1) {
#pragma unroll
            for (int ni = 0; ni < 16; ni++)
#pragma unroll
                for (int c = 0; c < 4; c++) {
                    int row = r0 + ((c >= 2) ? 8 : 0);
                    int tt = t0 + (row >> 2);
                    int ss = s0 + ni * 8 + fc * 2 + (c & 1);
                    if (ss > tt) accs[ni][c] = -1e30f;
                }
        }

        // ---- online softmax (P stays in accs) ----
#pragma unroll
        for (int h = 0; h < 2; h++) {
            float mx = -1e30f;
#pragma unroll
            for (int ni = 0; ni < 16; ni++) {
                mx = fmaxf(mx, accs[ni][2 * h]);
                mx = fmaxf(mx, accs[ni][2 * h + 1]);
            }
            mx = fmaxf(mx, __shfl_xor_sync(0xFFFFFFFFu, mx, 1));
            mx = fmaxf(mx, __shfl_xor_sync(0xFFFFFFFFu, mx, 2));
            float mnew = fmaxf(m_r[h], mx);
            float corr = __expf(m_r[h] - mnew);
            m_r[h] = mnew;
            float sum = 0.f;
#pragma unroll
            for (int ni = 0; ni < 16; ni++) {
                float p0 = __expf(accs[ni][2 * h] - mnew);
                float p1 = __expf(accs[ni][2 * h + 1] - mnew);
                accs[ni][2 * h] = p0;
                accs[ni][2 * h + 1] = p1;
                sum += p0 + p1;
            }
            sum += __shfl_xor_sync(0xFFFFFFFFu, sum, 1);
            sum += __shfl_xor_sync(0xFFFFFFFFu, sum, 2);
            l_r[h] = l_r[h] * corr + sum;
#pragma unroll
            for (int ni = 0; ni < 8; ni++) {
                acco[ni][2 * h] *= corr;
                acco[ni][2 * h + 1] *= corr;
            }
        }

        __syncthreads();  // all warps done reading Ks
        if (more) {
            int sn = s0 + 128;
#pragma unroll
            for (int i = 0; i < 4; i++) {
                int idx = tid + (i << 8);
                int j = idx >> 3, ch = idx & 7;
                cpa16(ks_u + (uint32_t)(j * QSH * 2 + ch * 16),
                      kbase + (size_t)(sn + j) * (Gn * Kn) + ch * 8);
            }
            CP_COMMIT;
            CP_WAIT1;  // V(it) complete
        } else {
            CP_WAIT0;
        }
        __syncthreads();

        // ---- O += P @ V : P packed from S accumulators (register-resident) ----
#pragma unroll
        for (int j = 0; j < 8; j++) {
            uint32_t af[4];
            af[0] = pack_h2(accs[2 * j][0], accs[2 * j][1]);
            af[1] = pack_h2(accs[2 * j][2], accs[2 * j][3]);
            af[2] = pack_h2(accs[2 * j + 1][0], accs[2 * j + 1][1]);
            af[3] = pack_h2(accs[2 * j + 1][2], accs[2 * j + 1][3]);
#pragma unroll
            for (int p = 0; p < 4; p++) {
                uint32_t b00, b01, b10, b11;
                LDSM_X4(b00, b01, b10, b11, vAddr + p * 16 * 272 + j * 32);
                MMA_F16(acco[2 * p], af[0], af[1], af[2], af[3], b00, b01);
                MMA_F16(acco[2 * p + 1], af[0], af[1], af[2], af[3], b10, b11);
            }
        }
        __syncthreads();  // all warps done reading Vs

        if (more) {
            int sn = s0 + 128;
#pragma unroll
            for (int i = 0; i < 4; i++) {
                int idx = tid + (i << 8);
                int d = idx >> 4, ch = idx & 15;
                cpa16(vs_u + (uint32_t)(d * VTH * 2 + ch * 16),
                      vtbase + (size_t)d * Tn + sn + ch * 8);
            }
            CP_COMMIT;
            CP_WAIT1;  // K(it+1) complete
            __syncthreads();
        }
    }

#pragma unroll
    for (int h = 0; h < 2; h++) {
        float inv = 1.f / l_r[h];
        int row = r0 + 8 * h;
        int tt = t0 + (row >> 2);
        int hh = g * Rn + (row & 3);
        __half* op = out + ((size_t)((size_t)b * Tn + tt) * Hn + hh) * Kn;
#pragma unroll
        for (int ni = 0; ni < 8; ni++) {
            int col = ni * 8 + fc * 2;
            *(__half2*)(op + col) =
                __floats2half2_rn(acco[ni][2 * h] * inv, acco[ni][2 * h + 1] * inv);
        }
    }
}

// ---- merged: attention (512 blocks) + gate/up/down weight transposes (3072) ----
__global__ __launch_bounds__(256, 2) void attn_trans_k(
    const __half* __restrict__ q16, const __half* __restrict__ k16,
    const __half* __restrict__ vt, __half* __restrict__ attn,
    const float* __restrict__ gate_w, const float* __restrict__ up_w,
    const float* __restrict__ down_w,
    __half* __restrict__ tg, __half* __restrict__ tu, __half* __restrict__ td) {
    extern __shared__ char smraw[];
    int b = blockIdx.x;
    if (b < 512) {
        flashattn_body(q16, k16, vt, attn, b & 63, b >> 6, 64, (__half*)smraw);
        return;
    }
    int b2 = b - 512;
    float (*t)[65] = (float(*)[65])smraw;
    const float* W; __half* Wt; int K, N, base;
    if (b2 < 1024)      { W = gate_w; Wt = tg; K = 1024; N = 4096; base = 0; }
    else if (b2 < 2048) { W = up_w;   Wt = tu; K = 1024; N = 4096; base = 1024; }
    else                { W = down_w; Wt = td; K = 4096; N = 1024; base = 2048; }
    int local = b2 - base;
    int nb = N >> 6;
    trans_tile(W, Wt, K, N, local % nb, local / nb, t);
}

// ---------------- launch ----------------
static void hgemm(const __half* A, const __half* Wt, const void* aux, void* C,
                  int M, int N, int Kd, int mode, int ohalf) {
    dim3 grid(N / 128, M / 128);
    hgemm_k<<<grid, 256, HG_SMEM>>>(A, Wt, aux, C, N, Kd, mode, ohalf);
}

extern "C" void kernel_launch(void* const* d_in, const int* in_sizes, int n_in,
                              void* d_out, int out_size) {
    const float* hidden = (const float*)d_in[0];
    const float* sinp   = (const float*)d_in[1];
    const float* cosp   = (const float*)d_in[2];
    /* d_in[3] = mask (exact causal tril; applied analytically) */
    const float* ln1    = (const float*)d_in[4];
    const float* ln2    = (const float*)d_in[5];
    const float* qn     = (const float*)d_in[6];
    const float* kn     = (const float*)d_in[7];
    const float* q_w    = (const float*)d_in[8];
    const float* k_w    = (const float*)d_in[9];
    const float* v_w    = (const float*)d_in[10];
    const float* o_w    = (const float*)d_in[11];
    const float* gate_w = (const float*)d_in[12];
    const float* up_w   = (const float*)d_in[13];
    const float* down_w = (const float*)d_in[14];
    float* out = (float*)d_out;

    cudaFuncSetAttribute(hgemm_k, cudaFuncAttributeMaxDynamicSharedMemorySize, HG_SMEM);
    cudaFuncSetAttribute(qkv_trans_k, cudaFuncAttributeMaxDynamicSharedMemorySize, HG_SMEM);
    cudaFuncSetAttribute(gateup_k, cudaFuncAttributeMaxDynamicSharedMemorySize, HG_SMEM);
    cudaFuncSetAttribute(attn_trans_k, cudaFuncAttributeMaxDynamicSharedMemorySize, ATT_SMEM);

    __half *x, *qp, *kp, *v16, *q16, *k16, *vt, *attn, *y, *gate16, *up16, *ff;
    float *h2;
    __half *tq, *tk, *tv, *to, *tg, *tu, *td;
    cudaGetSymbolAddress((void**)&x, g_x);
    cudaGetSymbolAddress((void**)&qp, g_qp);
    cudaGetSymbolAddress((void**)&kp, g_kp);
    cudaGetSymbolAddress((void**)&v16, g_v16);
    cudaGetSymbolAddress((void**)&q16, g_q16);
    cudaGetSymbolAddress((void**)&k16, g_k16);
    cudaGetSymbolAddress((void**)&vt, g_vt);
    cudaGetSymbolAddress((void**)&attn, g_attn);
    cudaGetSymbolAddress((void**)&h2, g_h2);
    cudaGetSymbolAddress((void**)&y, g_y);
    cudaGetSymbolAddress((void**)&gate16, g_gate16);
    cudaGetSymbolAddress((void**)&up16, g_up16);
    cudaGetSymbolAddress((void**)&ff, g_ff);
    cudaGetSymbolAddress((void**)&tq, g_wt_q);
    cudaGetSymbolAddress((void**)&tk, g_wt_k);
    cudaGetSymbolAddress((void**)&tv, g_wt_v);
    cudaGetSymbolAddress((void**)&to, g_wt_o);
    cudaGetSymbolAddress((void**)&tg, g_wt_gate);
    cudaGetSymbolAddress((void**)&tu, g_wt_up);
    cudaGetSymbolAddress((void**)&td, g_wt_down);

    const int M = Mrows;

    pre_k<<<Mrows + 384, 256>>>(hidden, ln1, x, q_w, k_w, v_w, tq, tk, tv);

    qkv_trans_k<<<384 + 256, 256, HG_SMEM>>>(x, tq, tk, tv, qp, kp, v16, o_w, to);

    norm_vt_k<<<NR_BLOCKS + 1024, 256>>>(qp, q16, kp, k16, qn, kn, sinp, cosp, v16, vt);

    attn_trans_k<<<512 + 3072, 256, ATT_SMEM>>>(q16, k16, vt, attn,
                                                gate_w, up_w, down_w, tg, tu, td);

    hgemm(attn, to, hidden, h2, M, Dn, Hn * Kn, 1, 0);

    rmsnorm_k<<<M, 256>>>(h2, ln2, y);

    gateup_k<<<2048, 256, HG_SMEM>>>(y, tg, tu, gate16, up16);

    silu_mul_k<<<(M * Fn / 8 + 255) / 256, 256>>>(gate16, up16, ff);

    hgemm(ff, td, h2, out, M, Dn, Fn, 1, 0);
}

// round 16
// speedup vs baseline: 2.2622x; 1.0414x over previous
#include <cuda_runtime.h>
#include <cuda_fp16.h>
#include <math.h>
#include <stdint.h>

#define Bn 2
#define Tn 2048
#define Dn 1024
#define Hn 16
#define Gn 4
#define Kn 64
#define Rn (Hn / Gn)
#define Fn 4096
#define EPSF 1e-6f
#define Mrows (Bn * Tn)

// ---------------- scratch ----------------
__device__ __half g_x[Mrows * Dn];
__device__ __half g_qp[Mrows * Hn * Kn];
__device__ __half g_kp[Mrows * Gn * Kn];
__device__ __half g_v16[Mrows * Gn * Kn];
__device__ __half g_q16[Mrows * Hn * Kn];
__device__ __half g_k16[Mrows * Gn * Kn];
__device__ __half g_vt[Bn * Gn * Kn * Tn];
__device__ __half g_attn[Mrows * Hn * Kn];
__device__ float  g_h2[Mrows * Dn];
__device__ __half g_y[Mrows * Dn];
__device__ __half g_ff[Mrows * Fn];
__device__ __half g_wt_q[1024 * 1024];
__device__ __half g_wt_k[256 * 1024];
__device__ __half g_wt_v[256 * 1024];
__device__ __half g_wt_o[1024 * 1024];
__device__ __half g_wt_gate[4096 * 1024];
__device__ __half g_wt_up[4096 * 1024];
__device__ __half g_wt_down[1024 * 4096];

// ---------------- helpers ----------------
__device__ __forceinline__ uint32_t smem_u32(const void* p) {
    return (uint32_t)__cvta_generic_to_shared(p);
}
__device__ __forceinline__ void cpa16(uint32_t dst, const void* src) {
    asm volatile("cp.async.cg.shared.global [%0], [%1], 16;" ::"r"(dst), "l"(src));
}
#define CP_COMMIT asm volatile("cp.async.commit_group;")
#define CP_WAIT0 asm volatile("cp.async.wait_group 0;")
#define CP_WAIT1 asm volatile("cp.async.wait_group 1;")
#define CP_WAIT2 asm volatile("cp.async.wait_group 2;")

#define MMA_F16(d, a0, a1, a2, a3, b0, b1)                                    \
    asm volatile(                                                             \
        "mma.sync.aligned.m16n8k16.row.col.f32.f16.f16.f32 "                  \
        "{%0,%1,%2,%3}, {%4,%5,%6,%7}, {%8,%9}, {%0,%1,%2,%3};"               \
        : "+f"(d[0]), "+f"(d[1]), "+f"(d[2]), "+f"(d[3])                      \
        : "r"(a0), "r"(a1), "r"(a2), "r"(a3), "r"(b0), "r"(b1))

#define LDSM_X4(r0, r1, r2, r3, addr)                                         \
    asm volatile("ldmatrix.sync.aligned.m8n8.x4.shared.b16 {%0,%1,%2,%3}, [%4];" \
                 : "=r"(r0), "=r"(r1), "=r"(r2), "=r"(r3) : "r"(addr))

__device__ __forceinline__ uint32_t pack_h2(float a, float b) {
    __half2 h = __floats2half2_rn(a, b);
    return *reinterpret_cast<uint32_t*>(&h);
}

// ---------------- 64x64 transpose tile helper ----------------
__device__ __forceinline__ void trans_tile(const float* W, __half* Wt, int K, int N,
                                           int bx, int by, float (*t)[65]) {
    {
        int x = threadIdx.x & 63, y = threadIdx.x >> 6;
#pragma unroll
        for (int j = 0; j < 16; j++)
            t[y + j * 4][x] = W[(size_t)(by * 64 + y + j * 4) * N + bx * 64 + x];
    }
    __syncthreads();
    {
        int x = threadIdx.x & 31, y = threadIdx.x >> 5;
#pragma unroll
        for (int j = 0; j < 8; j++) {
            int n = y + j * 8;
            __half2 v = __floats2half2_rn(t[2 * x][n], t[2 * x + 1][n]);
            *(__half2*)(Wt + (size_t)(bx * 64 + n) * K + by * 64 + 2 * x) = v;
        }
    }
}

// ---------------- RMSNorm body ----------------
__device__ __forceinline__ void rmsnorm_body(const float* __restrict__ in,
                                             const float* __restrict__ sc,
                                             __half* __restrict__ out, int row,
                                             float* sm) {
    const float4* x4 = (const float4*)(in + (size_t)row * Dn);
    float4 v = x4[threadIdx.x];
    float ss = v.x * v.x + v.y * v.y + v.z * v.z + v.w * v.w;
    for (int o = 16; o; o >>= 1) ss += __shfl_xor_sync(0xFFFFFFFFu, ss, o);
    int w = threadIdx.x >> 5;
    if ((threadIdx.x & 31) == 0) sm[w] = ss;
    __syncthreads();
    if (threadIdx.x == 0) {
        float tot = 0.f;
        for (int i = 0; i < 8; i++) tot += sm[i];
        sm[0] = tot;
    }
    __syncthreads();
    float inv = rsqrtf(sm[0] / (float)Dn + EPSF);
    float4 s4 = ((const float4*)sc)[threadIdx.x];
    __half2* o2 = (__half2*)(out + (size_t)row * Dn) + threadIdx.x * 2;
    o2[0] = __floats2half2_rn(v.x * inv * s4.x, v.y * inv * s4.y);
    o2[1] = __floats2half2_rn(v.z * inv * s4.z, v.w * inv * s4.w);
}

// ---------------- pre: rmsnorm(ln1) + q/k/v weight transposes ----------------
__global__ __launch_bounds__(256) void pre_k(
    const float* __restrict__ hidden, const float* __restrict__ ln1,
    __half* __restrict__ x,
    const float* __restrict__ q_w, const float* __restrict__ k_w,
    const float* __restrict__ v_w,
    __half* __restrict__ tq, __half* __restrict__ tk, __half* __restrict__ tv) {
    __shared__ float t[64][65];
    int b = blockIdx.x;
    if (b < Mrows) {
        rmsnorm_body(hidden, ln1, x, b, &t[0][0]);
        return;
    }
    int b2 = b - Mrows;
    const float* W; __half* Wt; int K, N, base;
    if (b2 < 256)      { W = q_w; Wt = tq; K = 1024; N = 1024; base = 0; }
    else if (b2 < 320) { W = k_w; Wt = tk; K = 1024; N = 256;  base = 256; }
    else               { W = v_w; Wt = tv; K = 1024; N = 256;  base = 320; }
    int local = b2 - base;
    int nb = N >> 6;
    trans_tile(W, Wt, K, N, local % nb, local / nb, t);
}

// ---------------- standalone RMSNorm (ln2) ----------------
__global__ void rmsnorm_k(const float* __restrict__ in, const float* __restrict__ sc,
                          __half* __restrict__ out) {
    __shared__ float sm[8];
    rmsnorm_body(in, sc, out, blockIdx.x, sm);
}

// ---------------- merged: per-head norm+rope (q,k) + V transpose ----------------
#define QWARPS (Bn * Tn * Hn)
#define KWARPS (Bn * Tn * Gn)
#define NR_BLOCKS ((QWARPS + KWARPS) / 8)
__global__ void norm_vt_k(const __half* __restrict__ qp, __half* __restrict__ q16,
                          const __half* __restrict__ kp, __half* __restrict__ k16,
                          const float* __restrict__ qscale, const float* __restrict__ kscale,
                          const float* __restrict__ sinp, const float* __restrict__ cosp,
                          const __half* __restrict__ v16, __half* __restrict__ vt) {
    __shared__ __half t[32][33];
    int b = blockIdx.x;
    if (b >= NR_BLOCKS) {
        int b2 = b - NR_BLOCKS;
        int xb = b2 & 63, yb = (b2 >> 6) & 1, bg = b2 >> 7;
        int bb = bg >> 2, g = bg & 3;
        int t0 = xb * 32, d0 = yb * 32;
        int x = threadIdx.x & 31, y = threadIdx.x >> 5;
#pragma unroll
        for (int j = 0; j < 4; j++) {
            int tt = t0 + y + j * 8;
            t[y + j * 8][x] = v16[((size_t)((size_t)bb * Tn + tt) * Gn + g) * Kn + d0 + x];
        }
        __syncthreads();
#pragma unroll
        for (int j = 0; j < 4; j++) {
            int dd = d0 + y + j * 8;
            vt[((size_t)bg * Kn + dd) * Tn + t0 + x] = t[x][y + j * 8];
        }
        return;
    }
    int gw = b * 8 + (threadIdx.x >> 5);
    int lane = threadIdx.x & 31;
    const __half* src; __half* dst; const float* nscale; int bt;
    if (gw < QWARPS) {
        src = qp + (size_t)gw * Kn;
        dst = q16 + (size_t)gw * Kn;
        nscale = qscale;
        bt = gw / Hn;
    } else {
        int g2 = gw - QWARPS;
        src = kp + (size_t)g2 * Kn;
        dst = k16 + (size_t)g2 * Kn;
        nscale = kscale;
        bt = g2 / Gn;
    }
    float x1 = __half2float(src[lane]);
    float x2 = __half2float(src[lane + 32]);
    float ss = x1 * x1 + x2 * x2;
    for (int o = 16; o; o >>= 1) ss += __shfl_xor_sync(0xFFFFFFFFu, ss, o);
    float inv = rsqrtf(ss / (float)Kn + EPSF);
    x1 = x1 * inv * nscale[lane];
    x2 = x2 * inv * nscale[lane + 32];
    float s = sinp[bt * (Kn / 2) + lane];
    float c = cosp[bt * (Kn / 2) + lane];
    dst[lane]      = __float2half(x1 * c - x2 * s);
    dst[lane + 32] = __float2half(x2 * c + x1 * s);
}

// ============================================================
// FP16 GEMM core (ldmatrix, single-sync 4-stage cp.async)
// ============================================================
#define HAS 40
#define HG_STAGE 10240
#define HSTG 4
#define HG_SMEM (2 * HSTG * HG_STAGE)

__device__ __forceinline__ void hgemm_issue(uint32_t aB, uint32_t bB, int s,
                                            const __half* Arow, const __half* Brow,
                                            int k0, int Kd) {
    int tid = threadIdx.x;
#pragma unroll
    for (int j = 0; j < 2; j++) {
        int idx = tid + j * 256;
        int row = idx >> 2, ch = idx & 3;
        uint32_t dst = (uint32_t)(row * (HAS * 2) + ch * 16);
        cpa16(aB + s * HG_STAGE + dst, Arow + (size_t)row * Kd + k0 + ch * 8);
        cpa16(bB + s * HG_STAGE + dst, Brow + (size_t)row * Kd + k0 + ch * 8);
    }
}

__device__ __forceinline__ void hgemm_compute(uint32_t aAddr, uint32_t bAddr,
                                              float acc[4][4][4]) {
#pragma unroll
    for (int k2 = 0; k2 < 2; k2++) {
        uint32_t af[4][4], bf[4][2];
#pragma unroll
        for (int mi = 0; mi < 4; mi++)
            LDSM_X4(af[mi][0], af[mi][1], af[mi][2], af[mi][3],
                    aAddr + mi * 16 * 80 + k2 * 32);
#pragma unroll
        for (int p = 0; p < 2; p++)
            LDSM_X4(bf[2 * p][0], bf[2 * p][1], bf[2 * p + 1][0], bf[2 * p + 1][1],
                    bAddr + p * 16 * 80 + k2 * 32);
#pragma unroll
        for (int mi = 0; mi < 4; mi++)
#pragma unroll
            for (int ni = 0; ni < 4; ni++)
                MMA_F16(acc[mi][ni], af[mi][0], af[mi][1], af[mi][2], af[mi][3],
                        bf[ni][0], bf[ni][1]);
    }
}

__device__ __forceinline__ void hgemm_body(const __half* A, const __half* Wt,
                                           const void* aux, void* Cv,
                                           int N, int Kd, int bx, int by,
                                           int mode, int ohalf, char* smn) {
    uint32_t aB = smem_u32(smn);
    uint32_t bB = aB + HSTG * HG_STAGE;
    int tid = threadIdx.x;
    int lane = tid & 31, wid = tid >> 5;
    int wm = wid >> 2, wn = wid & 3;
    int fr = lane >> 2, fc = lane & 3;

    int rA = (lane & 7) + ((lane >> 3) & 1) * 8;
    int cA = (lane >> 4) * 8;
    uint32_t aOff = (uint32_t)((wm * 64 + rA) * 80 + cA * 2);
    int rB = (lane & 7) + (lane >> 4) * 8;
    int cB = ((lane >> 3) & 1) * 8;
    uint32_t bOff = (uint32_t)((wn * 32 + rB) * 80 + cB * 2);

    const __half* Arow = A + (size_t)(by * 128) * Kd;
    const __half* Brow = Wt + (size_t)(bx * 128) * Kd;

    float acc[4][4][4];
#pragma unroll
    for (int mi = 0; mi < 4; mi++)
#pragma unroll
        for (int ni = 0; ni < 4; ni++)
#pragma unroll
            for (int c = 0; c < 4; c++) acc[mi][ni][c] = 0.f;

    int nk = Kd / 32;
    hgemm_issue(aB, bB, 0, Arow, Brow, 0, Kd); CP_COMMIT;
    hgemm_issue(aB, bB, 1, Arow, Brow, 32, Kd); CP_COMMIT;
    hgemm_issue(aB, bB, 2, Arow, Brow, 64, Kd); CP_COMMIT;

    for (int i = 0; i < nk; i++) {
        if (i + 3 <= nk) { CP_WAIT2; }
        else if (i + 2 == nk) { CP_WAIT1; }
        else { CP_WAIT0; }
        __syncthreads();
        if (i + 3 < nk) {
            hgemm_issue(aB, bB, (i + 3) % HSTG, Arow, Brow, (i + 3) * 32, Kd);
            CP_COMMIT;
        }
        int s = i % HSTG;
        hgemm_compute(aB + s * HG_STAGE + aOff, bB + s * HG_STAGE + bOff, acc);
    }

#pragma unroll
    for (int mi = 0; mi < 4; mi++) {
#pragma unroll
        for (int ni = 0; ni < 4; ni++) {
            int row = by * 128 + wm * 64 + mi * 16 + fr;
            int col = bx * 128 + wn * 32 + ni * 8 + fc * 2;
            float2 r0 = make_float2(acc[mi][ni][0], acc[mi][ni][1]);
            float2 r1 = make_float2(acc[mi][ni][2], acc[mi][ni][3]);
            if (mode == 1) {
                const float* ap = (const float*)aux;
                float2 h0 = *(const float2*)(ap + (size_t)row * N + col);
                float2 h1 = *(const float2*)(ap + (size_t)(row + 8) * N + col);
                r0.x += h0.x; r0.y += h0.y;
                r1.x += h1.x; r1.y += h1.y;
            }
            if (ohalf) {
                __half* C = (__half*)Cv;
                *(__half2*)(C + (size_t)row * N + col) = __floats2half2_rn(r0.x, r0.y);
                *(__half2*)(C + (size_t)(row + 8) * N + col) = __floats2half2_rn(r1.x, r1.y);
            } else {
                float* C = (float*)Cv;
                *(float2*)(C + (size_t)row * N + col) = r0;
                *(float2*)(C + (size_t)(row + 8) * N + col) = r1;
            }
        }
    }
}

__global__ __launch_bounds__(256, 2) void hgemm_k(
    const __half* __restrict__ A, const __half* __restrict__ Wt,
    const void* __restrict__ aux, void* __restrict__ C,
    int N, int Kd, int mode, int ohalf) {
    extern __shared__ char smn[];
    hgemm_body(A, Wt, aux, C, N, Kd, blockIdx.x, blockIdx.y, mode, ohalf, smn);
}

// ---- merged: qkv GEMM (384) + o_w transpose (256) ----
__global__ __launch_bounds__(256, 2) void qkv_trans_k(
    const __half* __restrict__ A,
    const __half* __restrict__ Wtq, const __half* __restrict__ Wtk, const __half* __restrict__ Wtv,
    __half* __restrict__ Cq, __half* __restrict__ Ck, __half* __restrict__ Cv,
    const float* __restrict__ o_w, __half* __restrict__ to) {
    extern __shared__ char smn[];
    int b = blockIdx.x;
    if (b < 384) {
        int bx = b % 12, by = b / 12;
        const __half* Wt; __half* C; int N;
        if (bx < 8)       { Wt = Wtq; C = Cq; N = 1024; }
        else if (bx < 10) { Wt = Wtk; C = Ck; N = 256; bx -= 8; }
        else              { Wt = Wtv; C = Cv; N = 256; bx -= 10; }
        hgemm_body(A, Wt, (const void*)0, C, N, Dn, bx, by, 0, 1, smn);
        return;
    }
    int b2 = b - 384;
    float (*t)[65] = (float(*)[65])smn;
    trans_tile(o_w, to, 1024, 1024, b2 % 16, b2 / 16, t);
}

// ============================================================
// Fused gate+up GEMM + silu: N-tile 64 per matrix, shared A pipeline.
// ff = silu(y@Wg) * (y@Wu), computed in fp32, written fp16.
// ============================================================
#define GU_STAGE 20480   // A 10240 + Bg 5120 + Bu 5120
#define GU_SMEM (HSTG * GU_STAGE)

__device__ __forceinline__ void gu_issue(uint32_t base, int s,
                                         const __half* Arow, const __half* Bg,
                                         const __half* Bu, int k0) {
    int tid = threadIdx.x;
    uint32_t st = base + s * GU_STAGE;
#pragma unroll
    for (int j = 0; j < 2; j++) {
        int idx = tid + j * 256;
        int row = idx >> 2, ch = idx & 3;
        cpa16(st + (uint32_t)(row * 80 + ch * 16), Arow + (size_t)row * Dn + k0 + ch * 8);
    }
    {
        int row = tid >> 2, ch = tid & 3;
        cpa16(st + 10240 + (uint32_t)(row * 80 + ch * 16), Bg + (size_t)row * Dn + k0 + ch * 8);
        cpa16(st + 15360 + (uint32_t)(row * 80 + ch * 16), Bu + (size_t)row * Dn + k0 + ch * 8);
    }
}

__global__ __launch_bounds__(256, 2) void gateup_fused_k(
    const __half* __restrict__ y,
    const __half* __restrict__ Wtg, const __half* __restrict__ Wtu,
    __half* __restrict__ ff) {
    extern __shared__ char smn[];
    uint32_t base = smem_u32(smn);
    int tid = threadIdx.x;
    int lane = tid & 31, wid = tid >> 5;
    int wm = wid >> 2, wn = wid & 3;
    int fr = lane >> 2, fc = lane & 3;
    int bx = blockIdx.x & 63, by = blockIdx.x >> 6;

    int rA = (lane & 7) + ((lane >> 3) & 1) * 8;
    int cA = (lane >> 4) * 8;
    uint32_t aOff = (uint32_t)((wm * 64 + rA) * 80 + cA * 2);
    int rB = (lane & 7) + (lane >> 4) * 8;
    int cB = ((lane >> 3) & 1) * 8;
    uint32_t bOff = (uint32_t)((wn * 16 + rB) * 80 + cB * 2);

    const __half* Arow = y + (size_t)(by * 128) * Dn;
    const __half* Bg = Wtg + (size_t)(bx * 64) * Dn;
    const __half* Bu = Wtu + (size_t)(bx * 64) * Dn;

    float ag[4][2][4], au[4][2][4];
#pragma unroll
    for (int mi = 0; mi < 4; mi++)
#pragma unroll
        for (int ni = 0; ni < 2; ni++)
#pragma unroll
            for (int c = 0; c < 4; c++) { ag[mi][ni][c] = 0.f; au[mi][ni][c] = 0.f; }

    int nk = Dn / 32;  // 32
    gu_issue(base, 0, Arow, Bg, Bu, 0); CP_COMMIT;
    gu_issue(base, 1, Arow, Bg, Bu, 32); CP_COMMIT;
    gu_issue(base, 2, Arow, Bg, Bu, 64); CP_COMMIT;

    for (int i = 0; i < nk; i++) {
        if (i + 3 <= nk) { CP_WAIT2; }
        else if (i + 2 == nk) { CP_WAIT1; }
        else { CP_WAIT0; }
        __syncthreads();
        if (i + 3 < nk) {
            gu_issue(base, (i + 3) % HSTG, Arow, Bg, Bu, (i + 3) * 32);
            CP_COMMIT;
        }
        uint32_t st = base + (i % HSTG) * GU_STAGE;
        uint32_t aAddr = st + aOff;
        uint32_t gAddr = st + 10240 + bOff;
        uint32_t uAddr = st + 15360 + bOff;
#pragma unroll
        for (int k2 = 0; k2 < 2; k2++) {
            uint32_t af[4][4];
#pragma unroll
            for (int mi = 0; mi < 4; mi++)
                LDSM_X4(af[mi][0], af[mi][1], af[mi][2], af[mi][3],
                        aAddr + mi * 16 * 80 + k2 * 32);
            uint32_t bg0, bg1, bg2, bg3, bu0, bu1, bu2, bu3;
            LDSM_X4(bg0, bg1, bg2, bg3, gAddr + k2 * 32);
            LDSM_X4(bu0, bu1, bu2, bu3, uAddr + k2 * 32);
#pragma unroll
            for (int mi = 0; mi < 4; mi++) {
                MMA_F16(ag[mi][0], af[mi][0], af[mi][1], af[mi][2], af[mi][3], bg0, bg1);
                MMA_F16(ag[mi][1], af[mi][0], af[mi][1], af[mi][2], af[mi][3], bg2, bg3);
                MMA_F16(au[mi][0], af[mi][0], af[mi][1], af[mi][2], af[mi][3], bu0, bu1);
                MMA_F16(au[mi][1], af[mi][0], af[mi][1], af[mi][2], af[mi][3], bu2, bu3);
            }
        }
    }

#pragma unroll
    for (int mi = 0; mi < 4; mi++) {
#pragma unroll
        for (int ni = 0; ni < 2; ni++) {
            int row = by * 128 + wm * 64 + mi * 16 + fr;
            int col = bx * 64 + wn * 16 + ni * 8 + fc * 2;
            float g0 = ag[mi][ni][0], g1 = ag[mi][ni][1];
            float g2 = ag[mi][ni][2], g3 = ag[mi][ni][3];
            float f0 = g0 / (1.f + __expf(-g0)) * au[mi][ni][0];
            float f1 = g1 / (1.f + __expf(-g1)) * au[mi][ni][1];
            float f2 = g2 / (1.f + __expf(-g2)) * au[mi][ni][2];
            float f3 = g3 / (1.f + __expf(-g3)) * au[mi][ni][3];
            *(__half2*)(ff + (size_t)row * Fn + col) = __floats2half2_rn(f0, f1);
            *(__half2*)(ff + (size_t)(row + 8) * Fn + col) = __floats2half2_rn(f2, f3);
        }
    }
}

// ============================================================
// Flash attention body: fp16 MMA, register-resident P.
// ============================================================
#define QSH 72
#define VTH 136
#define ATT_SMEM ((128 * QSH + 128 * QSH + 64 * VTH) * 2)

__device__ __forceinline__ void flashattn_body(
    const __half* __restrict__ q16, const __half* __restrict__ k16,
    const __half* __restrict__ vt, __half* __restrict__ out,
    int bxi, int bg, int nbx, __half* smh) {
    __half* Qs = smh;
    __half* Ks = Qs + 128 * QSH;
    __half* Vs = Ks + 128 * QSH;
    uint32_t qs_u = smem_u32(Qs), ks_u = smem_u32(Ks), vs_u = smem_u32(Vs);

    int tid = threadIdx.x;
    int lane = tid & 31, wid = tid >> 5;
    int fr = lane >> 2, fc = lane & 3;

    int rA = (lane & 7) + ((lane >> 3) & 1) * 8;
    int cA = (lane >> 4) * 8;
    int rB = (lane & 7) + (lane >> 4) * 8;
    int cB = ((lane >> 3) & 1) * 8;
    uint32_t qAddr = qs_u + (uint32_t)((wid * 16 + rA) * 144 + cA * 2);
    uint32_t kAddr = ks_u + (uint32_t)(rB * 144 + cB * 2);
    uint32_t vAddr = vs_u + (uint32_t)(rB * 272 + cB * 2);

    int b = bg >> 2, g = bg & 3;
    int t0 = (nbx - 1 - bxi) * 32;
    int ntiles = (t0 >> 7) + 1;

    const __half* qbase = q16 + ((size_t)((size_t)b * Tn + t0) * Hn + g * Rn) * Kn;
    const __half* kbase = k16 + ((size_t)b * Tn * Gn + g) * Kn;
    const __half* vtbase = vt + (size_t)bg * Kn * Tn;

#pragma unroll
    for (int i = 0; i < 4; i++) {
        int idx = tid + (i << 8);
        int m = idx >> 3, ch = idx & 7;
        cpa16(qs_u + (uint32_t)(m * QSH * 2 + ch * 16),
              qbase + (size_t)(m >> 2) * (Hn * Kn) + (m & 3) * Kn + ch * 8);
    }
    CP_COMMIT;
#pragma unroll
    for (int i = 0; i < 4; i++) {
        int idx = tid + (i << 8);
        int j = idx >> 3, ch = idx & 7;
        cpa16(ks_u + (uint32_t)(j * QSH * 2 + ch * 16),
              kbase + (size_t)j * (Gn * Kn) + ch * 8);
    }
    CP_COMMIT;
#pragma unroll
    for (int i = 0; i < 4; i++) {
        int idx = tid + (i << 8);
        int d = idx >> 4, ch = idx & 15;
        cpa16(vs_u + (uint32_t)(d * VTH * 2 + ch * 16),
              vtbase + (size_t)d * Tn + 0 + ch * 8);
    }
    CP_COMMIT;
    CP_WAIT0;
    __syncthreads();

    float m_r[2], l_r[2], acco[8][4];
#pragma unroll
    for (int h = 0; h < 2; h++) { m_r[h] = -INFINITY; l_r[h] = 0.f; }
#pragma unroll
    for (int ni = 0; ni < 8; ni++)
#pragma unroll
        for (int c = 0; c < 4; c++) acco[ni][c] = 0.f;

    int r0 = wid * 16 + fr;

    for (int it = 0; it < ntiles; it++) {
        int s0 = it << 7;
        bool more = (it + 1 < ntiles);

        float accs[16][4];
#pragma unroll
        for (int ni = 0; ni < 16; ni++)
#pragma unroll
            for (int c = 0; c < 4; c++) accs[ni][c] = 0.f;

#pragma unroll
        for (int k2 = 0; k2 < 4; k2++) {
            uint32_t af[4];
            LDSM_X4(af[0], af[1], af[2], af[3], qAddr + k2 * 32);
#pragma unroll
            for (int p = 0; p < 8; p++) {
                uint32_t b00, b01, b10, b11;
                LDSM_X4(b00, b01, b10, b11, kAddr + p * 16 * 144 + k2 * 32);
                MMA_F16(accs[2 * p], af[0], af[1], af[2], af[3], b00, b01);
                MMA_F16(accs[2 * p + 1], af[0], af[1], af[2], af[3], b10, b11);
            }
        }

#pragma unroll
        for (int ni = 0; ni < 16; ni++)
#pragma unroll
            for (int c = 0; c < 4; c++) accs[ni][c] *= 0.125f;
        if (it == ntiles - 1) {
#pragma unroll
            for (int ni = 0; ni < 16; ni++)
#pragma unroll
                for (int c = 0; c < 4; c++) {
                    int row = r0 + ((c >= 2) ? 8 : 0);
                    int tt = t0 + (row >> 2);
                    int ss = s0 + ni * 8 + fc * 2 + (c & 1);
                    if (ss > tt) accs[ni][c] = -1e30f;
                }
        }

#pragma unroll
        for (int h = 0; h < 2; h++) {
            float mx = -1e30f;
#pragma unroll
            for (int ni = 0; ni < 16; ni++) {
                mx = fmaxf(mx, accs[ni][2 * h]);
                mx = fmaxf(mx, accs[ni][2 * h + 1]);
            }
            mx = fmaxf(mx, __shfl_xor_sync(0xFFFFFFFFu, mx, 1));
            mx = fmaxf(mx, __shfl_xor_sync(0xFFFFFFFFu, mx, 2));
            float mnew = fmaxf(m_r[h], mx);
            float corr = __expf(m_r[h] - mnew);
            m_r[h] = mnew;
            float sum = 0.f;
#pragma unroll
            for (int ni = 0; ni < 16; ni++) {
                float p0 = __expf(accs[ni][2 * h] - mnew);
                float p1 = __expf(accs[ni][2 * h + 1] - mnew);
                accs[ni][2 * h] = p0;
                accs[ni][2 * h + 1] = p1;
                sum += p0 + p1;
            }
            sum += __shfl_xor_sync(0xFFFFFFFFu, sum, 1);
            sum += __shfl_xor_sync(0xFFFFFFFFu, sum, 2);
            l_r[h] = l_r[h] * corr + sum;
#pragma unroll
            for (int ni = 0; ni < 8; ni++) {
                acco[ni][2 * h] *= corr;
                acco[ni][2 * h + 1] *= corr;
            }
        }

        __syncthreads();
        if (more) {
            int sn = s0 + 128;
#pragma unroll
            for (int i = 0; i < 4; i++) {
                int idx = tid + (i << 8);
                int j = idx >> 3, ch = idx & 7;
                cpa16(ks_u + (uint32_t)(j * QSH * 2 + ch * 16),
                      kbase + (size_t)(sn + j) * (Gn * Kn) + ch * 8);
            }
            CP_COMMIT;
            CP_WAIT1;
        } else {
            CP_WAIT0;
        }
        __syncthreads();

#pragma unroll
        for (int j = 0; j < 8; j++) {
            uint32_t af[4];
            af[0] = pack_h2(accs[2 * j][0], accs[2 * j][1]);
            af[1] = pack_h2(accs[2 * j][2], accs[2 * j][3]);
            af[2] = pack_h2(accs[2 * j + 1][0], accs[2 * j + 1][1]);
            af[3] = pack_h2(accs[2 * j + 1][2], accs[2 * j + 1][3]);
#pragma unroll
            for (int p = 0; p < 4; p++) {
                uint32_t b00, b01, b10, b11;
                LDSM_X4(b00, b01, b10, b11, vAddr + p * 16 * 272 + j * 32);
                MMA_F16(acco[2 * p], af[0], af[1], af[2], af[3], b00, b01);
                MMA_F16(acco[2 * p + 1], af[0], af[1], af[2], af[3], b10, b11);
            }
        }
        __syncthreads();

        if (more) {
            int sn = s0 + 128;
#pragma unroll
            for (int i = 0; i < 4; i++) {
                int idx = tid + (i << 8);
                int d = idx >> 4, ch = idx & 15;
                cpa16(vs_u + (uint32_t)(d * VTH * 2 + ch * 16),
                      vtbase + (size_t)d * Tn + sn + ch * 8);
            }
            CP_COMMIT;
            CP_WAIT1;
            __syncthreads();
        }
    }

#pragma unroll
    for (int h = 0; h < 2; h++) {
        float inv = 1.f / l_r[h];
        int row = r0 + 8 * h;
        int tt = t0 + (row >> 2);
        int hh = g * Rn + (row & 3);
        __half* op = out + ((size_t)((size_t)b * Tn + tt) * Hn + hh) * Kn;
#pragma unroll
        for (int ni = 0; ni < 8; ni++) {
            int col = ni * 8 + fc * 2;
            *(__half2*)(op + col) =
                __floats2half2_rn(acco[ni][2 * h] * inv, acco[ni][2 * h + 1] * inv);
        }
    }
}

// ---- merged: attention (512) + gate/up/down weight transposes (3072) ----
__global__ __launch_bounds__(256, 2) void attn_trans_k(
    const __half* __restrict__ q16, const __half* __restrict__ k16,
    const __half* __restrict__ vt, __half* __restrict__ attn,
    const float* __restrict__ gate_w, const float* __restrict__ up_w,
    const float* __restrict__ down_w,
    __half* __restrict__ tg, __half* __restrict__ tu, __half* __restrict__ td) {
    extern __shared__ char smraw[];
    int b = blockIdx.x;
    if (b < 512) {
        flashattn_body(q16, k16, vt, attn, b & 63, b >> 6, 64, (__half*)smraw);
        return;
    }
    int b2 = b - 512;
    float (*t)[65] = (float(*)[65])smraw;
    const float* W; __half* Wt; int K, N, base;
    if (b2 < 1024)      { W = gate_w; Wt = tg; K = 1024; N = 4096; base = 0; }
    else if (b2 < 2048) { W = up_w;   Wt = tu; K = 1024; N = 4096; base = 1024; }
    else                { W = down_w; Wt = td; K = 4096; N = 1024; base = 2048; }
    int local = b2 - base;
    int nb = N >> 6;
    trans_tile(W, Wt, K, N, local % nb, local / nb, t);
}

// ---------------- launch ----------------
static void hgemm(const __half* A, const __half* Wt, const void* aux, void* C,
                  int M, int N, int Kd, int mode, int ohalf) {
    dim3 grid(N / 128, M / 128);
    hgemm_k<<<grid, 256, HG_SMEM>>>(A, Wt, aux, C, N, Kd, mode, ohalf);
}

extern "C" void kernel_launch(void* const* d_in, const int* in_sizes, int n_in,
                              void* d_out, int out_size) {
    const float* hidden = (const float*)d_in[0];
    const float* sinp   = (const float*)d_in[1];
    const float* cosp   = (const float*)d_in[2];
    /* d_in[3] = mask (exact causal tril; applied analytically) */
    const float* ln1    = (const float*)d_in[4];
    const float* ln2    = (const float*)d_in[5];
    const float* qn     = (const float*)d_in[6];
    const float* kn     = (const float*)d_in[7];
    const float* q_w    = (const float*)d_in[8];
    const float* k_w    = (const float*)d_in[9];
    const float* v_w    = (const float*)d_in[10];
    const float* o_w    = (const float*)d_in[11];
    const float* gate_w = (const float*)d_in[12];
    const float* up_w   = (const float*)d_in[13];
    const float* down_w = (const float*)d_in[14];
    float* out = (float*)d_out;

    cudaFuncSetAttribute(hgemm_k, cudaFuncAttributeMaxDynamicSharedMemorySize, HG_SMEM);
    cudaFuncSetAttribute(qkv_trans_k, cudaFuncAttributeMaxDynamicSharedMemorySize, HG_SMEM);
    cudaFuncSetAttribute(gateup_fused_k, cudaFuncAttributeMaxDynamicSharedMemorySize, GU_SMEM);
    cudaFuncSetAttribute(attn_trans_k, cudaFuncAttributeMaxDynamicSharedMemorySize, ATT_SMEM);

    __half *x, *qp, *kp, *v16, *q16, *k16, *vt, *attn, *y, *ff;
    float *h2;
    __half *tq, *tk, *tv, *to, *tg, *tu, *td;
    cudaGetSymbolAddress((void**)&x, g_x);
    cudaGetSymbolAddress((void**)&qp, g_qp);
    cudaGetSymbolAddress((void**)&kp, g_kp);
    cudaGetSymbolAddress((void**)&v16, g_v16);
    cudaGetSymbolAddress((void**)&q16, g_q16);
    cudaGetSymbolAddress((void**)&k16, g_k16);
    cudaGetSymbolAddress((void**)&vt, g_vt);
    cudaGetSymbolAddress((void**)&attn, g_attn);
    cudaGetSymbolAddress((void**)&h2, g_h2);
    cudaGetSymbolAddress((void**)&y, g_y);
    cudaGetSymbolAddress((void**)&ff, g_ff);
    cudaGetSymbolAddress((void**)&tq, g_wt_q);
    cudaGetSymbolAddress((void**)&tk, g_wt_k);
    cudaGetSymbolAddress((void**)&tv, g_wt_v);
    cudaGetSymbolAddress((void**)&to, g_wt_o);
    cudaGetSymbolAddress((void**)&tg, g_wt_gate);
    cudaGetSymbolAddress((void**)&tu, g_wt_up);
    cudaGetSymbolAddress((void**)&td, g_wt_down);

    const int M = Mrows;

    pre_k<<<Mrows + 384, 256>>>(hidden, ln1, x, q_w, k_w, v_w, tq, tk, tv);

    qkv_trans_k<<<384 + 256, 256, HG_SMEM>>>(x, tq, tk, tv, qp, kp, v16, o_w, to);

    norm_vt_k<<<NR_BLOCKS + 1024, 256>>>(qp, q16, kp, k16, qn, kn, sinp, cosp, v16, vt);

    attn_trans_k<<<512 + 3072, 256, ATT_SMEM>>>(q16, k16, vt, attn,
                                                gate_w, up_w, down_w, tg, tu, td);

    hgemm(attn, to, hidden, h2, M, Dn, Hn * Kn, 1, 0);

    rmsnorm_k<<<M, 256>>>(h2, ln2, y);

    // fused gate+up+silu: ff = silu(y@Wg) * (y@Wu)
    gateup_fused_k<<<2048, 256, GU_SMEM>>>(y, tg, tu, ff);

    hgemm(ff, td, h2, out, M, Dn, Fn, 1, 0);
}

// round 17
// speedup vs baseline: 2.2767x; 1.0064x over previous
#include <cuda_runtime.h>
#include <cuda_fp16.h>
#include <math.h>
#include <stdint.h>

#define Bn 2
#define Tn 2048
#define Dn 1024
#define Hn 16
#define Gn 4
#define Kn 64
#define Rn (Hn / Gn)
#define Fn 4096
#define EPSF 1e-6f
#define Mrows (Bn * Tn)

// ---------------- scratch ----------------
__device__ __half g_x[Mrows * Dn];
__device__ __half g_qp[Mrows * Hn * Kn];
__device__ __half g_kp[Mrows * Gn * Kn];
__device__ __half g_v16[Mrows * Gn * Kn];
__device__ __half g_q16[Mrows * Hn * Kn];
__device__ __half g_k16[Mrows * Gn * Kn];
__device__ __half g_vt[Bn * Gn * Kn * Tn];
__device__ __half g_attn[Mrows * Hn * Kn];
__device__ float  g_h2[Mrows * Dn];
__device__ __half g_y[Mrows * Dn];
__device__ __half g_ff[Mrows * Fn];
__device__ __half g_wt_q[1024 * 1024];
__device__ __half g_wt_k[256 * 1024];
__device__ __half g_wt_v[256 * 1024];
__device__ __half g_wt_o[1024 * 1024];
__device__ __half g_wt_gate[4096 * 1024];
__device__ __half g_wt_up[4096 * 1024];
__device__ __half g_wt_down[1024 * 4096];

// ---------------- helpers ----------------
__device__ __forceinline__ uint32_t smem_u32(const void* p) {
    return (uint32_t)__cvta_generic_to_shared(p);
}
__device__ __forceinline__ void cpa16(uint32_t dst, const void* src) {
    asm volatile("cp.async.cg.shared.global [%0], [%1], 16;" ::"r"(dst), "l"(src));
}
#define CP_COMMIT asm volatile("cp.async.commit_group;")
#define CP_WAIT0 asm volatile("cp.async.wait_group 0;")
#define CP_WAIT1 asm volatile("cp.async.wait_group 1;")
#define CP_WAIT2 asm volatile("cp.async.wait_group 2;")

#define MMA_F16(d, a0, a1, a2, a3, b0, b1)                                    \
    asm volatile(                                                             \
        "mma.sync.aligned.m16n8k16.row.col.f32.f16.f16.f32 "                  \
        "{%0,%1,%2,%3}, {%4,%5,%6,%7}, {%8,%9}, {%0,%1,%2,%3};"               \
        : "+f"(d[0]), "+f"(d[1]), "+f"(d[2]), "+f"(d[3])                      \
        : "r"(a0), "r"(a1), "r"(a2), "r"(a3), "r"(b0), "r"(b1))

#define LDSM_X4(r0, r1, r2, r3, addr)                                         \
    asm volatile("ldmatrix.sync.aligned.m8n8.x4.shared.b16 {%0,%1,%2,%3}, [%4];" \
                 : "=r"(r0), "=r"(r1), "=r"(r2), "=r"(r3) : "r"(addr))

__device__ __forceinline__ uint32_t pack_h2(float a, float b) {
    __half2 h = __floats2half2_rn(a, b);
    return *reinterpret_cast<uint32_t*>(&h);
}

// ---------------- 64x64 transpose tile helper ----------------
__device__ __forceinline__ void trans_tile(const float* W, __half* Wt, int K, int N,
                                           int bx, int by, float (*t)[65]) {
    {
        int x = threadIdx.x & 63, y = threadIdx.x >> 6;
#pragma unroll
        for (int j = 0; j < 16; j++)
            t[y + j * 4][x] = W[(size_t)(by * 64 + y + j * 4) * N + bx * 64 + x];
    }
    __syncthreads();
    {
        int x = threadIdx.x & 31, y = threadIdx.x >> 5;
#pragma unroll
        for (int j = 0; j < 8; j++) {
            int n = y + j * 8;
            __half2 v = __floats2half2_rn(t[2 * x][n], t[2 * x + 1][n]);
            *(__half2*)(Wt + (size_t)(bx * 64 + n) * K + by * 64 + 2 * x) = v;
        }
    }
}

// ---------------- RMSNorm body ----------------
__device__ __forceinline__ void rmsnorm_body(const float* __restrict__ in,
                                             const float* __restrict__ sc,
                                             __half* __restrict__ out, int row,
                                             float* sm) {
    const float4* x4 = (const float4*)(in + (size_t)row * Dn);
    float4 v = x4[threadIdx.x];
    float ss = v.x * v.x + v.y * v.y + v.z * v.z + v.w * v.w;
    for (int o = 16; o; o >>= 1) ss += __shfl_xor_sync(0xFFFFFFFFu, ss, o);
    int w = threadIdx.x >> 5;
    if ((threadIdx.x & 31) == 0) sm[w] = ss;
    __syncthreads();
    if (threadIdx.x == 0) {
        float tot = 0.f;
        for (int i = 0; i < 8; i++) tot += sm[i];
        sm[0] = tot;
    }
    __syncthreads();
    float inv = rsqrtf(sm[0] / (float)Dn + EPSF);
    float4 s4 = ((const float4*)sc)[threadIdx.x];
    __half2* o2 = (__half2*)(out + (size_t)row * Dn) + threadIdx.x * 2;
    o2[0] = __floats2half2_rn(v.x * inv * s4.x, v.y * inv * s4.y);
    o2[1] = __floats2half2_rn(v.z * inv * s4.z, v.w * inv * s4.w);
}

// ---------------- pre: rmsnorm(ln1) + q/k/v weight transposes ----------------
__global__ __launch_bounds__(256) void pre_k(
    const float* __restrict__ hidden, const float* __restrict__ ln1,
    __half* __restrict__ x,
    const float* __restrict__ q_w, const float* __restrict__ k_w,
    const float* __restrict__ v_w,
    __half* __restrict__ tq, __half* __restrict__ tk, __half* __restrict__ tv) {
    __shared__ float t[64][65];
    int b = blockIdx.x;
    if (b < Mrows) {
        rmsnorm_body(hidden, ln1, x, b, &t[0][0]);
        return;
    }
    int b2 = b - Mrows;
    const float* W; __half* Wt; int K, N, base;
    if (b2 < 256)      { W = q_w; Wt = tq; K = 1024; N = 1024; base = 0; }
    else if (b2 < 320) { W = k_w; Wt = tk; K = 1024; N = 256;  base = 256; }
    else               { W = v_w; Wt = tv; K = 1024; N = 256;  base = 320; }
    int local = b2 - base;
    int nb = N >> 6;
    trans_tile(W, Wt, K, N, local % nb, local / nb, t);
}

// ---------------- standalone RMSNorm (ln2) ----------------
__global__ void rmsnorm_k(const float* __restrict__ in, const float* __restrict__ sc,
                          __half* __restrict__ out) {
    __shared__ float sm[8];
    rmsnorm_body(in, sc, out, blockIdx.x, sm);
}

// ---------------- merged: per-head norm+rope (q,k) + V transpose ----------------
#define QWARPS (Bn * Tn * Hn)
#define KWARPS (Bn * Tn * Gn)
#define NR_BLOCKS ((QWARPS + KWARPS) / 8)
__global__ void norm_vt_k(const __half* __restrict__ qp, __half* __restrict__ q16,
                          const __half* __restrict__ kp, __half* __restrict__ k16,
                          const float* __restrict__ qscale, const float* __restrict__ kscale,
                          const float* __restrict__ sinp, const float* __restrict__ cosp,
                          const __half* __restrict__ v16, __half* __restrict__ vt) {
    __shared__ __half t[32][33];
    int b = blockIdx.x;
    if (b >= NR_BLOCKS) {
        int b2 = b - NR_BLOCKS;
        int xb = b2 & 63, yb = (b2 >> 6) & 1, bg = b2 >> 7;
        int bb = bg >> 2, g = bg & 3;
        int t0 = xb * 32, d0 = yb * 32;
        int x = threadIdx.x & 31, y = threadIdx.x >> 5;
#pragma unroll
        for (int j = 0; j < 4; j++) {
            int tt = t0 + y + j * 8;
            t[y + j * 8][x] = v16[((size_t)((size_t)bb * Tn + tt) * Gn + g) * Kn + d0 + x];
        }
        __syncthreads();
#pragma unroll
        for (int j = 0; j < 4; j++) {
            int dd = d0 + y + j * 8;
            vt[((size_t)bg * Kn + dd) * Tn + t0 + x] = t[x][y + j * 8];
        }
        return;
    }
    int gw = b * 8 + (threadIdx.x >> 5);
    int lane = threadIdx.x & 31;
    const __half* src; __half* dst; const float* nscale; int bt;
    if (gw < QWARPS) {
        src = qp + (size_t)gw * Kn;
        dst = q16 + (size_t)gw * Kn;
        nscale = qscale;
        bt = gw / Hn;
    } else {
        int g2 = gw - QWARPS;
        src = kp + (size_t)g2 * Kn;
        dst = k16 + (size_t)g2 * Kn;
        nscale = kscale;
        bt = g2 / Gn;
    }
    float x1 = __half2float(src[lane]);
    float x2 = __half2float(src[lane + 32]);
    float ss = x1 * x1 + x2 * x2;
    for (int o = 16; o; o >>= 1) ss += __shfl_xor_sync(0xFFFFFFFFu, ss, o);
    float inv = rsqrtf(ss / (float)Kn + EPSF);
    x1 = x1 * inv * nscale[lane];
    x2 = x2 * inv * nscale[lane + 32];
    float s = sinp[bt * (Kn / 2) + lane];
    float c = cosp[bt * (Kn / 2) + lane];
    dst[lane]      = __float2half(x1 * c - x2 * s);
    dst[lane + 32] = __float2half(x2 * c + x1 * s);
}

// ============================================================
// FP16 GEMM core (ldmatrix, single-sync 4-stage cp.async)
// ============================================================
#define HAS 40
#define HG_STAGE 10240
#define HSTG 4
#define HG_SMEM (2 * HSTG * HG_STAGE)

__device__ __forceinline__ void hgemm_issue(uint32_t aB, uint32_t bB, int s,
                                            const __half* Arow, const __half* Brow,
                                            int k0, int Kd) {
    int tid = threadIdx.x;
#pragma unroll
    for (int j = 0; j < 2; j++) {
        int idx = tid + j * 256;
        int row = idx >> 2, ch = idx & 3;
        uint32_t dst = (uint32_t)(row * (HAS * 2) + ch * 16);
        cpa16(aB + s * HG_STAGE + dst, Arow + (size_t)row * Kd + k0 + ch * 8);
        cpa16(bB + s * HG_STAGE + dst, Brow + (size_t)row * Kd + k0 + ch * 8);
    }
}

__device__ __forceinline__ void hgemm_compute(uint32_t aAddr, uint32_t bAddr,
                                              float acc[4][4][4]) {
#pragma unroll
    for (int k2 = 0; k2 < 2; k2++) {
        uint32_t af[4][4], bf[4][2];
#pragma unroll
        for (int mi = 0; mi < 4; mi++)
            LDSM_X4(af[mi][0], af[mi][1], af[mi][2], af[mi][3],
                    aAddr + mi * 16 * 80 + k2 * 32);
#pragma unroll
        for (int p = 0; p < 2; p++)
            LDSM_X4(bf[2 * p][0], bf[2 * p][1], bf[2 * p + 1][0], bf[2 * p + 1][1],
                    bAddr + p * 16 * 80 + k2 * 32);
#pragma unroll
        for (int mi = 0; mi < 4; mi++)
#pragma unroll
            for (int ni = 0; ni < 4; ni++)
                MMA_F16(acc[mi][ni], af[mi][0], af[mi][1], af[mi][2], af[mi][3],
                        bf[ni][0], bf[ni][1]);
    }
}

__device__ __forceinline__ void hgemm_body(const __half* A, const __half* Wt,
                                           const void* aux, void* Cv,
                                           int N, int Kd, int bx, int by,
                                           int mode, int ohalf, char* smn) {
    uint32_t aB = smem_u32(smn);
    uint32_t bB = aB + HSTG * HG_STAGE;
    int tid = threadIdx.x;
    int lane = tid & 31, wid = tid >> 5;
    int wm = wid >> 2, wn = wid & 3;
    int fr = lane >> 2, fc = lane & 3;

    int rA = (lane & 7) + ((lane >> 3) & 1) * 8;
    int cA = (lane >> 4) * 8;
    uint32_t aOff = (uint32_t)((wm * 64 + rA) * 80 + cA * 2);
    int rB = (lane & 7) + (lane >> 4) * 8;
    int cB = ((lane >> 3) & 1) * 8;
    uint32_t bOff = (uint32_t)((wn * 32 + rB) * 80 + cB * 2);

    const __half* Arow = A + (size_t)(by * 128) * Kd;
    const __half* Brow = Wt + (size_t)(bx * 128) * Kd;

    float acc[4][4][4];
#pragma unroll
    for (int mi = 0; mi < 4; mi++)
#pragma unroll
        for (int ni = 0; ni < 4; ni++)
#pragma unroll
            for (int c = 0; c < 4; c++) acc[mi][ni][c] = 0.f;

    int nk = Kd / 32;
    hgemm_issue(aB, bB, 0, Arow, Brow, 0, Kd); CP_COMMIT;
    hgemm_issue(aB, bB, 1, Arow, Brow, 32, Kd); CP_COMMIT;
    hgemm_issue(aB, bB, 2, Arow, Brow, 64, Kd); CP_COMMIT;

    for (int i = 0; i < nk; i++) {
        if (i + 3 <= nk) { CP_WAIT2; }
        else if (i + 2 == nk) { CP_WAIT1; }
        else { CP_WAIT0; }
        __syncthreads();
        if (i + 3 < nk) {
            hgemm_issue(aB, bB, (i + 3) % HSTG, Arow, Brow, (i + 3) * 32, Kd);
            CP_COMMIT;
        }
        int s = i % HSTG;
        hgemm_compute(aB + s * HG_STAGE + aOff, bB + s * HG_STAGE + bOff, acc);
    }

#pragma unroll
    for (int mi = 0; mi < 4; mi++) {
#pragma unroll
        for (int ni = 0; ni < 4; ni++) {
            int row = by * 128 + wm * 64 + mi * 16 + fr;
            int col = bx * 128 + wn * 32 + ni * 8 + fc * 2;
            float2 r0 = make_float2(acc[mi][ni][0], acc[mi][ni][1]);
            float2 r1 = make_float2(acc[mi][ni][2], acc[mi][ni][3]);
            if (mode == 1) {
                const float* ap = (const float*)aux;
                float2 h0 = *(const float2*)(ap + (size_t)row * N + col);
                float2 h1 = *(const float2*)(ap + (size_t)(row + 8) * N + col);
                r0.x += h0.x; r0.y += h0.y;
                r1.x += h1.x; r1.y += h1.y;
            }
            if (ohalf) {
                __half* C = (__half*)Cv;
                *(__half2*)(C + (size_t)row * N + col) = __floats2half2_rn(r0.x, r0.y);
                *(__half2*)(C + (size_t)(row + 8) * N + col) = __floats2half2_rn(r1.x, r1.y);
            } else {
                float* C = (float*)Cv;
                *(float2*)(C + (size_t)row * N + col) = r0;
                *(float2*)(C + (size_t)(row + 8) * N + col) = r1;
            }
        }
    }
}

__global__ __launch_bounds__(256, 2) void hgemm_k(
    const __half* __restrict__ A, const __half* __restrict__ Wt,
    const void* __restrict__ aux, void* __restrict__ C,
    int N, int Kd, int mode, int ohalf) {
    extern __shared__ char smn[];
    hgemm_body(A, Wt, aux, C, N, Kd, blockIdx.x, blockIdx.y, mode, ohalf, smn);
}

// ---- merged: qkv GEMM (384) + o_w transpose (256) ----
__global__ __launch_bounds__(256, 2) void qkv_trans_k(
    const __half* __restrict__ A,
    const __half* __restrict__ Wtq, const __half* __restrict__ Wtk, const __half* __restrict__ Wtv,
    __half* __restrict__ Cq, __half* __restrict__ Ck, __half* __restrict__ Cv,
    const float* __restrict__ o_w, __half* __restrict__ to) {
    extern __shared__ char smn[];
    int b = blockIdx.x;
    if (b < 384) {
        int bx = b % 12, by = b / 12;
        const __half* Wt; __half* C; int N;
        if (bx < 8)       { Wt = Wtq; C = Cq; N = 1024; }
        else if (bx < 10) { Wt = Wtk; C = Ck; N = 256; bx -= 8; }
        else              { Wt = Wtv; C = Cv; N = 256; bx -= 10; }
        hgemm_body(A, Wt, (const void*)0, C, N, Dn, bx, by, 0, 1, smn);
        return;
    }
    int b2 = b - 384;
    float (*t)[65] = (float(*)[65])smn;
    trans_tile(o_w, to, 1024, 1024, b2 % 16, b2 / 16, t);
}

// ============================================================
// Fused gate+up GEMM + silu
// ============================================================
#define GU_STAGE 20480
#define GU_SMEM (HSTG * GU_STAGE)

__device__ __forceinline__ void gu_issue(uint32_t base, int s,
                                         const __half* Arow, const __half* Bg,
                                         const __half* Bu, int k0) {
    int tid = threadIdx.x;
    uint32_t st = base + s * GU_STAGE;
#pragma unroll
    for (int j = 0; j < 2; j++) {
        int idx = tid + j * 256;
        int row = idx >> 2, ch = idx & 3;
        cpa16(st + (uint32_t)(row * 80 + ch * 16), Arow + (size_t)row * Dn + k0 + ch * 8);
    }
    {
        int row = tid >> 2, ch = tid & 3;
        cpa16(st + 10240 + (uint32_t)(row * 80 + ch * 16), Bg + (size_t)row * Dn + k0 + ch * 8);
        cpa16(st + 15360 + (uint32_t)(row * 80 + ch * 16), Bu + (size_t)row * Dn + k0 + ch * 8);
    }
}

__global__ __launch_bounds__(256, 2) void gateup_fused_k(
    const __half* __restrict__ y,
    const __half* __restrict__ Wtg, const __half* __restrict__ Wtu,
    __half* __restrict__ ff) {
    extern __shared__ char smn[];
    uint32_t base = smem_u32(smn);
    int tid = threadIdx.x;
    int lane = tid & 31, wid = tid >> 5;
    int wm = wid >> 2, wn = wid & 3;
    int fr = lane >> 2, fc = lane & 3;
    int bx = blockIdx.x & 63, by = blockIdx.x >> 6;

    int rA = (lane & 7) + ((lane >> 3) & 1) * 8;
    int cA = (lane >> 4) * 8;
    uint32_t aOff = (uint32_t)((wm * 64 + rA) * 80 + cA * 2);
    int rB = (lane & 7) + (lane >> 4) * 8;
    int cB = ((lane >> 3) & 1) * 8;
    uint32_t bOff = (uint32_t)((wn * 16 + rB) * 80 + cB * 2);

    const __half* Arow = y + (size_t)(by * 128) * Dn;
    const __half* Bg = Wtg + (size_t)(bx * 64) * Dn;
    const __half* Bu = Wtu + (size_t)(bx * 64) * Dn;

    float ag[4][2][4], au[4][2][4];
#pragma unroll
    for (int mi = 0; mi < 4; mi++)
#pragma unroll
        for (int ni = 0; ni < 2; ni++)
#pragma unroll
            for (int c = 0; c < 4; c++) { ag[mi][ni][c] = 0.f; au[mi][ni][c] = 0.f; }

    int nk = Dn / 32;
    gu_issue(base, 0, Arow, Bg, Bu, 0); CP_COMMIT;
    gu_issue(base, 1, Arow, Bg, Bu, 32); CP_COMMIT;
    gu_issue(base, 2, Arow, Bg, Bu, 64); CP_COMMIT;

    for (int i = 0; i < nk; i++) {
        if (i + 3 <= nk) { CP_WAIT2; }
        else if (i + 2 == nk) { CP_WAIT1; }
        else { CP_WAIT0; }
        __syncthreads();
        if (i + 3 < nk) {
            gu_issue(base, (i + 3) % HSTG, Arow, Bg, Bu, (i + 3) * 32);
            CP_COMMIT;
        }
        uint32_t st = base + (i % HSTG) * GU_STAGE;
        uint32_t aAddr = st + aOff;
        uint32_t gAddr = st + 10240 + bOff;
        uint32_t uAddr = st + 15360 + bOff;
#pragma unroll
        for (int k2 = 0; k2 < 2; k2++) {
            uint32_t af[4][4];
#pragma unroll
            for (int mi = 0; mi < 4; mi++)
                LDSM_X4(af[mi][0], af[mi][1], af[mi][2], af[mi][3],
                        aAddr + mi * 16 * 80 + k2 * 32);
            uint32_t bg0, bg1, bg2, bg3, bu0, bu1, bu2, bu3;
            LDSM_X4(bg0, bg1, bg2, bg3, gAddr + k2 * 32);
            LDSM_X4(bu0, bu1, bu2, bu3, uAddr + k2 * 32);
#pragma unroll
            for (int mi = 0; mi < 4; mi++) {
                MMA_F16(ag[mi][0], af[mi][0], af[mi][1], af[mi][2], af[mi][3], bg0, bg1);
                MMA_F16(ag[mi][1], af[mi][0], af[mi][1], af[mi][2], af[mi][3], bg2, bg3);
                MMA_F16(au[mi][0], af[mi][0], af[mi][1], af[mi][2], af[mi][3], bu0, bu1);
                MMA_F16(au[mi][1], af[mi][0], af[mi][1], af[mi][2], af[mi][3], bu2, bu3);
            }
        }
    }

#pragma unroll
    for (int mi = 0; mi < 4; mi++) {
#pragma unroll
        for (int ni = 0; ni < 2; ni++) {
            int row = by * 128 + wm * 64 + mi * 16 + fr;
            int col = bx * 64 + wn * 16 + ni * 8 + fc * 2;
            float g0 = ag[mi][ni][0], g1 = ag[mi][ni][1];
            float g2 = ag[mi][ni][2], g3 = ag[mi][ni][3];
            float f0 = g0 / (1.f + __expf(-g0)) * au[mi][ni][0];
            float f1 = g1 / (1.f + __expf(-g1)) * au[mi][ni][1];
            float f2 = g2 / (1.f + __expf(-g2)) * au[mi][ni][2];
            float f3 = g3 / (1.f + __expf(-g3)) * au[mi][ni][3];
            *(__half2*)(ff + (size_t)row * Fn + col) = __floats2half2_rn(f0, f1);
            *(__half2*)(ff + (size_t)(row + 8) * Fn + col) = __floats2half2_rn(f2, f3);
        }
    }
}

// ============================================================
// Flash attention body: fp16 MMA, register-resident P,
// double-buffered K/V with one combined prefetch group per tile.
// ============================================================
#define QSH 72
#define VTH 136
#define KSTG_B (128 * QSH * 2)   // 18432 bytes per K stage
#define VSTG_B (64 * VTH * 2)    // 17408 bytes per V stage
#define ATT_SMEM ((128 * QSH) * 2 + 2 * KSTG_B + 2 * VSTG_B)

__device__ __forceinline__ void flashattn_body(
    const __half* __restrict__ q16, const __half* __restrict__ k16,
    const __half* __restrict__ vt, __half* __restrict__ out,
    int bxi, int bg, int nbx, __half* smh) {
    __half* Qs = smh;
    __half* Ks = Qs + 128 * QSH;           // 2 stages
    __half* Vs = Ks + 2 * 128 * QSH;       // 2 stages
    uint32_t qs_u = smem_u32(Qs), ks_u = smem_u32(Ks), vs_u = smem_u32(Vs);

    int tid = threadIdx.x;
    int lane = tid & 31, wid = tid >> 5;
    int fr = lane >> 2, fc = lane & 3;

    int rA = (lane & 7) + ((lane >> 3) & 1) * 8;
    int cA = (lane >> 4) * 8;
    int rB = (lane & 7) + (lane >> 4) * 8;
    int cB = ((lane >> 3) & 1) * 8;
    uint32_t qAddr = qs_u + (uint32_t)((wid * 16 + rA) * 144 + cA * 2);
    uint32_t kAddr0 = ks_u + (uint32_t)(rB * 144 + cB * 2);
    uint32_t vAddr0 = vs_u + (uint32_t)(rB * 272 + cB * 2);

    int b = bg >> 2, g = bg & 3;
    int t0 = (nbx - 1 - bxi) * 32;
    int ntiles = (t0 >> 7) + 1;

    const __half* qbase = q16 + ((size_t)((size_t)b * Tn + t0) * Hn + g * Rn) * Kn;
    const __half* kbase = k16 + ((size_t)b * Tn * Gn + g) * Kn;
    const __half* vtbase = vt + (size_t)bg * Kn * Tn;

    // prologue group 1: Q + K0 + V0
#pragma unroll
    for (int i = 0; i < 4; i++) {
        int idx = tid + (i << 8);
        int m = idx >> 3, ch = idx & 7;
        cpa16(qs_u + (uint32_t)(m * QSH * 2 + ch * 16),
              qbase + (size_t)(m >> 2) * (Hn * Kn) + (m & 3) * Kn + ch * 8);
    }
#pragma unroll
    for (int i = 0; i < 4; i++) {
        int idx = tid + (i << 8);
        int j = idx >> 3, ch = idx & 7;
        cpa16(ks_u + (uint32_t)(j * QSH * 2 + ch * 16),
              kbase + (size_t)j * (Gn * Kn) + ch * 8);
    }
#pragma unroll
    for (int i = 0; i < 4; i++) {
        int idx = tid + (i << 8);
        int d = idx >> 4, ch = idx & 15;
        cpa16(vs_u + (uint32_t)(d * VTH * 2 + ch * 16),
              vtbase + (size_t)d * Tn + 0 + ch * 8);
    }
    CP_COMMIT;
    // prologue group 2: K1 + V1 (if present)
    if (ntiles > 1) {
#pragma unroll
        for (int i = 0; i < 4; i++) {
            int idx = tid + (i << 8);
            int j = idx >> 3, ch = idx & 7;
            cpa16(ks_u + (uint32_t)(KSTG_B + j * QSH * 2 + ch * 16),
                  kbase + (size_t)(128 + j) * (Gn * Kn) + ch * 8);
        }
#pragma unroll
        for (int i = 0; i < 4; i++) {
            int idx = tid + (i << 8);
            int d = idx >> 4, ch = idx & 15;
            cpa16(vs_u + (uint32_t)(VSTG_B + d * VTH * 2 + ch * 16),
                  vtbase + (size_t)d * Tn + 128 + ch * 8);
        }
        CP_COMMIT;
        CP_WAIT1;
    } else {
        CP_WAIT0;
    }
    __syncthreads();

    float m_r[2], l_r[2], acco[8][4];
#pragma unroll
    for (int h = 0; h < 2; h++) { m_r[h] = -INFINITY; l_r[h] = 0.f; }
#pragma unroll
    for (int ni = 0; ni < 8; ni++)
#pragma unroll
        for (int c = 0; c < 4; c++) acco[ni][c] = 0.f;

    int r0 = wid * 16 + fr;

    for (int it = 0; it < ntiles; it++) {
        int s0 = it << 7;
        int buf = it & 1;
        uint32_t kA = kAddr0 + (uint32_t)buf * KSTG_B;
        uint32_t vA = vAddr0 + (uint32_t)buf * VSTG_B;

        // ---- S = Q @ K^T ----
        float accs[16][4];
#pragma unroll
        for (int ni = 0; ni < 16; ni++)
#pragma unroll
            for (int c = 0; c < 4; c++) accs[ni][c] = 0.f;

#pragma unroll
        for (int k2 = 0; k2 < 4; k2++) {
            uint32_t af[4];
            LDSM_X4(af[0], af[1], af[2], af[3], qAddr + k2 * 32);
#pragma unroll
            for (int p = 0; p < 8; p++) {
                uint32_t b00, b01, b10, b11;
                LDSM_X4(b00, b01, b10, b11, kA + p * 16 * 144 + k2 * 32);
                MMA_F16(accs[2 * p], af[0], af[1], af[2], af[3], b00, b01);
                MMA_F16(accs[2 * p + 1], af[0], af[1], af[2], af[3], b10, b11);
            }
        }

#pragma unroll
        for (int ni = 0; ni < 16; ni++)
#pragma unroll
            for (int c = 0; c < 4; c++) accs[ni][c] *= 0.125f;
        if (it == ntiles - 1) {
#pragma unroll
            for (int ni = 0; ni < 16; ni++)
#pragma unroll
                for (int c = 0; c < 4; c++) {
                    int row = r0 + ((c >= 2) ? 8 : 0);
                    int tt = t0 + (row >> 2);
                    int ss = s0 + ni * 8 + fc * 2 + (c & 1);
                    if (ss > tt) accs[ni][c] = -1e30f;
                }
        }

        // ---- online softmax (P stays in accs) ----
#pragma unroll
        for (int h = 0; h < 2; h++) {
            float mx = -1e30f;
#pragma unroll
            for (int ni = 0; ni < 16; ni++) {
                mx = fmaxf(mx, accs[ni][2 * h]);
                mx = fmaxf(mx, accs[ni][2 * h + 1]);
            }
            mx = fmaxf(mx, __shfl_xor_sync(0xFFFFFFFFu, mx, 1));
            mx = fmaxf(mx, __shfl_xor_sync(0xFFFFFFFFu, mx, 2));
            float mnew = fmaxf(m_r[h], mx);
            float corr = __expf(m_r[h] - mnew);
            m_r[h] = mnew;
            float sum = 0.f;
#pragma unroll
            for (int ni = 0; ni < 16; ni++) {
                float p0 = __expf(accs[ni][2 * h] - mnew);
                float p1 = __expf(accs[ni][2 * h + 1] - mnew);
                accs[ni][2 * h] = p0;
                accs[ni][2 * h + 1] = p1;
                sum += p0 + p1;
            }
            sum += __shfl_xor_sync(0xFFFFFFFFu, sum, 1);
            sum += __shfl_xor_sync(0xFFFFFFFFu, sum, 2);
            l_r[h] = l_r[h] * corr + sum;
#pragma unroll
            for (int ni = 0; ni < 8; ni++) {
                acco[ni][2 * h] *= corr;
                acco[ni][2 * h + 1] *= corr;
            }
        }

        // ---- O += P @ V : register-resident P ----
#pragma unroll
        for (int j = 0; j < 8; j++) {
            uint32_t af[4];
            af[0] = pack_h2(accs[2 * j][0], accs[2 * j][1]);
            af[1] = pack_h2(accs[2 * j][2], accs[2 * j][3]);
            af[2] = pack_h2(accs[2 * j + 1][0], accs[2 * j + 1][1]);
            af[3] = pack_h2(accs[2 * j + 1][2], accs[2 * j + 1][3]);
#pragma unroll
            for (int p = 0; p < 4; p++) {
                uint32_t b00, b01, b10, b11;
                LDSM_X4(b00, b01, b10, b11, vA + p * 16 * 272 + j * 32);
                MMA_F16(acco[2 * p], af[0], af[1], af[2], af[3], b00, b01);
                MMA_F16(acco[2 * p + 1], af[0], af[1], af[2], af[3], b10, b11);
            }
        }

        __syncthreads();  // all warps done reading buf (K and V)

        if (it + 2 < ntiles) {
            int sn = s0 + 256;  // tile it+2 -> same buf
#pragma unroll
            for (int i = 0; i < 4; i++) {
                int idx = tid + (i << 8);
                int j = idx >> 3, ch = idx & 7;
                cpa16(ks_u + (uint32_t)(buf * KSTG_B + j * QSH * 2 + ch * 16),
                      kbase + (size_t)(sn + j) * (Gn * Kn) + ch * 8);
            }
#pragma unroll
            for (int i = 0; i < 4; i++) {
                int idx = tid + (i << 8);
                int d = idx >> 4, ch = idx & 15;
                cpa16(vs_u + (uint32_t)(buf * VSTG_B + d * VTH * 2 + ch * 16),
                      vtbase + (size_t)d * Tn + sn + ch * 8);
            }
            CP_COMMIT;
        }
        if (it + 1 < ntiles) {
            if (it + 2 < ntiles) { CP_WAIT1; } else { CP_WAIT0; }
            __syncthreads();  // tile it+1 data visible to all warps
        }
    }

#pragma unroll
    for (int h = 0; h < 2; h++) {
        float inv = 1.f / l_r[h];
        int row = r0 + 8 * h;
        int tt = t0 + (row >> 2);
        int hh = g * Rn + (row & 3);
        __half* op = out + ((size_t)((size_t)b * Tn + tt) * Hn + hh) * Kn;
#pragma unroll
        for (int ni = 0; ni < 8; ni++) {
            int col = ni * 8 + fc * 2;
            *(__half2*)(op + col) =
                __floats2half2_rn(acco[ni][2 * h] * inv, acco[ni][2 * h + 1] * inv);
        }
    }
}

// ---- merged: attention (512) + gate/up/down weight transposes (3072) ----
__global__ __launch_bounds__(256, 2) void attn_trans_k(
    const __half* __restrict__ q16, const __half* __restrict__ k16,
    const __half* __restrict__ vt, __half* __restrict__ attn,
    const float* __restrict__ gate_w, const float* __restrict__ up_w,
    const float* __restrict__ down_w,
    __half* __restrict__ tg, __half* __restrict__ tu, __half* __restrict__ td) {
    extern __shared__ char smraw[];
    int b = blockIdx.x;
    if (b < 512) {
        flashattn_body(q16, k16, vt, attn, b & 63, b >> 6, 64, (__half*)smraw);
        return;
    }
    int b2 = b - 512;
    float (*t)[65] = (float(*)[65])smraw;
    const float* W; __half* Wt; int K, N, base;
    if (b2 < 1024)      { W = gate_w; Wt = tg; K = 1024; N = 4096; base = 0; }
    else if (b2 < 2048) { W = up_w;   Wt = tu; K = 1024; N = 4096; base = 1024; }
    else                { W = down_w; Wt = td; K = 4096; N = 1024; base = 2048; }
    int local = b2 - base;
    int nb = N >> 6;
    trans_tile(W, Wt, K, N, local % nb, local / nb, t);
}

// ---------------- launch ----------------
static void hgemm(const __half* A, const __half* Wt, const void* aux, void* C,
                  int M, int N, int Kd, int mode, int ohalf) {
    dim3 grid(N / 128, M / 128);
    hgemm_k<<<grid, 256, HG_SMEM>>>(A, Wt, aux, C, N, Kd, mode, ohalf);
}

extern "C" void kernel_launch(void* const* d_in, const int* in_sizes, int n_in,
                              void* d_out, int out_size) {
    const float* hidden = (const float*)d_in[0];
    const float* sinp   = (const float*)d_in[1];
    const float* cosp   = (const float*)d_in[2];
    /* d_in[3] = mask (exact causal tril; applied analytically) */
    const float* ln1    = (const float*)d_in[4];
    const float* ln2    = (const float*)d_in[5];
    const float* qn     = (const float*)d_in[6];
    const float* kn     = (const float*)d_in[7];
    const float* q_w    = (const float*)d_in[8];
    const float* k_w    = (const float*)d_in[9];
    const float* v_w    = (const float*)d_in[10];
    const float* o_w    = (const float*)d_in[11];
    const float* gate_w = (const float*)d_in[12];
    const float* up_w   = (const float*)d_in[13];
    const float* down_w = (const float*)d_in[14];
    float* out = (float*)d_out;

    cudaFuncSetAttribute(hgemm_k, cudaFuncAttributeMaxDynamicSharedMemorySize, HG_SMEM);
    cudaFuncSetAttribute(qkv_trans_k, cudaFuncAttributeMaxDynamicSharedMemorySize, HG_SMEM);
    cudaFuncSetAttribute(gateup_fused_k, cudaFuncAttributeMaxDynamicSharedMemorySize, GU_SMEM);
    cudaFuncSetAttribute(attn_trans_k, cudaFuncAttributeMaxDynamicSharedMemorySize, ATT_SMEM);

    __half *x, *qp, *kp, *v16, *q16, *k16, *vt, *attn, *y, *ff;
    float *h2;
    __half *tq, *tk, *tv, *to, *tg, *tu, *td;
    cudaGetSymbolAddress((void**)&x, g_x);
    cudaGetSymbolAddress((void**)&qp, g_qp);
    cudaGetSymbolAddress((void**)&kp, g_kp);
    cudaGetSymbolAddress((void**)&v16, g_v16);
    cudaGetSymbolAddress((void**)&q16, g_q16);
    cudaGetSymbolAddress((void**)&k16, g_k16);
    cudaGetSymbolAddress((void**)&vt, g_vt);
    cudaGetSymbolAddress((void**)&attn, g_attn);
    cudaGetSymbolAddress((void**)&h2, g_h2);
    cudaGetSymbolAddress((void**)&y, g_y);
    cudaGetSymbolAddress((void**)&ff, g_ff);
    cudaGetSymbolAddress((void**)&tq, g_wt_q);
    cudaGetSymbolAddress((void**)&tk, g_wt_k);
    cudaGetSymbolAddress((void**)&tv, g_wt_v);
    cudaGetSymbolAddress((void**)&to, g_wt_o);
    cudaGetSymbolAddress((void**)&tg, g_wt_gate);
    cudaGetSymbolAddress((void**)&tu, g_wt_up);
    cudaGetSymbolAddress((void**)&td, g_wt_down);

    const int M = Mrows;

    pre_k<<<Mrows + 384, 256>>>(hidden, ln1, x, q_w, k_w, v_w, tq, tk, tv);

    qkv_trans_k<<<384 + 256, 256, HG_SMEM>>>(x, tq, tk, tv, qp, kp, v16, o_w, to);

    norm_vt_k<<<NR_BLOCKS + 1024, 256>>>(qp, q16, kp, k16, qn, kn, sinp, cosp, v16, vt);

    attn_trans_k<<<512 + 3072, 256, ATT_SMEM>>>(q16, k16, vt, attn,
                                                gate_w, up_w, down_w, tg, tu, td);

    hgemm(attn, to, hidden, h2, M, Dn, Hn * Kn, 1, 0);

    rmsnorm_k<<<M, 256>>>(h2, ln2, y);

    gateup_fused_k<<<2048, 256, GU_SMEM>>>(y, tg, tu, ff);

    hgemm(ff, td, h2, out, M, Dn, Fn, 1, 0);
}